// round 1
// baseline (speedup 1.0000x reference)
#include <cuda_runtime.h>
#include <math.h>

// ---------------------------------------------------------------------------
// Problem constants (T=8, N=M=1024, H=8, D=256, NB = int(256*ln 256) = 1419)
// ---------------------------------------------------------------------------
#define TT   8
#define NPT  1024
#define HH   8
#define DDIM 256
#define NBF  1419
#define ROWS (TT * HH * NPT)   // 65536 rows of (t,h,n)
#define BATCH (TT * HH)        // 64
#define HDCAT (HH * DDIM)      // 2048

// data_normalizer = 256^-0.25 = 0.25 exactly
#define DNORM   0.25f
#define DNORM2  0.0625f
#define EPSF    1e-4f

// ---------------------------------------------------------------------------
// Scratch (device globals -- allocation inside kernel_launch is forbidden)
// ---------------------------------------------------------------------------
__device__ float g_qall[(size_t)ROWS * DDIM];       //  67 MB
__device__ float g_kall[(size_t)ROWS * DDIM];       //  67 MB
__device__ float g_vall[(size_t)ROWS * DDIM];       //  67 MB
__device__ float g_qp  [(size_t)ROWS * NBF];        // 372 MB (dash -> q_prime in place)
__device__ float g_kp  [(size_t)ROWS * NBF];        // 372 MB (dash -> k_prime in place)
__device__ float g_ctx [(size_t)BATCH * NBF * DDIM];//  93 MB
__device__ float g_outs[(size_t)TT * NPT * HDCAT];  //  67 MB (permuted concat)
__device__ float g_ksum[(size_t)BATCH * NBF];
__device__ float g_dinv[(size_t)ROWS];
__device__ float g_kmax[(size_t)BATCH];
__device__ float g_projs[(size_t)NBF * DDIM];       // proj * 0.25

// ---------------------------------------------------------------------------
// Generic register-tiled SGEMM.
//   C[M,N] = op(A)[M,K] * op(B)[K,N]   (+bias / *row-scale, strided col store)
//   TA=0: A(i,k)=A[i*lda+k]   TA=1: A(i,k)=A[k*lda+i]
//   TB=0: B(k,j)=B[k*ldb+j]   TB=1: B(k,j)=B[j*ldb+k]
//   Batch: z -> (t = z/Hdiv, h = z%Hdiv); pointer += t*xT + h*xH
//   EPI: 0 = plain, 1 = +bias[col], 2 = *scale[row] (with colMul store stride)
// ---------------------------------------------------------------------------
#define BM 128
#define BN 128
#define BKK 16
#define TM 8
#define TN 8

template<int TA, int TB, int EPI>
__global__ void __launch_bounds__(256)
gemm_k(const float* __restrict__ A, const float* __restrict__ B,
       float* __restrict__ C,
       int M, int N, int K, int lda, int ldb, int ldc,
       long aT, long aH, long bT, long bH, long cT, long cH, int Hdiv,
       const float* __restrict__ bias, long biasH,
       const float* __restrict__ scale, long scT, long scH,
       int colMul)
{
    const int bz = blockIdx.z;
    const int t = bz / Hdiv, h = bz % Hdiv;
    A += t * aT + h * aH;
    B += t * bT + h * bH;
    C += t * cT + h * cH;
    if (EPI == 1) bias  += (long)h * biasH;
    if (EPI == 2) scale += t * scT + h * scH;

    __shared__ float As[BKK][BM];
    __shared__ float Bs[BKK][BN];

    const int m0 = blockIdx.y * BM;
    const int n0 = blockIdx.x * BN;
    const int tid = threadIdx.x;
    const int tr = tid >> 4;          // 0..15
    const int tc = tid & 15;          // 0..15

    float acc[TM][TN];
#pragma unroll
    for (int i = 0; i < TM; i++)
#pragma unroll
        for (int j = 0; j < TN; j++) acc[i][j] = 0.f;

    for (int k0 = 0; k0 < K; k0 += BKK) {
        // ---- load A tile into As[kk][mm]
#pragma unroll
        for (int it = 0; it < (BM * BKK) / 256; it++) {
            int idx = tid + it * 256;
            int kk, mm;
            if (TA == 0) { kk = idx & (BKK - 1); mm = idx / BKK; }
            else         { mm = idx & (BM - 1);  kk = idx / BM;  }
            int gm = m0 + mm, gk = k0 + kk;
            float v = 0.f;
            if (gm < M && gk < K)
                v = (TA == 0) ? A[(long)gm * lda + gk]
                              : A[(long)gk * lda + gm];
            As[kk][mm] = v;
        }
        // ---- load B tile into Bs[kk][nn]
#pragma unroll
        for (int it = 0; it < (BN * BKK) / 256; it++) {
            int idx = tid + it * 256;
            int kk, nn;
            if (TB == 0) { nn = idx & (BN - 1);  kk = idx / BN;  }
            else         { kk = idx & (BKK - 1); nn = idx / BKK; }
            int gn = n0 + nn, gk = k0 + kk;
            float v = 0.f;
            if (gn < N && gk < K)
                v = (TB == 0) ? B[(long)gk * ldb + gn]
                              : B[(long)gn * ldb + gk];
            Bs[kk][nn] = v;
        }
        __syncthreads();

#pragma unroll
        for (int kk = 0; kk < BKK; kk++) {
            float a[TM], b[TN];
#pragma unroll
            for (int i = 0; i < TM; i++) a[i] = As[kk][tr * TM + i];
#pragma unroll
            for (int j = 0; j < TN; j++) b[j] = Bs[kk][tc * TN + j];
#pragma unroll
            for (int i = 0; i < TM; i++)
#pragma unroll
                for (int j = 0; j < TN; j++)
                    acc[i][j] += a[i] * b[j];
        }
        __syncthreads();
    }

    // ---- epilogue / store
#pragma unroll
    for (int i = 0; i < TM; i++) {
        int row = m0 + tr * TM + i;
        if (row >= M) continue;
        float s = (EPI == 2) ? scale[row] : 1.f;
#pragma unroll
        for (int j = 0; j < TN; j++) {
            int col = n0 + tc * TN + j;
            if (col < N) {
                float v = acc[i][j];
                if (EPI == 1) v += bias[col];
                if (EPI == 2) v *= s;
                C[(long)row * ldc + (long)col * colMul] = v;
            }
        }
    }
}

// ---------------------------------------------------------------------------
// Small kernels
// ---------------------------------------------------------------------------
__global__ void scale_proj_k(const float* __restrict__ proj,
                             float* __restrict__ out, int n)
{
    int i = blockIdx.x * blockDim.x + threadIdx.x;
    if (i < n) out[i] = proj[i] * DNORM;
}

// q feature map: per row r, diag from q_all, stab = row max of dash, exp in place
__global__ void __launch_bounds__(256)
qexp_k(float* __restrict__ qp, const float* __restrict__ qall)
{
    const long r = blockIdx.x;
    const float* drow = qall + r * DDIM;
    float* prow = qp + r * (long)NBF;
    const int tid = threadIdx.x;
    __shared__ float red[256];

    // diag = 0.5 * sum(x^2) * dn^2
    float x = drow[tid];
    red[tid] = x * x;
    __syncthreads();
    for (int s = 128; s > 0; s >>= 1) {
        if (tid < s) red[tid] += red[tid + s];
        __syncthreads();
    }
    const float diag = 0.5f * DNORM2 * red[0];
    __syncthreads();

    // row max
    float mx = -3.4e38f;
    for (int j = tid; j < NBF; j += 256) mx = fmaxf(mx, prow[j]);
    red[tid] = mx;
    __syncthreads();
    for (int s = 128; s > 0; s >>= 1) {
        if (tid < s) red[tid] = fmaxf(red[tid], red[tid + s]);
        __syncthreads();
    }
    const float c = diag + red[0];
    const float ratio = 1.0f / sqrtf((float)NBF);

    for (int j = tid; j < NBF; j += 256)
        prow[j] = ratio * (expf(prow[j] - c) + EPSF);
}

// global max of k_dash per (t,h) slab
__global__ void __launch_bounds__(1024)
kmax_k(const float* __restrict__ kp, float* __restrict__ kmaxout)
{
    const int b = blockIdx.x;
    const float* base = kp + (long)b * NPT * NBF;
    const long n = (long)NPT * NBF;
    float mx = -3.4e38f;
    for (long i = threadIdx.x; i < n; i += 1024) mx = fmaxf(mx, base[i]);
    __shared__ float red[1024];
    red[threadIdx.x] = mx;
    __syncthreads();
    for (int s = 512; s > 0; s >>= 1) {
        if (threadIdx.x < s) red[threadIdx.x] = fmaxf(red[threadIdx.x], red[threadIdx.x + s]);
        __syncthreads();
    }
    if (threadIdx.x == 0) kmaxout[b] = red[0];
}

// k feature map: stab = global slab max
__global__ void __launch_bounds__(256)
kexp_k(float* __restrict__ kp, const float* __restrict__ kall,
       const float* __restrict__ kmax)
{
    const long r = blockIdx.x;
    const int b = (int)(r >> 10);
    const float* drow = kall + r * DDIM;
    float* prow = kp + r * (long)NBF;
    const int tid = threadIdx.x;
    __shared__ float red[256];

    float x = drow[tid];
    red[tid] = x * x;
    __syncthreads();
    for (int s = 128; s > 0; s >>= 1) {
        if (tid < s) red[tid] += red[tid + s];
        __syncthreads();
    }
    const float c = 0.5f * DNORM2 * red[0] + kmax[b];
    const float ratio = 1.0f / sqrtf((float)NBF);

    for (int j = tid; j < NBF; j += 256)
        prow[j] = ratio * (expf(prow[j] - c) + EPSF);
}

// k_sum[b, m] = sum_n k_prime[b, n, m]
__global__ void ksum_k(const float* __restrict__ kp, float* __restrict__ ksum)
{
    const int b = blockIdx.y;
    const int m = blockIdx.x * blockDim.x + threadIdx.x;
    if (m >= NBF) return;
    const float* base = kp + (long)b * NPT * NBF + m;
    float s = 0.f;
    for (int n = 0; n < NPT; n++) s += base[(long)n * NBF];
    ksum[(long)b * NBF + m] = s;
}

// d_inv[r] = 1 / dot(q_prime[r,:], k_sum[b,:])
__global__ void __launch_bounds__(256)
dinv_k(const float* __restrict__ qp, const float* __restrict__ ksum,
       float* __restrict__ dinv)
{
    const long r = blockIdx.x;
    const int b = (int)(r >> 10);
    const float* qrow = qp + r * (long)NBF;
    const float* ks = ksum + (long)b * NBF;
    const int tid = threadIdx.x;
    float s = 0.f;
    for (int j = tid; j < NBF; j += 256) s += qrow[j] * ks[j];
    __shared__ float red[256];
    red[tid] = s;
    __syncthreads();
    for (int st = 128; st > 0; st >>= 1) {
        if (tid < st) red[tid] += red[tid + st];
        __syncthreads();
    }
    if (tid == 0) dinv[r] = 1.0f / red[0];
}

// ---------------------------------------------------------------------------
// Launch
// ---------------------------------------------------------------------------
extern "C" void kernel_launch(void* const* d_in, const int* in_sizes, int n_in,
                              void* d_out, int out_size)
{
    const float* q     = (const float*)d_in[0];
    const float* k     = (const float*)d_in[1];
    const float* v     = (const float*)d_in[2];
    const float* Wq    = (const float*)d_in[3];
    const float* bq    = (const float*)d_in[4];
    const float* Wk    = (const float*)d_in[5];
    const float* bk    = (const float*)d_in[6];
    const float* Wv    = (const float*)d_in[7];
    const float* bv    = (const float*)d_in[8];
    const float* W_out = (const float*)d_in[9];
    const float* b_out = (const float*)d_in[10];
    const float* proj  = (const float*)d_in[11];
    float* out = (float*)d_out;

    float *qall, *kall, *vall, *qp, *kp, *ctx, *outs, *ksum, *dinv, *kmax, *projs;
    cudaGetSymbolAddress((void**)&qall,  g_qall);
    cudaGetSymbolAddress((void**)&kall,  g_kall);
    cudaGetSymbolAddress((void**)&vall,  g_vall);
    cudaGetSymbolAddress((void**)&qp,    g_qp);
    cudaGetSymbolAddress((void**)&kp,    g_kp);
    cudaGetSymbolAddress((void**)&ctx,   g_ctx);
    cudaGetSymbolAddress((void**)&outs,  g_outs);
    cudaGetSymbolAddress((void**)&ksum,  g_ksum);
    cudaGetSymbolAddress((void**)&dinv,  g_dinv);
    cudaGetSymbolAddress((void**)&kmax,  g_kmax);
    cudaGetSymbolAddress((void**)&projs, g_projs);

    // 0) proj * data_normalizer
    scale_proj_k<<<(NBF * DDIM + 255) / 256, 256>>>(proj, projs, NBF * DDIM);

    // 1) per-head projections: [t,h] batched  C[1024,256] = X[t] * W[h] + b[h]
    {
        dim3 grid((DDIM + BN - 1) / BN, (NPT + BM - 1) / BM, BATCH);
        gemm_k<0, 0, 1><<<grid, 256>>>(q, Wq, qall,
            NPT, DDIM, DDIM, DDIM, DDIM, DDIM,
            (long)NPT * DDIM, 0, 0, (long)DDIM * DDIM,
            (long)HH * NPT * DDIM, (long)NPT * DDIM, HH,
            bq, DDIM, nullptr, 0, 0, 1);
        gemm_k<0, 0, 1><<<grid, 256>>>(k, Wk, kall,
            NPT, DDIM, DDIM, DDIM, DDIM, DDIM,
            (long)NPT * DDIM, 0, 0, (long)DDIM * DDIM,
            (long)HH * NPT * DDIM, (long)NPT * DDIM, HH,
            bk, DDIM, nullptr, 0, 0, 1);
        gemm_k<0, 0, 1><<<grid, 256>>>(v, Wv, vall,
            NPT, DDIM, DDIM, DDIM, DDIM, DDIM,
            (long)NPT * DDIM, 0, 0, (long)DDIM * DDIM,
            (long)HH * NPT * DDIM, (long)NPT * DDIM, HH,
            bv, DDIM, nullptr, 0, 0, 1);
    }

    // 2) dash: C[1024,1419] = X_all[b] * projs^T   (NT)
    {
        dim3 grid((NBF + BN - 1) / BN, (NPT + BM - 1) / BM, BATCH);
        gemm_k<0, 1, 0><<<grid, 256>>>(qall, projs, qp,
            NPT, NBF, DDIM, DDIM, DDIM, NBF,
            (long)NPT * DDIM, 0, 0, 0,
            (long)NPT * NBF, 0, 1,
            nullptr, 0, nullptr, 0, 0, 1);
        gemm_k<0, 1, 0><<<grid, 256>>>(kall, projs, kp,
            NPT, NBF, DDIM, DDIM, DDIM, NBF,
            (long)NPT * DDIM, 0, 0, 0,
            (long)NPT * NBF, 0, 1,
            nullptr, 0, nullptr, 0, 0, 1);
    }

    // 3) feature maps (exp in place)
    qexp_k<<<ROWS, 256>>>(qp, qall);
    kmax_k<<<BATCH, 1024>>>(kp, kmax);
    kexp_k<<<ROWS, 256>>>(kp, kall, kmax);
    ksum_k<<<dim3((NBF + 255) / 256, BATCH), 256>>>(kp, ksum);
    dinv_k<<<ROWS, 256>>>(qp, ksum, dinv);

    // 4) context: C[1419,256] = k_prime[b]^T * v_all[b]   (TN)
    {
        dim3 grid((DDIM + BN - 1) / BN, (NBF + BM - 1) / BM, BATCH);
        gemm_k<1, 0, 0><<<grid, 256>>>(kp, vall, ctx,
            NBF, DDIM, NPT, NBF, DDIM, DDIM,
            (long)NPT * NBF, 0, (long)NPT * DDIM, 0,
            (long)NBF * DDIM, 0, 1,
            nullptr, 0, nullptr, 0, 0, 1);
    }

    // 5) out: C[1024,256] = q_prime[b] * ctx[b], *d_inv row scale,
    //    stored permuted into outs[t, n, e*H + h]
    {
        dim3 grid((DDIM + BN - 1) / BN, (NPT + BM - 1) / BM, BATCH);
        gemm_k<0, 0, 2><<<grid, 256>>>(qp, ctx, outs,
            NPT, DDIM, NBF, NBF, DDIM, HDCAT,
            (long)HH * NPT * NBF, (long)NPT * NBF,
            (long)HH * NBF * DDIM, (long)NBF * DDIM,
            (long)NPT * HDCAT, 1, HH,
            nullptr, 0, dinv, (long)HH * NPT, (long)NPT, HH);
    }

    // 6) output projection: rep[8192,256] = outs[8192,2048] * W_out^T + b_out
    {
        dim3 grid((DDIM + BN - 1) / BN, (TT * NPT + BM - 1) / BM, 1);
        gemm_k<0, 1, 1><<<grid, 256>>>(outs, W_out, out,
            TT * NPT, DDIM, HDCAT, HDCAT, HDCAT, DDIM,
            0, 0, 0, 0, 0, 0, 1,
            b_out, 0, nullptr, 0, 0, 1);
    }
}

// round 2
// speedup vs baseline: 1.0456x; 1.0456x over previous
#include <cuda_runtime.h>
#include <math.h>

// ---------------------------------------------------------------------------
// Problem constants (T=8, N=M=1024, H=8, D=256, NB = int(256*ln 256) = 1419)
// ---------------------------------------------------------------------------
#define TT   8
#define NPT  1024
#define HH   8
#define DDIM 256
#define NBF  1419
#define NBP  1424              // NBF padded to multiple of 16 floats (alignment)
#define ROWS (TT * HH * NPT)   // 65536 rows of (t,h,n)
#define BATCH (TT * HH)        // 64
#define HDCAT (HH * DDIM)      // 2048

#define DNORM   0.25f          // 256^-0.25
#define DNORM2  0.0625f
#define EPSF    1e-4f

// ---------------------------------------------------------------------------
// Scratch (device globals; zero-initialized at module load -> padding regions
// that are never written stay 0, which the padded-GEMM math relies on)
// ---------------------------------------------------------------------------
__device__ float g_qall[(size_t)ROWS * DDIM];
__device__ float g_kall[(size_t)ROWS * DDIM];
__device__ float g_vall[(size_t)ROWS * DDIM];
__device__ float g_qp  [(size_t)ROWS * NBP + 4096];   // dash -> q_prime (in place)
__device__ float g_kp  [(size_t)ROWS * NBP + 4096];   // dash -> k_prime (in place)
__device__ float g_ctx [(size_t)BATCH * NBP * DDIM];
__device__ float g_outs[(size_t)TT * NPT * HDCAT];
__device__ float g_ksum[(size_t)BATCH * NBF];
__device__ float g_dinv[(size_t)ROWS];
__device__ float g_kmax[(size_t)BATCH];
__device__ float g_projs[(size_t)NBP * DDIM];         // proj * 0.25, pad rows = 0

// ---------------------------------------------------------------------------
// Double-buffered, float4, packed-f32x2 SGEMM.
//   C[M,N] = op(A)[M,K] * op(B)[K,N]
//   TA=0: A(i,k)=A[i*lda+k]   TA=1: A(i,k)=A[k*lda+i]
//   TB=0: B(k,j)=B[k*ldb+j]   TB=1: B(k,j)=B[j*ldb+k]
//   EPI: 0 plain, 1 +bias[col], 2 *scale[row] (store stride colMul)
//   Requirements: K % 8 == 0; lda/ldb % 4 == 0; M,N % 4 == 0.
//   A-tile overreads past M (TA=1 edge) land in zero-init slack (finite).
// ---------------------------------------------------------------------------
#define BM 128
#define BN 128

template<int TA, int TB, int EPI>
__global__ void __launch_bounds__(256)
gemm2_k(const float* __restrict__ Ag, const float* __restrict__ Bg,
        float* __restrict__ Cg,
        int M, int N, int K, int lda, int ldb, int ldc,
        long aT, long aH, long bT, long bH, long cT, long cH, int Hdiv,
        const float* __restrict__ bias, long biasH,
        const float* __restrict__ scale, long scT, long scH,
        int colMul)
{
    const int bz = blockIdx.z;
    const int t = bz / Hdiv, h = bz % Hdiv;
    const float* A = Ag + (long)t * aT + (long)h * aH;
    const float* B = Bg + (long)t * bT + (long)h * bH;
    float*       C = Cg + (long)t * cT + (long)h * cH;
    const float* biasp  = (EPI == 1) ? bias  + (long)h * biasH : nullptr;
    const float* scalep = (EPI == 2) ? scale + (long)t * scT + (long)h * scH : nullptr;

    // A stored duplicated: As2[k][2m] == As2[k][2m+1] == A(m0+m, k0+k)
    __shared__ __align__(16) float As2[2][8][2 * BM];
    __shared__ __align__(16) float Bs [2][8][BN];

    const int m0 = blockIdx.y * BM;
    const int n0 = blockIdx.x * BN;
    const int tid = threadIdx.x;
    const int tr = tid >> 4;     // 0..15 -> rows tr*8..tr*8+7
    const int tc = tid & 15;     // 0..15 -> cols tc*4..+3 and 64+tc*4..+3

    unsigned long long acc[8][4];
#pragma unroll
    for (int i = 0; i < 8; i++)
#pragma unroll
        for (int j = 0; j < 4; j++) acc[i][j] = 0ull;

    const int nk = K >> 3;
    float4 ra, rb;

#define LOAD_TILES(k0_)                                                        \
    do {                                                                       \
        if (TA == 0) {                                                         \
            int row_ = tid >> 1, kc_ = (tid & 1) << 2;                         \
            int gm_ = m0 + row_;                                               \
            ra = (gm_ < M) ? *(const float4*)(A + (long)gm_ * lda + (k0_) + kc_)\
                           : make_float4(0.f, 0.f, 0.f, 0.f);                  \
        } else {                                                               \
            int kk_ = tid >> 5, m4_ = (tid & 31) << 2;                         \
            int gm_ = m0 + m4_;                                                \
            ra = (gm_ < M) ? *(const float4*)(A + (long)((k0_) + kk_) * lda + gm_)\
                           : make_float4(0.f, 0.f, 0.f, 0.f);                  \
        }                                                                      \
        if (TB == 0) {                                                         \
            int kk_ = tid >> 5, n4_ = (tid & 31) << 2;                         \
            int gn_ = n0 + n4_;                                                \
            rb = (gn_ < N) ? *(const float4*)(B + (long)((k0_) + kk_) * ldb + gn_)\
                           : make_float4(0.f, 0.f, 0.f, 0.f);                  \
        } else {                                                               \
            int row_ = tid >> 1, kc_ = (tid & 1) << 2;                         \
            int gn_ = n0 + row_;                                               \
            rb = (gn_ < N) ? *(const float4*)(B + (long)gn_ * ldb + (k0_) + kc_)\
                           : make_float4(0.f, 0.f, 0.f, 0.f);                  \
        }                                                                      \
    } while (0)

#define STORE_TILES(buf_)                                                      \
    do {                                                                       \
        if (TA == 0) {                                                         \
            int row_ = tid >> 1, kc_ = (tid & 1) << 2;                         \
            *(float2*)&As2[buf_][kc_ + 0][2 * row_] = make_float2(ra.x, ra.x); \
            *(float2*)&As2[buf_][kc_ + 1][2 * row_] = make_float2(ra.y, ra.y); \
            *(float2*)&As2[buf_][kc_ + 2][2 * row_] = make_float2(ra.z, ra.z); \
            *(float2*)&As2[buf_][kc_ + 3][2 * row_] = make_float2(ra.w, ra.w); \
        } else {                                                               \
            int kk_ = tid >> 5, m4_ = (tid & 31) << 2;                         \
            *(float4*)&As2[buf_][kk_][2 * m4_ + 0] = make_float4(ra.x, ra.x, ra.y, ra.y); \
            *(float4*)&As2[buf_][kk_][2 * m4_ + 4] = make_float4(ra.z, ra.z, ra.w, ra.w); \
        }                                                                      \
        if (TB == 0) {                                                         \
            int kk_ = tid >> 5, n4_ = (tid & 31) << 2;                         \
            *(float4*)&Bs[buf_][kk_][n4_] = rb;                                \
        } else {                                                               \
            int row_ = tid >> 1, kc_ = (tid & 1) << 2;                         \
            Bs[buf_][kc_ + 0][row_] = rb.x;                                    \
            Bs[buf_][kc_ + 1][row_] = rb.y;                                    \
            Bs[buf_][kc_ + 2][row_] = rb.z;                                    \
            Bs[buf_][kc_ + 3][row_] = rb.w;                                    \
        }                                                                      \
    } while (0)

    LOAD_TILES(0);
    STORE_TILES(0);
    __syncthreads();

    int buf = 0;
    for (int kt = 0; kt < nk; kt++) {
        const bool pf = (kt + 1 < nk);
        if (pf) LOAD_TILES((kt + 1) << 3);

#pragma unroll
        for (int kk = 0; kk < 8; kk++) {
            unsigned long long a[8], b[4];
            const float* ap = &As2[buf][kk][tr << 4];
            ulonglong2 t0 = *(const ulonglong2*)(ap + 0);
            ulonglong2 t1 = *(const ulonglong2*)(ap + 4);
            ulonglong2 t2 = *(const ulonglong2*)(ap + 8);
            ulonglong2 t3 = *(const ulonglong2*)(ap + 12);
            a[0] = t0.x; a[1] = t0.y; a[2] = t1.x; a[3] = t1.y;
            a[4] = t2.x; a[5] = t2.y; a[6] = t3.x; a[7] = t3.y;
            const float* bp = &Bs[buf][kk][tc << 2];
            ulonglong2 u0 = *(const ulonglong2*)(bp);
            ulonglong2 u1 = *(const ulonglong2*)(bp + 64);
            b[0] = u0.x; b[1] = u0.y; b[2] = u1.x; b[3] = u1.y;
#pragma unroll
            for (int i = 0; i < 8; i++)
#pragma unroll
                for (int j = 0; j < 4; j++)
                    asm("fma.rn.f32x2 %0, %1, %2, %0;"
                        : "+l"(acc[i][j]) : "l"(a[i]), "l"(b[j]));
        }

        if (pf) STORE_TILES(buf ^ 1);
        __syncthreads();
        buf ^= 1;
    }

    // ---- epilogue
#pragma unroll
    for (int i = 0; i < 8; i++) {
        int row = m0 + (tr << 3) + i;
        if (row >= M) continue;
        float s = (EPI == 2) ? scalep[row] : 1.f;
        float* crow = C + (long)row * ldc;
#pragma unroll
        for (int p = 0; p < 4; p++) {
            float x, y;
            asm("mov.b64 {%0, %1}, %2;" : "=f"(x), "=f"(y) : "l"(acc[i][p]));
            int c0 = n0 + ((p < 2) ? ((tc << 2) + (p << 1))
                                   : (64 + (tc << 2) + ((p - 2) << 1)));
            if (c0 < N) {
                float v = x;
                if (EPI == 1) v += biasp[c0];
                if (EPI == 2) v *= s;
                crow[(long)c0 * colMul] = v;
            }
            if (c0 + 1 < N) {
                float v = y;
                if (EPI == 1) v += biasp[c0 + 1];
                if (EPI == 2) v *= s;
                crow[(long)(c0 + 1) * colMul] = v;
            }
        }
    }
#undef LOAD_TILES
#undef STORE_TILES
}

// ---------------------------------------------------------------------------
// Small kernels
// ---------------------------------------------------------------------------
__global__ void scale_proj_k(const float* __restrict__ proj,
                             float* __restrict__ out, int n)
{
    int i = blockIdx.x * blockDim.x + threadIdx.x;
    if (i < n) out[i] = proj[i] * DNORM;
}

// q feature map: per row r, diag from q_all, stab = row max of dash, exp in place
__global__ void __launch_bounds__(256)
qexp_k(float* __restrict__ qp, const float* __restrict__ qall)
{
    const long r = blockIdx.x;
    const float* drow = qall + r * DDIM;
    float* prow = qp + r * (long)NBP;
    const int tid = threadIdx.x;
    __shared__ float red[256];

    float x = drow[tid];
    red[tid] = x * x;
    __syncthreads();
    for (int s = 128; s > 0; s >>= 1) {
        if (tid < s) red[tid] += red[tid + s];
        __syncthreads();
    }
    const float diag = 0.5f * DNORM2 * red[0];
    __syncthreads();

    float mx = -3.4e38f;
    for (int j = tid; j < NBF; j += 256) mx = fmaxf(mx, prow[j]);
    red[tid] = mx;
    __syncthreads();
    for (int s = 128; s > 0; s >>= 1) {
        if (tid < s) red[tid] = fmaxf(red[tid], red[tid + s]);
        __syncthreads();
    }
    const float c = diag + red[0];
    const float ratio = 1.0f / sqrtf((float)NBF);

    for (int j = tid; j < NBF; j += 256)
        prow[j] = ratio * (expf(prow[j] - c) + EPSF);
}

// global max of k_dash per (t,h) slab (skips padding columns)
__global__ void __launch_bounds__(1024)
kmax_k(const float* __restrict__ kp, float* __restrict__ kmaxout)
{
    const int b = blockIdx.x;
    const float* base = kp + (size_t)b * NPT * NBP;
    float mx = -3.4e38f;
    for (int r = 0; r < NPT; r++) {
        const float* row = base + (size_t)r * NBP;
        for (int j = threadIdx.x; j < NBF; j += 1024)
            mx = fmaxf(mx, row[j]);
    }
    __shared__ float red[1024];
    red[threadIdx.x] = mx;
    __syncthreads();
    for (int s = 512; s > 0; s >>= 1) {
        if (threadIdx.x < s)
            red[threadIdx.x] = fmaxf(red[threadIdx.x], red[threadIdx.x + s]);
        __syncthreads();
    }
    if (threadIdx.x == 0) kmaxout[b] = red[0];
}

// k feature map: stab = global slab max
__global__ void __launch_bounds__(256)
kexp_k(float* __restrict__ kp, const float* __restrict__ kall,
       const float* __restrict__ kmax)
{
    const long r = blockIdx.x;
    const int b = (int)(r >> 10);
    const float* drow = kall + r * DDIM;
    float* prow = kp + r * (long)NBP;
    const int tid = threadIdx.x;
    __shared__ float red[256];

    float x = drow[tid];
    red[tid] = x * x;
    __syncthreads();
    for (int s = 128; s > 0; s >>= 1) {
        if (tid < s) red[tid] += red[tid + s];
        __syncthreads();
    }
    const float c = 0.5f * DNORM2 * red[0] + kmax[b];
    const float ratio = 1.0f / sqrtf((float)NBF);

    for (int j = tid; j < NBF; j += 256)
        prow[j] = ratio * (expf(prow[j] - c) + EPSF);
}

// k_sum[b, m] = sum_n k_prime[b, n, m]
__global__ void ksum_k(const float* __restrict__ kp, float* __restrict__ ksum)
{
    const int b = blockIdx.y;
    const int m = blockIdx.x * blockDim.x + threadIdx.x;
    if (m >= NBF) return;
    const float* base = kp + (size_t)b * NPT * NBP + m;
    float s = 0.f;
    for (int n = 0; n < NPT; n++) s += base[(size_t)n * NBP];
    ksum[(long)b * NBF + m] = s;
}

// d_inv[r] = 1 / dot(q_prime[r,:], k_sum[b,:])
__global__ void __launch_bounds__(256)
dinv_k(const float* __restrict__ qp, const float* __restrict__ ksum,
       float* __restrict__ dinv)
{
    const long r = blockIdx.x;
    const int b = (int)(r >> 10);
    const float* qrow = qp + r * (long)NBP;
    const float* ks = ksum + (long)b * NBF;
    const int tid = threadIdx.x;
    float s = 0.f;
    for (int j = tid; j < NBF; j += 256) s += qrow[j] * ks[j];
    __shared__ float red[256];
    red[tid] = s;
    __syncthreads();
    for (int st = 128; st > 0; st >>= 1) {
        if (tid < st) red[tid] += red[tid + st];
        __syncthreads();
    }
    if (tid == 0) dinv[r] = 1.0f / red[0];
}

// ---------------------------------------------------------------------------
// Launch
// ---------------------------------------------------------------------------
extern "C" void kernel_launch(void* const* d_in, const int* in_sizes, int n_in,
                              void* d_out, int out_size)
{
    const float* q     = (const float*)d_in[0];
    const float* k     = (const float*)d_in[1];
    const float* v     = (const float*)d_in[2];
    const float* Wq    = (const float*)d_in[3];
    const float* bq    = (const float*)d_in[4];
    const float* Wk    = (const float*)d_in[5];
    const float* bk    = (const float*)d_in[6];
    const float* Wv    = (const float*)d_in[7];
    const float* bv    = (const float*)d_in[8];
    const float* W_out = (const float*)d_in[9];
    const float* b_out = (const float*)d_in[10];
    const float* proj  = (const float*)d_in[11];
    float* out = (float*)d_out;

    float *qall, *kall, *vall, *qp, *kp, *ctx, *outs, *ksum, *dinv, *kmax, *projs;
    cudaGetSymbolAddress((void**)&qall,  g_qall);
    cudaGetSymbolAddress((void**)&kall,  g_kall);
    cudaGetSymbolAddress((void**)&vall,  g_vall);
    cudaGetSymbolAddress((void**)&qp,    g_qp);
    cudaGetSymbolAddress((void**)&kp,    g_kp);
    cudaGetSymbolAddress((void**)&ctx,   g_ctx);
    cudaGetSymbolAddress((void**)&outs,  g_outs);
    cudaGetSymbolAddress((void**)&ksum,  g_ksum);
    cudaGetSymbolAddress((void**)&dinv,  g_dinv);
    cudaGetSymbolAddress((void**)&kmax,  g_kmax);
    cudaGetSymbolAddress((void**)&projs, g_projs);

    // 0) proj * data_normalizer (pad rows of g_projs stay zero-init)
    scale_proj_k<<<(NBF * DDIM + 255) / 256, 256>>>(proj, projs, NBF * DDIM);

    // 1) per-head projections: C[1024,256] = X[t] * W[h] + b[h]
    {
        dim3 grid(DDIM / BN, NPT / BM, BATCH);
        gemm2_k<0, 0, 1><<<grid, 256>>>(q, Wq, qall,
            NPT, DDIM, DDIM, DDIM, DDIM, DDIM,
            (long)NPT * DDIM, 0, 0, (long)DDIM * DDIM,
            (long)HH * NPT * DDIM, (long)NPT * DDIM, HH,
            bq, DDIM, nullptr, 0, 0, 1);
        gemm2_k<0, 0, 1><<<grid, 256>>>(k, Wk, kall,
            NPT, DDIM, DDIM, DDIM, DDIM, DDIM,
            (long)NPT * DDIM, 0, 0, (long)DDIM * DDIM,
            (long)HH * NPT * DDIM, (long)NPT * DDIM, HH,
            bk, DDIM, nullptr, 0, 0, 1);
        gemm2_k<0, 0, 1><<<grid, 256>>>(v, Wv, vall,
            NPT, DDIM, DDIM, DDIM, DDIM, DDIM,
            (long)NPT * DDIM, 0, 0, (long)DDIM * DDIM,
            (long)HH * NPT * DDIM, (long)NPT * DDIM, HH,
            bv, DDIM, nullptr, 0, 0, 1);
    }

    // 2) dash: C[1024,1424] = X_all[b] * projs^T  (pad cols -> 0)
    {
        dim3 grid((NBP + BN - 1) / BN, NPT / BM, BATCH);
        gemm2_k<0, 1, 0><<<grid, 256>>>(qall, projs, qp,
            NPT, NBP, DDIM, DDIM, DDIM, NBP,
            (long)NPT * DDIM, 0, 0, 0,
            (long)NPT * NBP, 0, 1,
            nullptr, 0, nullptr, 0, 0, 1);
        gemm2_k<0, 1, 0><<<grid, 256>>>(kall, projs, kp,
            NPT, NBP, DDIM, DDIM, DDIM, NBP,
            (long)NPT * DDIM, 0, 0, 0,
            (long)NPT * NBP, 0, 1,
            nullptr, 0, nullptr, 0, 0, 1);
    }

    // 3) feature maps (exp in place; pads untouched, stay 0)
    qexp_k<<<ROWS, 256>>>(qp, qall);
    kmax_k<<<BATCH, 1024>>>(kp, kmax);
    kexp_k<<<ROWS, 256>>>(kp, kall, kmax);
    ksum_k<<<dim3((NBF + 255) / 256, BATCH), 256>>>(kp, ksum);
    dinv_k<<<ROWS, 256>>>(qp, ksum, dinv);

    // 4) context: C[1424,256] = k_prime[b]^T * v_all[b]  (pad rows -> 0)
    {
        dim3 grid(DDIM / BN, (NBP + BM - 1) / BM, BATCH);
        gemm2_k<1, 0, 0><<<grid, 256>>>(kp, vall, ctx,
            NBP, DDIM, NPT, NBP, DDIM, DDIM,
            (long)NPT * NBP, 0, (long)NPT * DDIM, 0,
            (long)NBP * DDIM, 0, 1,
            nullptr, 0, nullptr, 0, 0, 1);
    }

    // 5) out: C[1024,256] = q_prime[b] * ctx[b] (K=NBP; pad K terms are 0*0),
    //    row-scaled by d_inv, stored permuted into outs[t, n, e*H + h]
    {
        dim3 grid(DDIM / BN, NPT / BM, BATCH);
        gemm2_k<0, 0, 2><<<grid, 256>>>(qp, ctx, outs,
            NPT, DDIM, NBP, NBP, DDIM, HDCAT,
            (long)HH * NPT * NBP, (long)NPT * NBP,
            (long)HH * NBP * DDIM, (long)NBP * DDIM,
            (long)NPT * HDCAT, 1, HH,
            nullptr, 0, dinv, (long)HH * NPT, (long)NPT, HH);
    }

    // 6) output projection: rep[8192,256] = outs[8192,2048] * W_out^T + b_out
    {
        dim3 grid(DDIM / BN, (TT * NPT) / BM, 1);
        gemm2_k<0, 1, 1><<<grid, 256>>>(outs, W_out, out,
            TT * NPT, DDIM, HDCAT, HDCAT, HDCAT, DDIM,
            0, 0, 0, 0, 0, 0, 1,
            b_out, 0, nullptr, 0, 0, 1);
    }
}

// round 4
// speedup vs baseline: 1.6279x; 1.5569x over previous
#include <cuda_runtime.h>
#include <cuda_bf16.h>
#include <cstdint>
#include <math.h>

// ---------------------------------------------------------------------------
// Problem constants (T=8, N=M=1024, H=8, D=256, NB = int(256*ln 256) = 1419)
// ---------------------------------------------------------------------------
#define TT   8
#define NPT  1024
#define HH   8
#define DDIM 256
#define NBF  1419
#define NBP  1440              // padded to multiple of 32
#define ROWS (TT * HH * NPT)   // 65536
#define BATCH (TT * HH)        // 64
#define HDCAT (HH * DDIM)      // 2048

#define DNORM   0.25f          // 256^-0.25
#define DNORM2  0.0625f
#define EPSF    1e-4f

// ---------------------------------------------------------------------------
// Scratch (device globals, zero-init at load; pad regions rely on 0)
// ---------------------------------------------------------------------------
__device__ float g_qall[(size_t)ROWS * DDIM];
__device__ float g_kall[(size_t)ROWS * DDIM];
__device__ float g_vall[(size_t)ROWS * DDIM];
__device__ float g_qp  [(size_t)ROWS * NBP];
__device__ float g_kp  [(size_t)ROWS * NBP];
__device__ float g_ctx [(size_t)BATCH * NBP * DDIM];
__device__ float g_outs[(size_t)TT * NPT * HDCAT];
__device__ float g_ksum[(size_t)BATCH * NBF];
__device__ float g_dinv[(size_t)ROWS];
__device__ float g_kmax[(size_t)BATCH];
__device__ float g_projs[(size_t)NBP * DDIM];   // proj * 0.25; pad rows = 0

// ---------------------------------------------------------------------------
// bf16 split helpers
// ---------------------------------------------------------------------------
__device__ __forceinline__ void split2(float x, float y,
                                       uint32_t& hi, uint32_t& lo)
{
    __nv_bfloat16 hx = __float2bfloat16_rn(x);
    __nv_bfloat16 hy = __float2bfloat16_rn(y);
    float lx = x - __bfloat162float(hx);
    float ly = y - __bfloat162float(hy);
    __nv_bfloat16 lxb = __float2bfloat16_rn(lx);
    __nv_bfloat16 lyb = __float2bfloat16_rn(ly);
    hi = ((uint32_t)__bfloat16_as_ushort(hy) << 16) | __bfloat16_as_ushort(hx);
    lo = ((uint32_t)__bfloat16_as_ushort(lyb) << 16) | __bfloat16_as_ushort(lxb);
}

__device__ __forceinline__ void mma16816(float* c, uint32_t a0, uint32_t a1,
                                         uint32_t a2, uint32_t a3,
                                         uint32_t b0, uint32_t b1)
{
    asm volatile(
        "mma.sync.aligned.m16n8k16.row.col.f32.bf16.bf16.f32 "
        "{%0,%1,%2,%3},{%4,%5,%6,%7},{%8,%9},{%0,%1,%2,%3};"
        : "+f"(c[0]), "+f"(c[1]), "+f"(c[2]), "+f"(c[3])
        : "r"(a0), "r"(a1), "r"(a2), "r"(a3), "r"(b0), "r"(b1));
}

// ---------------------------------------------------------------------------
// SMEM tile geometry: 128 rows x 32 k, row stride 40 bf16 (conflict-free frags)
// Tiles per buffer: A_hi, A_lo, B_hi, B_lo (5120 bf16 each); 2 buffers.
// ---------------------------------------------------------------------------
#define TSTRIDE 40
#define TILE_E  (128 * TSTRIDE)        // 5120 bf16
#define BUF_E   (4 * TILE_E)           // 20480 bf16
#define MMASMEM_BYTES (2 * BUF_E * 2)  // 81920 bytes

// row-pattern global load: source row-major [rows][K]; 4 float4 per thread
__device__ __forceinline__ void loadg_row(const float* __restrict__ P, int ldp,
                                          int rows, int r0, int k0, int tid,
                                          float4* v)
{
    const int r = tid & 127, half = tid >> 7;
    const int gr = r0 + r;
    const bool ok = gr < rows;
    const float* p = P + (long)gr * ldp + k0 + half * 16;
#pragma unroll
    for (int j = 0; j < 4; j++)
        v[j] = ok ? *(const float4*)(p + j * 4) : make_float4(0.f, 0.f, 0.f, 0.f);
}

__device__ __forceinline__ void store_row(__nv_bfloat16* hi, __nv_bfloat16* lo,
                                          int tid, const float4* v)
{
    const int r = tid & 127, half = tid >> 7;
#pragma unroll
    for (int j = 0; j < 4; j++) {
        const int c = half * 16 + j * 4;
        uint32_t h0, l0, h1, l1;
        split2(v[j].x, v[j].y, h0, l0);
        split2(v[j].z, v[j].w, h1, l1);
        *(uint2*)(hi + r * TSTRIDE + c) = make_uint2(h0, h1);
        *(uint2*)(lo + r * TSTRIDE + c) = make_uint2(l0, l1);
    }
}

// col-pattern global load: source [K][rows] (rows contiguous)
__device__ __forceinline__ void loadg_col(const float* __restrict__ P, int ldp,
                                          int rows, int r0, int k0, int tid,
                                          float4* v)
{
    const int lk = tid & 31, mq = tid >> 5;
    const float* p = P + (long)(k0 + lk) * ldp + r0 + mq * 16;
#pragma unroll
    for (int j = 0; j < 4; j++) {
        const bool ok = (r0 + mq * 16 + j * 4) < rows;
        v[j] = ok ? *(const float4*)(p + j * 4) : make_float4(0.f, 0.f, 0.f, 0.f);
    }
}

__device__ __forceinline__ void store_col(__nv_bfloat16* hi, __nv_bfloat16* lo,
                                          int tid, const float4* v)
{
    const int lk = tid & 31, mq = tid >> 5;
#pragma unroll
    for (int j = 0; j < 4; j++) {
        float vv[4] = {v[j].x, v[j].y, v[j].z, v[j].w};
#pragma unroll
        for (int e = 0; e < 4; e++) {
            const int m = mq * 16 + j * 4 + e;
            __nv_bfloat16 hb = __float2bfloat16_rn(vv[e]);
            float lf = vv[e] - __bfloat162float(hb);
            hi[m * TSTRIDE + lk] = hb;
            lo[m * TSTRIDE + lk] = __float2bfloat16_rn(lf);
        }
    }
}

// ---------------------------------------------------------------------------
// bf16x3 mma.sync GEMM:  C[M,N] = op(A)[M,K] * op(B)[K,N]
//   TA=0: A(i,k)=A[i*lda+k]   TA=1: A(i,k)=A[k*lda+i]
//   TB=0: B(k,j)=B[k*ldb+j]   TB=1: B(k,j)=B[j*ldb+k]
//   EPI: 0 plain, 1 +bias[col], 2 *scale[row] (store stride colMul)
//   Requirements: K % 32 == 0, M % 4 == 0, lda/ldb % 4 == 0.
// 128x128 CTA tile, 256 threads (8 warps of 64x32).
// ---------------------------------------------------------------------------
template<int TA, int TB, int EPI>
__global__ void __launch_bounds__(256)
gemm_mma(const float* __restrict__ Ag, const float* __restrict__ Bg,
         float* __restrict__ Cg,
         int M, int N, int K, int lda, int ldb, int ldc,
         long aT, long aH, long bT, long bH, long cT, long cH, int Hdiv,
         const float* __restrict__ bias, long biasH,
         const float* __restrict__ scale, long scT, long scH,
         int colMul)
{
    extern __shared__ __nv_bfloat16 smb[];

    const int tid = threadIdx.x;
    const int wid = tid >> 5, lane = tid & 31;
    const int warp_m = wid >> 2, warp_n = wid & 3;   // 2 x 4 warp grid
    const int g = lane >> 2, tg = lane & 3;

    const int bz = blockIdx.z;
    const int t = bz / Hdiv, h = bz % Hdiv;
    const float* A = Ag + (long)t * aT + (long)h * aH;
    const float* B = Bg + (long)t * bT + (long)h * bH;
    float*       C = Cg + (long)t * cT + (long)h * cH;
    const float* biasp  = (EPI == 1) ? bias  + (long)h * biasH : nullptr;
    const float* scalep = (EPI == 2) ? scale + (long)t * scT + (long)h * scH : nullptr;

    const int m0 = blockIdx.y * 128;
    const int n0 = blockIdx.x * 128;

    float acc[4][4][4];
#pragma unroll
    for (int i = 0; i < 4; i++)
#pragma unroll
        for (int j = 0; j < 4; j++)
#pragma unroll
            for (int e = 0; e < 4; e++) acc[i][j][e] = 0.f;

    const int S = K >> 5;
    float4 va[4], vb[4];

    // ---- stage 0
    if (TA == 0) loadg_row(A, lda, M, m0, 0, tid, va);
    else         loadg_col(A, lda, M, m0, 0, tid, va);
    if (TB == 1) loadg_row(B, ldb, N, n0, 0, tid, vb);
    else         loadg_col(B, ldb, N, n0, 0, tid, vb);
    {
        __nv_bfloat16* bb = smb;
        if (TA == 0) store_row(bb, bb + TILE_E, tid, va);
        else         store_col(bb, bb + TILE_E, tid, va);
        if (TB == 1) store_row(bb + 2 * TILE_E, bb + 3 * TILE_E, tid, vb);
        else         store_col(bb + 2 * TILE_E, bb + 3 * TILE_E, tid, vb);
    }
    __syncthreads();

    int buf = 0;
    for (int s = 0; s < S; s++) {
        const bool pf = (s + 1 < S);
        if (pf) {
            const int k0 = (s + 1) << 5;
            if (TA == 0) loadg_row(A, lda, M, m0, k0, tid, va);
            else         loadg_col(A, lda, M, m0, k0, tid, va);
            if (TB == 1) loadg_row(B, ldb, N, n0, k0, tid, vb);
            else         loadg_col(B, ldb, N, n0, k0, tid, vb);
        }

        // ---- compute on buf
        const __nv_bfloat16* bb = smb + buf * BUF_E;
        const __nv_bfloat16* Ah = bb;
        const __nv_bfloat16* Al = bb + TILE_E;
        const __nv_bfloat16* Bh = bb + 2 * TILE_E;
        const __nv_bfloat16* Bl = bb + 3 * TILE_E;

#pragma unroll
        for (int ks = 0; ks < 2; ks++) {
            const int ko = ks << 4;
            uint32_t bh[4][2], bl[4][2];
#pragma unroll
            for (int nb = 0; nb < 4; nb++) {
                const int n = warp_n * 32 + nb * 8 + g;
                const __nv_bfloat16* ph = Bh + n * TSTRIDE + ko + 2 * tg;
                const __nv_bfloat16* pl = Bl + n * TSTRIDE + ko + 2 * tg;
                bh[nb][0] = *(const uint32_t*)ph;
                bh[nb][1] = *(const uint32_t*)(ph + 8);
                bl[nb][0] = *(const uint32_t*)pl;
                bl[nb][1] = *(const uint32_t*)(pl + 8);
            }
#pragma unroll
            for (int ma = 0; ma < 4; ma++) {
                const int m = warp_m * 64 + ma * 16 + g;
                const __nv_bfloat16* ph = Ah + m * TSTRIDE + ko + 2 * tg;
                const __nv_bfloat16* pl = Al + m * TSTRIDE + ko + 2 * tg;
                uint32_t ah0 = *(const uint32_t*)ph;
                uint32_t ah1 = *(const uint32_t*)(ph + 8 * TSTRIDE);
                uint32_t ah2 = *(const uint32_t*)(ph + 8);
                uint32_t ah3 = *(const uint32_t*)(ph + 8 * TSTRIDE + 8);
                uint32_t al0 = *(const uint32_t*)pl;
                uint32_t al1 = *(const uint32_t*)(pl + 8 * TSTRIDE);
                uint32_t al2 = *(const uint32_t*)(pl + 8);
                uint32_t al3 = *(const uint32_t*)(pl + 8 * TSTRIDE + 8);
#pragma unroll
                for (int nb = 0; nb < 4; nb++) {
                    mma16816(acc[ma][nb], ah0, ah1, ah2, ah3, bh[nb][0], bh[nb][1]);
                    mma16816(acc[ma][nb], ah0, ah1, ah2, ah3, bl[nb][0], bl[nb][1]);
                    mma16816(acc[ma][nb], al0, al1, al2, al3, bh[nb][0], bh[nb][1]);
                }
            }
        }

        if (pf) {
            __nv_bfloat16* nb_ = smb + (buf ^ 1) * BUF_E;
            if (TA == 0) store_row(nb_, nb_ + TILE_E, tid, va);
            else         store_col(nb_, nb_ + TILE_E, tid, va);
            if (TB == 1) store_row(nb_ + 2 * TILE_E, nb_ + 3 * TILE_E, tid, vb);
            else         store_col(nb_ + 2 * TILE_E, nb_ + 3 * TILE_E, tid, vb);
        }
        __syncthreads();
        buf ^= 1;
    }

    // ---- epilogue
#pragma unroll
    for (int ma = 0; ma < 4; ma++) {
        const int rbase = m0 + warp_m * 64 + ma * 16 + g;
#pragma unroll
        for (int hf = 0; hf < 2; hf++) {
            const int row = rbase + hf * 8;
            if (row >= M) continue;
            const float sc = (EPI == 2) ? scalep[row] : 1.f;
            float* crow = C + (long)row * ldc;
#pragma unroll
            for (int nb = 0; nb < 4; nb++) {
                const int col = n0 + warp_n * 32 + nb * 8 + 2 * tg;
                float v0 = acc[ma][nb][hf * 2 + 0];
                float v1 = acc[ma][nb][hf * 2 + 1];
                if (col < N) {
                    if (EPI == 1) v0 += biasp[col];
                    if (EPI == 2) v0 *= sc;
                    crow[(long)col * colMul] = v0;
                }
                if (col + 1 < N) {
                    if (EPI == 1) v1 += biasp[col + 1];
                    if (EPI == 2) v1 *= sc;
                    crow[(long)(col + 1) * colMul] = v1;
                }
            }
        }
    }
}

// ---------------------------------------------------------------------------
// Small kernels
// ---------------------------------------------------------------------------
__global__ void scale_proj_k(const float* __restrict__ proj,
                             float* __restrict__ out, int n)
{
    int i = blockIdx.x * blockDim.x + threadIdx.x;
    if (i < n) out[i] = proj[i] * DNORM;
}

__global__ void __launch_bounds__(256)
qexp_k(float* __restrict__ qp, const float* __restrict__ qall)
{
    const long r = blockIdx.x;
    const float* drow = qall + r * DDIM;
    float* prow = qp + r * (long)NBP;
    const int tid = threadIdx.x;
    __shared__ float red[256];

    float x = drow[tid];
    red[tid] = x * x;
    __syncthreads();
    for (int s = 128; s > 0; s >>= 1) {
        if (tid < s) red[tid] += red[tid + s];
        __syncthreads();
    }
    const float diag = 0.5f * DNORM2 * red[0];
    __syncthreads();

    float mx = -3.4e38f;
    for (int j = tid; j < NBF; j += 256) mx = fmaxf(mx, prow[j]);
    red[tid] = mx;
    __syncthreads();
    for (int s = 128; s > 0; s >>= 1) {
        if (tid < s) red[tid] = fmaxf(red[tid], red[tid + s]);
        __syncthreads();
    }
    const float c = diag + red[0];
    const float ratio = 1.0f / sqrtf((float)NBF);

    for (int j = tid; j < NBF; j += 256)
        prow[j] = ratio * (expf(prow[j] - c) + EPSF);
}

__global__ void __launch_bounds__(1024)
kmax_k(const float* __restrict__ kp, float* __restrict__ kmaxout)
{
    const int b = blockIdx.x;
    const float* base = kp + (size_t)b * NPT * NBP;
    float mx = -3.4e38f;
    for (int r = 0; r < NPT; r++) {
        const float* row = base + (size_t)r * NBP;
        for (int j = threadIdx.x; j < NBF; j += 1024)
            mx = fmaxf(mx, row[j]);
    }
    __shared__ float red[1024];
    red[threadIdx.x] = mx;
    __syncthreads();
    for (int s = 512; s > 0; s >>= 1) {
        if (threadIdx.x < s)
            red[threadIdx.x] = fmaxf(red[threadIdx.x], red[threadIdx.x + s]);
        __syncthreads();
    }
    if (threadIdx.x == 0) kmaxout[b] = red[0];
}

__global__ void __launch_bounds__(256)
kexp_k(float* __restrict__ kp, const float* __restrict__ kall,
       const float* __restrict__ kmax)
{
    const long r = blockIdx.x;
    const int b = (int)(r >> 10);
    const float* drow = kall + r * DDIM;
    float* prow = kp + r * (long)NBP;
    const int tid = threadIdx.x;
    __shared__ float red[256];

    float x = drow[tid];
    red[tid] = x * x;
    __syncthreads();
    for (int s = 128; s > 0; s >>= 1) {
        if (tid < s) red[tid] += red[tid + s];
        __syncthreads();
    }
    const float c = 0.5f * DNORM2 * red[0] + kmax[b];
    const float ratio = 1.0f / sqrtf((float)NBF);

    for (int j = tid; j < NBF; j += 256)
        prow[j] = ratio * (expf(prow[j] - c) + EPSF);
}

__global__ void ksum_k(const float* __restrict__ kp, float* __restrict__ ksum)
{
    const int b = blockIdx.y;
    const int m = blockIdx.x * blockDim.x + threadIdx.x;
    if (m >= NBF) return;
    const float* base = kp + (size_t)b * NPT * NBP + m;
    float s = 0.f;
    for (int n = 0; n < NPT; n++) s += base[(size_t)n * NBP];
    ksum[(long)b * NBF + m] = s;
}

__global__ void __launch_bounds__(256)
dinv_k(const float* __restrict__ qp, const float* __restrict__ ksum,
       float* __restrict__ dinv)
{
    const long r = blockIdx.x;
    const int b = (int)(r >> 10);
    const float* qrow = qp + r * (long)NBP;
    const float* ks = ksum + (long)b * NBF;
    const int tid = threadIdx.x;
    float s = 0.f;
    for (int j = tid; j < NBF; j += 256) s += qrow[j] * ks[j];
    __shared__ float red[256];
    red[tid] = s;
    __syncthreads();
    for (int st = 128; st > 0; st >>= 1) {
        if (tid < st) red[tid] += red[tid + st];
        __syncthreads();
    }
    if (tid == 0) dinv[r] = 1.0f / red[0];
}

// ---------------------------------------------------------------------------
// Launch
// ---------------------------------------------------------------------------
extern "C" void kernel_launch(void* const* d_in, const int* in_sizes, int n_in,
                              void* d_out, int out_size)
{
    const float* q     = (const float*)d_in[0];
    const float* k     = (const float*)d_in[1];
    const float* v     = (const float*)d_in[2];
    const float* Wq    = (const float*)d_in[3];
    const float* bq    = (const float*)d_in[4];
    const float* Wk    = (const float*)d_in[5];
    const float* bk    = (const float*)d_in[6];
    const float* Wv    = (const float*)d_in[7];
    const float* bv    = (const float*)d_in[8];
    const float* W_out = (const float*)d_in[9];
    const float* b_out = (const float*)d_in[10];
    const float* proj  = (const float*)d_in[11];
    float* out = (float*)d_out;

    float *qall, *kall, *vall, *qp, *kp, *ctx, *outs, *ksum, *dinv, *kmax, *projs;
    cudaGetSymbolAddress((void**)&qall,  g_qall);
    cudaGetSymbolAddress((void**)&kall,  g_kall);
    cudaGetSymbolAddress((void**)&vall,  g_vall);
    cudaGetSymbolAddress((void**)&qp,    g_qp);
    cudaGetSymbolAddress((void**)&kp,    g_kp);
    cudaGetSymbolAddress((void**)&ctx,   g_ctx);
    cudaGetSymbolAddress((void**)&outs,  g_outs);
    cudaGetSymbolAddress((void**)&ksum,  g_ksum);
    cudaGetSymbolAddress((void**)&dinv,  g_dinv);
    cudaGetSymbolAddress((void**)&kmax,  g_kmax);
    cudaGetSymbolAddress((void**)&projs, g_projs);

    cudaFuncSetAttribute(gemm_mma<0,0,1>, cudaFuncAttributeMaxDynamicSharedMemorySize, MMASMEM_BYTES);
    cudaFuncSetAttribute(gemm_mma<0,1,0>, cudaFuncAttributeMaxDynamicSharedMemorySize, MMASMEM_BYTES);
    cudaFuncSetAttribute(gemm_mma<1,0,0>, cudaFuncAttributeMaxDynamicSharedMemorySize, MMASMEM_BYTES);
    cudaFuncSetAttribute(gemm_mma<0,0,2>, cudaFuncAttributeMaxDynamicSharedMemorySize, MMASMEM_BYTES);
    cudaFuncSetAttribute(gemm_mma<0,1,1>, cudaFuncAttributeMaxDynamicSharedMemorySize, MMASMEM_BYTES);

    // 0) proj * data_normalizer (pad rows of g_projs stay zero)
    scale_proj_k<<<(NBF * DDIM + 255) / 256, 256>>>(proj, projs, NBF * DDIM);

    // 1) per-head projections: C[1024,256] = X[t] * W[h] + b[h]
    {
        dim3 grid(DDIM / 128, NPT / 128, BATCH);
        gemm_mma<0, 0, 1><<<grid, 256, MMASMEM_BYTES>>>(q, Wq, qall,
            NPT, DDIM, DDIM, DDIM, DDIM, DDIM,
            (long)NPT * DDIM, 0, 0, (long)DDIM * DDIM,
            (long)HH * NPT * DDIM, (long)NPT * DDIM, HH,
            bq, DDIM, nullptr, 0, 0, 1);
        gemm_mma<0, 0, 1><<<grid, 256, MMASMEM_BYTES>>>(k, Wk, kall,
            NPT, DDIM, DDIM, DDIM, DDIM, DDIM,
            (long)NPT * DDIM, 0, 0, (long)DDIM * DDIM,
            (long)HH * NPT * DDIM, (long)NPT * DDIM, HH,
            bk, DDIM, nullptr, 0, 0, 1);
        gemm_mma<0, 0, 1><<<grid, 256, MMASMEM_BYTES>>>(v, Wv, vall,
            NPT, DDIM, DDIM, DDIM, DDIM, DDIM,
            (long)NPT * DDIM, 0, 0, (long)DDIM * DDIM,
            (long)HH * NPT * DDIM, (long)NPT * DDIM, HH,
            bv, DDIM, nullptr, 0, 0, 1);
    }

    // 2) dash: C[1024,1440] = X_all[b] * projs^T
    {
        dim3 grid((NBP + 127) / 128, NPT / 128, BATCH);
        gemm_mma<0, 1, 0><<<grid, 256, MMASMEM_BYTES>>>(qall, projs, qp,
            NPT, NBP, DDIM, DDIM, DDIM, NBP,
            (long)NPT * DDIM, 0, 0, 0,
            (long)NPT * NBP, 0, 1,
            nullptr, 0, nullptr, 0, 0, 1);
        gemm_mma<0, 1, 0><<<grid, 256, MMASMEM_BYTES>>>(kall, projs, kp,
            NPT, NBP, DDIM, DDIM, DDIM, NBP,
            (long)NPT * DDIM, 0, 0, 0,
            (long)NPT * NBP, 0, 1,
            nullptr, 0, nullptr, 0, 0, 1);
    }

    // 3) feature maps (exp in place on cols < NBF; pad cols keep their 0)
    qexp_k<<<ROWS, 256>>>(qp, qall);
    kmax_k<<<BATCH, 1024>>>(kp, kmax);
    kexp_k<<<ROWS, 256>>>(kp, kall, kmax);
    ksum_k<<<dim3((NBF + 255) / 256, BATCH), 256>>>(kp, ksum);
    dinv_k<<<ROWS, 256>>>(qp, ksum, dinv);

    // 4) context: C[1440,256] = k_prime[b]^T * v_all[b]
    {
        dim3 grid(DDIM / 128, (NBP + 127) / 128, BATCH);
        gemm_mma<1, 0, 0><<<grid, 256, MMASMEM_BYTES>>>(kp, vall, ctx,
            NBP, DDIM, NPT, NBP, DDIM, DDIM,
            (long)NPT * NBP, 0, (long)NPT * DDIM, 0,
            (long)NBP * DDIM, 0, 1,
            nullptr, 0, nullptr, 0, 0, 1);
    }

    // 5) out: C[1024,256] = q_prime[b] * ctx[b] (K=1440; pads contribute 0),
    //    row-scaled by d_inv, stored permuted into outs[t, n, e*H + h]
    {
        dim3 grid(DDIM / 128, NPT / 128, BATCH);
        gemm_mma<0, 0, 2><<<grid, 256, MMASMEM_BYTES>>>(qp, ctx, outs,
            NPT, DDIM, NBP, NBP, DDIM, HDCAT,
            (long)HH * NPT * NBP, (long)NPT * NBP,
            (long)HH * NBP * DDIM, (long)NBP * DDIM,
            (long)NPT * HDCAT, 1, HH,
            nullptr, 0, dinv, (long)HH * NPT, (long)NPT, HH);
    }

    // 6) output projection: rep[8192,256] = outs[8192,2048] * W_out^T + b_out
    {
        dim3 grid(DDIM / 128, (TT * NPT) / 128, 1);
        gemm_mma<0, 1, 1><<<grid, 256, MMASMEM_BYTES>>>(outs, W_out, out,
            TT * NPT, DDIM, HDCAT, HDCAT, HDCAT, DDIM,
            0, 0, 0, 0, 0, 0, 1,
            b_out, 0, nullptr, 0, 0, 1);
    }
}

// round 6
// speedup vs baseline: 2.5526x; 1.5681x over previous
#include <cuda_runtime.h>
#include <cuda_bf16.h>
#include <cstdint>
#include <math.h>

// ---------------------------------------------------------------------------
// Problem constants (T=8, N=M=1024, H=8, D=256, NB = int(256*ln 256) = 1419)
// ---------------------------------------------------------------------------
#define TT   8
#define NPT  1024
#define HH   8
#define DDIM 256
#define NBF  1419
#define NBP  1440              // padded to multiple of 32
#define ROWS (TT * HH * NPT)   // 65536
#define BATCH (TT * HH)        // 64
#define HDCAT (HH * DDIM)      // 2048

#define DNORM   0.25f          // 256^-0.25
#define DNORM2  0.0625f
#define EPSF    1e-4f
#define RATIO   0.026547529f   // 1/sqrt(1419)

typedef __nv_bfloat16 bf16;

// ---------------------------------------------------------------------------
// Scratch (device globals; zero-init at load -> never-written pads stay 0)
// ---------------------------------------------------------------------------
// fp32 dash buffers
__device__ float g_qp[(size_t)ROWS * NBP];
__device__ float g_kp[(size_t)ROWS * NBP];
// bf16 hi/lo operand buffers
__device__ bf16 g_qin_h[(size_t)TT * NPT * DDIM],  g_qin_l[(size_t)TT * NPT * DDIM];
__device__ bf16 g_kin_h[(size_t)TT * NPT * DDIM],  g_kin_l[(size_t)TT * NPT * DDIM];
__device__ bf16 g_vin_h[(size_t)TT * NPT * DDIM],  g_vin_l[(size_t)TT * NPT * DDIM];
__device__ bf16 g_wtq_h[(size_t)HH * DDIM * DDIM], g_wtq_l[(size_t)HH * DDIM * DDIM];
__device__ bf16 g_wtk_h[(size_t)HH * DDIM * DDIM], g_wtk_l[(size_t)HH * DDIM * DDIM];
__device__ bf16 g_wtv_h[(size_t)HH * DDIM * DDIM], g_wtv_l[(size_t)HH * DDIM * DDIM];
__device__ bf16 g_pr_h[(size_t)NBP * DDIM],        g_pr_l[(size_t)NBP * DDIM];
__device__ bf16 g_wo_h[(size_t)DDIM * HDCAT],      g_wo_l[(size_t)DDIM * HDCAT];
__device__ bf16 g_qall_h[(size_t)ROWS * DDIM],     g_qall_l[(size_t)ROWS * DDIM];
__device__ bf16 g_kall_h[(size_t)ROWS * DDIM],     g_kall_l[(size_t)ROWS * DDIM];
__device__ bf16 g_vall_h[(size_t)ROWS * DDIM],     g_vall_l[(size_t)ROWS * DDIM];
__device__ bf16 g_vt_h[(size_t)ROWS * DDIM],       g_vt_l[(size_t)ROWS * DDIM];
__device__ bf16 g_qph[(size_t)ROWS * NBP],         g_qpl[(size_t)ROWS * NBP];
__device__ bf16 g_kpT_h[(size_t)BATCH * NBP * NPT], g_kpT_l[(size_t)BATCH * NBP * NPT];
__device__ bf16 g_ctxT_h[(size_t)BATCH * DDIM * NBP], g_ctxT_l[(size_t)BATCH * DDIM * NBP];
__device__ bf16 g_outs_h[(size_t)TT * NPT * HDCAT], g_outs_l[(size_t)TT * NPT * HDCAT];
// reduction scratch
__device__ float g_diagk[(size_t)ROWS];
__device__ float g_ksum[(size_t)BATCH * NBP];
__device__ float g_kpart[(size_t)BATCH * 32 * NBP];
__device__ float g_dinv[(size_t)ROWS];
__device__ float g_kmax[(size_t)BATCH];
__device__ float g_kmaxp[(size_t)BATCH * 8];

// ---------------------------------------------------------------------------
// helpers
// ---------------------------------------------------------------------------
__device__ __forceinline__ uint32_t smem_u32(const void* p) {
    uint32_t a;
    asm("{ .reg .u64 t; cvta.to.shared.u64 t, %1; cvt.u32.u64 %0, t; }"
        : "=r"(a) : "l"(p));
    return a;
}

__device__ __forceinline__ void ldm4(uint32_t& r0, uint32_t& r1,
                                     uint32_t& r2, uint32_t& r3, uint32_t a) {
    asm volatile("ldmatrix.sync.aligned.m8n8.x4.shared.b16 {%0,%1,%2,%3}, [%4];"
                 : "=r"(r0), "=r"(r1), "=r"(r2), "=r"(r3) : "r"(a));
}

__device__ __forceinline__ void mma16816(float* c, uint32_t a0, uint32_t a1,
                                         uint32_t a2, uint32_t a3,
                                         uint32_t b0, uint32_t b1) {
    asm volatile(
        "mma.sync.aligned.m16n8k16.row.col.f32.bf16.bf16.f32 "
        "{%0,%1,%2,%3},{%4,%5,%6,%7},{%8,%9},{%0,%1,%2,%3};"
        : "+f"(c[0]), "+f"(c[1]), "+f"(c[2]), "+f"(c[3])
        : "r"(a0), "r"(a1), "r"(a2), "r"(a3), "r"(b0), "r"(b1));
}

__device__ __forceinline__ void cpasync16(uint32_t dst, const bf16* src, int sz) {
    asm volatile("cp.async.cg.shared.global [%0], [%1], 16, %2;"
                 :: "r"(dst), "l"(__cvta_generic_to_global(src)), "r"(sz));
}

__device__ __forceinline__ void splitw(float x, bf16& h, bf16& l) {
    h = __float2bfloat16_rn(x);
    l = __float2bfloat16_rn(x - __bfloat162float(h));
}

// ---------------------------------------------------------------------------
// gemm5: NT bf16x3 mma.sync GEMM with cp.async 3-stage ring + ldmatrix.
//   C[M,N] = A[M,K] * B[N,K]^T ; A/B given as hi/lo bf16, k-contiguous.
//   EPI: 0 plain f32, 1 +bias f32, 2 *scale[row] + colMul store, bf16 pair,
//        3 +bias bf16 pair, 4 plain bf16 pair
//   K % 32 == 0, lda == ldb == K. 128x128 tile, 256 threads.
// ---------------------------------------------------------------------------
#define TSTRIDE 40
#define TILE_E  (128 * TSTRIDE)       // 5120 bf16
#define STAGE_E (4 * TILE_E)          // 20480 bf16 (Ah, Al, Bh, Bl)
#define G5SMEM  (3 * STAGE_E * 2)     // 122880 bytes

template<int EPI>
__global__ void __launch_bounds__(256)
gemm5(const bf16* __restrict__ Ahi, const bf16* __restrict__ Alo,
      const bf16* __restrict__ Bhi, const bf16* __restrict__ Blo,
      float* __restrict__ Cf, bf16* __restrict__ Chi, bf16* __restrict__ Clo,
      int M, int N, int K, int lda, int ldb, int ldc,
      long aT, long aH, long bT, long bH, long cT, long cH, int Hdiv,
      const float* __restrict__ bias, long biasH,
      const float* __restrict__ scale, long scT, long scH, int colMul)
{
    extern __shared__ bf16 smb[];
    const uint32_t sb = smem_u32(smb);
    const int tid = threadIdx.x;
    const int wid = tid >> 5, lane = tid & 31;
    const int warp_m = wid >> 2, warp_n = wid & 3;
    const int g = lane >> 2, tg = lane & 3;

    const int bz = blockIdx.z;
    const int t = bz / Hdiv, h = bz % Hdiv;
    const long aoff = (long)t * aT + (long)h * aH;
    const long boff = (long)t * bT + (long)h * bH;
    const long coff = (long)t * cT + (long)h * cH;
    const float* biasp  = (EPI == 1 || EPI == 3) ? bias + (long)h * biasH : nullptr;
    const float* scalep = (EPI == 2) ? scale + (long)t * scT + (long)h * scH : nullptr;

    const int m0 = blockIdx.y * 128;
    const int n0 = blockIdx.x * 128;

    const bf16* srcs[4] = {Ahi + aoff, Alo + aoff, Bhi + boff, Blo + boff};

    const int S = K >> 5;

    auto stage = [&](int s, int bi) {
#pragma unroll
        for (int T = 0; T < 4; T++) {
            const int rows  = (T < 2) ? M : N;
            const int rbase = (T < 2) ? m0 : n0;
            const int ld    = (T < 2) ? lda : ldb;
            const bf16* src = srcs[T];
            const int k0 = s << 5;
#pragma unroll
            for (int c = 0; c < 2; c++) {
                const int ch = tid + c * 256;          // 0..511
                const int r = ch >> 2, q = ch & 3;
                const int gr = rbase + r;
                const int sz = (gr < rows) ? 16 : 0;
                const bf16* sp = src + (long)(sz ? gr : rbase) * ld + k0 + q * 8;
                const uint32_t dst = sb + (uint32_t)(bi * STAGE_E + T * TILE_E
                                                     + r * TSTRIDE + q * 8) * 2;
                cpasync16(dst, sp, sz);
            }
        }
        asm volatile("cp.async.commit_group;" ::: "memory");
    };

    float acc[4][4][4];
#pragma unroll
    for (int i = 0; i < 4; i++)
#pragma unroll
        for (int j = 0; j < 4; j++)
#pragma unroll
            for (int e = 0; e < 4; e++) acc[i][j][e] = 0.f;

    stage(0, 0);
    stage(1, 1);

    for (int s = 0; s < S; s++) {
        const int bi = s % 3;
        if (s + 1 < S) asm volatile("cp.async.wait_group 1;" ::: "memory");
        else           asm volatile("cp.async.wait_group 0;" ::: "memory");
        __syncthreads();

        const uint32_t base = sb + (uint32_t)(bi * STAGE_E) * 2;
#pragma unroll
        for (int ks = 0; ks < 2; ks++) {
            const int ko = ks << 4;
            uint32_t bh[4][2], bl[4][2];
#pragma unroll
            for (int p = 0; p < 2; p++) {
                const int nrow = warp_n * 32 + p * 16 + ((lane >> 4) << 3) + (lane & 7);
                const int kcol = ko + ((lane >> 3) & 1) * 8;
                const uint32_t ab = base + (uint32_t)(2 * TILE_E + nrow * TSTRIDE + kcol) * 2;
                ldm4(bh[2 * p][0], bh[2 * p][1], bh[2 * p + 1][0], bh[2 * p + 1][1], ab);
                ldm4(bl[2 * p][0], bl[2 * p][1], bl[2 * p + 1][0], bl[2 * p + 1][1],
                     ab + (uint32_t)TILE_E * 2);
            }
#pragma unroll
            for (int ma = 0; ma < 4; ma++) {
                const int mrow = warp_m * 64 + ma * 16 + ((lane >> 3) & 1) * 8 + (lane & 7);
                const int kcol = ko + (lane >> 4) * 8;
                const uint32_t aa = base + (uint32_t)(mrow * TSTRIDE + kcol) * 2;
                uint32_t ah0, ah1, ah2, ah3, al0, al1, al2, al3;
                ldm4(ah0, ah1, ah2, ah3, aa);
                ldm4(al0, al1, al2, al3, aa + (uint32_t)TILE_E * 2);
#pragma unroll
                for (int nb = 0; nb < 4; nb++) {
                    mma16816(acc[ma][nb], ah0, ah1, ah2, ah3, bh[nb][0], bh[nb][1]);
                    mma16816(acc[ma][nb], ah0, ah1, ah2, ah3, bl[nb][0], bl[nb][1]);
                    mma16816(acc[ma][nb], al0, al1, al2, al3, bh[nb][0], bh[nb][1]);
                }
            }
        }
        if (s + 2 < S) stage(s + 2, (s + 2) % 3);
    }

    // ---- epilogue
#pragma unroll
    for (int ma = 0; ma < 4; ma++) {
        const int rbase = m0 + warp_m * 64 + ma * 16 + g;
#pragma unroll
        for (int hf = 0; hf < 2; hf++) {
            const int row = rbase + hf * 8;
            if (row >= M) continue;
            const float sc = (EPI == 2) ? scalep[row] : 1.f;
#pragma unroll
            for (int nb = 0; nb < 4; nb++) {
                const int col = n0 + warp_n * 32 + nb * 8 + 2 * tg;
#pragma unroll
                for (int e = 0; e < 2; e++) {
                    if (col + e >= N) continue;
                    float v = acc[ma][nb][hf * 2 + e];
                    if (EPI == 1 || EPI == 3) v += biasp[col + e];
                    if (EPI == 2) v *= sc;
                    long idx = coff + (long)row * ldc
                             + (EPI == 2 ? (long)(col + e) * colMul : (long)(col + e));
                    if (EPI == 0 || EPI == 1) {
                        Cf[idx] = v;
                    } else {
                        bf16 hb, lb; splitw(v, hb, lb);
                        Chi[idx] = hb; Clo[idx] = lb;
                    }
                }
            }
        }
    }
}

// ---------------------------------------------------------------------------
// conversion / transpose passes
// ---------------------------------------------------------------------------
__global__ void split_k(const float* __restrict__ s, bf16* __restrict__ h,
                        bf16* __restrict__ l, size_t n, float scl)
{
    size_t i = (size_t)blockIdx.x * blockDim.x + threadIdx.x;
    if (i < n) {
        float x = s[i] * scl;
        bf16 hb, lb; splitw(x, hb, lb);
        h[i] = hb; l[i] = lb;
    }
}

// fp32 [z][R][C] -> bf16 hi/lo [z][C][R]
__global__ void tsplit_k(const float* __restrict__ src, bf16* __restrict__ hi,
                         bf16* __restrict__ lo, int R, int C)
{
    __shared__ float sm[32][33];
    const int z = blockIdx.z;
    const int c0 = blockIdx.x * 32, r0 = blockIdx.y * 32;
    const float* s = src + (size_t)z * R * C;
    bf16* ho = hi + (size_t)z * R * C;
    bf16* lv = lo + (size_t)z * R * C;
    const int tx = threadIdx.x, ty = threadIdx.y;
    for (int i = ty; i < 32; i += 8)
        sm[i][tx] = s[(size_t)(r0 + i) * C + c0 + tx];
    __syncthreads();
    for (int i = ty; i < 32; i += 8) {
        float x = sm[tx][i];
        bf16 hb, lb; splitw(x, hb, lb);
        ho[(size_t)(c0 + i) * R + r0 + tx] = hb;
        lv[(size_t)(c0 + i) * R + r0 + tx] = lb;
    }
}

// bf16 [z][R][C] -> bf16 [z][C][R]
__global__ void tbf_k(const bf16* __restrict__ src, bf16* __restrict__ dst,
                      int R, int C)
{
    __shared__ bf16 sm[32][33];
    const int z = blockIdx.z;
    const int c0 = blockIdx.x * 32, r0 = blockIdx.y * 32;
    const bf16* s = src + (size_t)z * R * C;
    bf16* d = dst + (size_t)z * R * C;
    const int tx = threadIdx.x, ty = threadIdx.y;
    for (int i = ty; i < 32; i += 8)
        sm[i][tx] = s[(size_t)(r0 + i) * C + c0 + tx];
    __syncthreads();
    for (int i = ty; i < 32; i += 8)
        d[(size_t)(c0 + i) * R + r0 + tx] = sm[tx][i];
}

// ---------------------------------------------------------------------------
// feature-map / reduction kernels
// ---------------------------------------------------------------------------
__global__ void __launch_bounds__(256)
qexp_k(const float* __restrict__ qp, const bf16* __restrict__ qh,
       const bf16* __restrict__ ql, bf16* __restrict__ oh, bf16* __restrict__ ol)
{
    const size_t r = blockIdx.x;
    const float* prow = qp + r * NBP;
    const int tid = threadIdx.x;
    __shared__ float red[256];

    float x = __bfloat162float(qh[r * DDIM + tid]) + __bfloat162float(ql[r * DDIM + tid]);
    red[tid] = x * x;
    __syncthreads();
    for (int s = 128; s > 0; s >>= 1) {
        if (tid < s) red[tid] += red[tid + s];
        __syncthreads();
    }
    const float diag = 0.5f * DNORM2 * red[0];
    __syncthreads();

    float mx = -3.4e38f;
    for (int j = tid; j < NBF; j += 256) mx = fmaxf(mx, prow[j]);
    red[tid] = mx;
    __syncthreads();
    for (int s = 128; s > 0; s >>= 1) {
        if (tid < s) red[tid] = fmaxf(red[tid], red[tid + s]);
        __syncthreads();
    }
    const float c = diag + red[0];

    for (int j = tid; j < NBP; j += 256) {
        float v = (j < NBF) ? RATIO * (expf(prow[j] - c) + EPSF) : 0.f;
        bf16 hb, lb; splitw(v, hb, lb);
        oh[r * NBP + j] = hb; ol[r * NBP + j] = lb;
    }
}

__global__ void __launch_bounds__(256)
kdiag_k(const bf16* __restrict__ kh, const bf16* __restrict__ kl,
        float* __restrict__ diag)
{
    const size_t r = blockIdx.x;
    const int tid = threadIdx.x;
    __shared__ float red[256];
    float x = __bfloat162float(kh[r * DDIM + tid]) + __bfloat162float(kl[r * DDIM + tid]);
    red[tid] = x * x;
    __syncthreads();
    for (int s = 128; s > 0; s >>= 1) {
        if (tid < s) red[tid] += red[tid + s];
        __syncthreads();
    }
    if (tid == 0) diag[r] = 0.5f * DNORM2 * red[0];
}

__global__ void __launch_bounds__(1024)
kmax1_k(const float* __restrict__ kp, float* __restrict__ part)
{
    const int b = blockIdx.y, ch = blockIdx.x;
    const float* base = kp + (size_t)b * NPT * NBP + (size_t)ch * 128 * NBP;
    float mx = -3.4e38f;
    for (int r = 0; r < 128; r++) {
        const float* row = base + (size_t)r * NBP;
        for (int j = threadIdx.x; j < NBF; j += 1024)
            mx = fmaxf(mx, row[j]);
    }
    __shared__ float red[1024];
    red[threadIdx.x] = mx;
    __syncthreads();
    for (int s = 512; s > 0; s >>= 1) {
        if (threadIdx.x < s)
            red[threadIdx.x] = fmaxf(red[threadIdx.x], red[threadIdx.x + s]);
        __syncthreads();
    }
    if (threadIdx.x == 0) part[b * 8 + ch] = red[0];
}

__global__ void kmax2_k(const float* __restrict__ part, float* __restrict__ kmax)
{
    const int b = threadIdx.x;
    if (b < BATCH) {
        float mx = part[b * 8];
        for (int j = 1; j < 8; j++) mx = fmaxf(mx, part[b * 8 + j]);
        kmax[b] = mx;
    }
}

// transpose + exp for K: g_kp[b][n][m] fp32 -> kpT hi/lo [b][m][n] + ksum partials
__global__ void __launch_bounds__(256)
ktexp_k(const float* __restrict__ kp, const float* __restrict__ diag,
        const float* __restrict__ kmax, bf16* __restrict__ th,
        bf16* __restrict__ tl, float* __restrict__ part)
{
    __shared__ float sm[32][33];
    const int b = blockIdx.z;
    const int m0 = blockIdx.x * 32, n0 = blockIdx.y * 32;
    const int tx = threadIdx.x, ty = threadIdx.y;
    const float km = kmax[b];

    for (int i = ty; i < 32; i += 8) {
        const int n = n0 + i, m = m0 + tx;
        const float dk = diag[(size_t)b * NPT + n];
        const float v = kp[((size_t)b * NPT + n) * NBP + m];
        sm[i][tx] = (m < NBF) ? RATIO * (expf(v - dk - km) + EPSF) : 0.f;
    }
    __syncthreads();

    for (int i = ty; i < 32; i += 8) {
        const int m = m0 + i;
        const float v = sm[tx][i];
        bf16 hb, lb; splitw(v, hb, lb);
        const size_t idx = ((size_t)b * NBP + m) * NPT + n0 + tx;
        th[idx] = hb; tl[idx] = lb;
        // warp sum over n (lanes = tx)
        float s = v;
        for (int o = 16; o > 0; o >>= 1) s += __shfl_down_sync(0xffffffffu, s, o);
        if (tx == 0)
            part[((size_t)b * 32 + blockIdx.y) * NBP + m] = s;
    }
}

__global__ void ksum2_k(const float* __restrict__ part, float* __restrict__ ksum)
{
    const int b = blockIdx.y;
    const int m = blockIdx.x * blockDim.x + threadIdx.x;
    if (m >= NBP) return;
    float s = 0.f;
    for (int j = 0; j < 32; j++)
        s += part[((size_t)b * 32 + j) * NBP + m];
    ksum[(size_t)b * NBP + m] = s;
}

__global__ void __launch_bounds__(256)
dinv_k(const bf16* __restrict__ qh, const bf16* __restrict__ ql,
       const float* __restrict__ ksum, float* __restrict__ dinv)
{
    const size_t r = blockIdx.x;
    const int b = (int)(r >> 10);
    const int tid = threadIdx.x;
    float s = 0.f;
    for (int j = tid; j < NBF; j += 256) {
        float q = __bfloat162float(qh[r * NBP + j]) + __bfloat162float(ql[r * NBP + j]);
        s += q * ksum[(size_t)b * NBP + j];
    }
    __shared__ float red[256];
    red[tid] = s;
    __syncthreads();
    for (int st = 128; st > 0; st >>= 1) {
        if (tid < st) red[tid] += red[tid + st];
        __syncthreads();
    }
    if (tid == 0) dinv[r] = 1.0f / red[0];
}

// ---------------------------------------------------------------------------
// Launch
// ---------------------------------------------------------------------------
#define GETP(var, sym) cudaGetSymbolAddress((void**)&var, sym)

extern "C" void kernel_launch(void* const* d_in, const int* in_sizes, int n_in,
                              void* d_out, int out_size)
{
    const float* q     = (const float*)d_in[0];
    const float* k     = (const float*)d_in[1];
    const float* v     = (const float*)d_in[2];
    const float* Wq    = (const float*)d_in[3];
    const float* bq    = (const float*)d_in[4];
    const float* Wk    = (const float*)d_in[5];
    const float* bk    = (const float*)d_in[6];
    const float* Wv    = (const float*)d_in[7];
    const float* bv    = (const float*)d_in[8];
    const float* W_out = (const float*)d_in[9];
    const float* b_out = (const float*)d_in[10];
    const float* proj  = (const float*)d_in[11];
    float* out = (float*)d_out;

    float *qp, *kp, *diagk, *ksum, *kpart, *dinv, *kmax, *kmaxp;
    bf16 *qin_h, *qin_l, *kin_h, *kin_l, *vin_h, *vin_l;
    bf16 *wtq_h, *wtq_l, *wtk_h, *wtk_l, *wtv_h, *wtv_l;
    bf16 *pr_h, *pr_l, *wo_h, *wo_l;
    bf16 *qall_h, *qall_l, *kall_h, *kall_l, *vall_h, *vall_l, *vt_h, *vt_l;
    bf16 *qph, *qpl, *kpT_h, *kpT_l, *ctxT_h, *ctxT_l, *outs_h, *outs_l;

    GETP(qp, g_qp); GETP(kp, g_kp);
    GETP(qin_h, g_qin_h); GETP(qin_l, g_qin_l);
    GETP(kin_h, g_kin_h); GETP(kin_l, g_kin_l);
    GETP(vin_h, g_vin_h); GETP(vin_l, g_vin_l);
    GETP(wtq_h, g_wtq_h); GETP(wtq_l, g_wtq_l);
    GETP(wtk_h, g_wtk_h); GETP(wtk_l, g_wtk_l);
    GETP(wtv_h, g_wtv_h); GETP(wtv_l, g_wtv_l);
    GETP(pr_h, g_pr_h);   GETP(pr_l, g_pr_l);
    GETP(wo_h, g_wo_h);   GETP(wo_l, g_wo_l);
    GETP(qall_h, g_qall_h); GETP(qall_l, g_qall_l);
    GETP(kall_h, g_kall_h); GETP(kall_l, g_kall_l);
    GETP(vall_h, g_vall_h); GETP(vall_l, g_vall_l);
    GETP(vt_h, g_vt_h);     GETP(vt_l, g_vt_l);
    GETP(qph, g_qph);       GETP(qpl, g_qpl);
    GETP(kpT_h, g_kpT_h);   GETP(kpT_l, g_kpT_l);
    GETP(ctxT_h, g_ctxT_h); GETP(ctxT_l, g_ctxT_l);
    GETP(outs_h, g_outs_h); GETP(outs_l, g_outs_l);
    GETP(diagk, g_diagk); GETP(ksum, g_ksum); GETP(kpart, g_kpart);
    GETP(dinv, g_dinv); GETP(kmax, g_kmax); GETP(kmaxp, g_kmaxp);

    cudaFuncSetAttribute(gemm5<0>, cudaFuncAttributeMaxDynamicSharedMemorySize, G5SMEM);
    cudaFuncSetAttribute(gemm5<1>, cudaFuncAttributeMaxDynamicSharedMemorySize, G5SMEM);
    cudaFuncSetAttribute(gemm5<2>, cudaFuncAttributeMaxDynamicSharedMemorySize, G5SMEM);
    cudaFuncSetAttribute(gemm5<3>, cudaFuncAttributeMaxDynamicSharedMemorySize, G5SMEM);
    cudaFuncSetAttribute(gemm5<4>, cudaFuncAttributeMaxDynamicSharedMemorySize, G5SMEM);

    // ---- 0) splits of inputs / weights
    {
        const size_t nin = (size_t)TT * NPT * DDIM;
        split_k<<<(unsigned)((nin + 255) / 256), 256>>>(q, qin_h, qin_l, nin, 1.f);
        split_k<<<(unsigned)((nin + 255) / 256), 256>>>(k, kin_h, kin_l, nin, 1.f);
        split_k<<<(unsigned)((nin + 255) / 256), 256>>>(v, vin_h, vin_l, nin, 1.f);
        dim3 tg(8, 8, 8), tb(32, 8);
        tsplit_k<<<tg, tb>>>(Wq, wtq_h, wtq_l, DDIM, DDIM);
        tsplit_k<<<tg, tb>>>(Wk, wtk_h, wtk_l, DDIM, DDIM);
        tsplit_k<<<tg, tb>>>(Wv, wtv_h, wtv_l, DDIM, DDIM);
        const size_t npr = (size_t)NBF * DDIM;
        split_k<<<(unsigned)((npr + 255) / 256), 256>>>(proj, pr_h, pr_l, npr, DNORM);
        const size_t nwo = (size_t)DDIM * HDCAT;
        split_k<<<(unsigned)((nwo + 255) / 256), 256>>>(W_out, wo_h, wo_l, nwo, 1.f);
    }

    // ---- 1) per-head projections: C[t,h][1024,256] = X[t] * Wt[h]^T + b[h]
    {
        dim3 grid(2, 8, BATCH);
        gemm5<3><<<grid, 256, G5SMEM>>>(qin_h, qin_l, wtq_h, wtq_l,
            nullptr, qall_h, qall_l,
            NPT, DDIM, DDIM, DDIM, DDIM, DDIM,
            (long)NPT * DDIM, 0, 0, (long)DDIM * DDIM,
            (long)HH * NPT * DDIM, (long)NPT * DDIM, HH,
            bq, DDIM, nullptr, 0, 0, 1);
        gemm5<3><<<grid, 256, G5SMEM>>>(kin_h, kin_l, wtk_h, wtk_l,
            nullptr, kall_h, kall_l,
            NPT, DDIM, DDIM, DDIM, DDIM, DDIM,
            (long)NPT * DDIM, 0, 0, (long)DDIM * DDIM,
            (long)HH * NPT * DDIM, (long)NPT * DDIM, HH,
            bk, DDIM, nullptr, 0, 0, 1);
        gemm5<3><<<grid, 256, G5SMEM>>>(vin_h, vin_l, wtv_h, wtv_l,
            nullptr, vall_h, vall_l,
            NPT, DDIM, DDIM, DDIM, DDIM, DDIM,
            (long)NPT * DDIM, 0, 0, (long)DDIM * DDIM,
            (long)HH * NPT * DDIM, (long)NPT * DDIM, HH,
            bv, DDIM, nullptr, 0, 0, 1);
    }

    // ---- 2) dash: fp32 [z][1024][1440] = X_all[z] * projs^T
    {
        dim3 grid(12, 8, BATCH);
        gemm5<0><<<grid, 256, G5SMEM>>>(qall_h, qall_l, pr_h, pr_l,
            qp, nullptr, nullptr,
            NPT, NBP, DDIM, DDIM, DDIM, NBP,
            (long)NPT * DDIM, 0, 0, 0, (long)NPT * NBP, 0, 1,
            nullptr, 0, nullptr, 0, 0, 1);
        gemm5<0><<<grid, 256, G5SMEM>>>(kall_h, kall_l, pr_h, pr_l,
            kp, nullptr, nullptr,
            NPT, NBP, DDIM, DDIM, DDIM, NBP,
            (long)NPT * DDIM, 0, 0, 0, (long)NPT * NBP, 0, 1,
            nullptr, 0, nullptr, 0, 0, 1);
    }

    // ---- 3) feature maps
    qexp_k<<<ROWS, 256>>>(qp, qall_h, qall_l, qph, qpl);
    kdiag_k<<<ROWS, 256>>>(kall_h, kall_l, diagk);
    kmax1_k<<<dim3(8, BATCH), 1024>>>(kp, kmaxp);
    kmax2_k<<<1, 64>>>(kmaxp, kmax);
    ktexp_k<<<dim3(45, 32, BATCH), dim3(32, 8)>>>(kp, diagk, kmax, kpT_h, kpT_l, kpart);
    ksum2_k<<<dim3(6, BATCH), 256>>>(kpart, ksum);
    dinv_k<<<ROWS, 256>>>(qph, qpl, ksum, dinv);

    // ---- 4) vallT: [b][n][e] -> [b][e][n]
    {
        dim3 tg(8, 32, BATCH), tb(32, 8);
        tbf_k<<<tg, tb>>>(vall_h, vt_h, NPT, DDIM);
        tbf_k<<<tg, tb>>>(vall_l, vt_l, NPT, DDIM);
    }

    // ---- 5) ctxT[b][e][m] = vallT[b] * kpT[b]^T   (M=256, N=1440, K=1024)
    {
        dim3 grid(12, 2, BATCH);
        gemm5<4><<<grid, 256, G5SMEM>>>(vt_h, vt_l, kpT_h, kpT_l,
            nullptr, ctxT_h, ctxT_l,
            DDIM, NBP, NPT, NPT, NPT, NBP,
            (long)DDIM * NPT, 0, (long)NBP * NPT, 0, (long)DDIM * NBP, 0, 1,
            nullptr, 0, nullptr, 0, 0, 1);
    }

    // ---- 6) out[t,h][n][e] = qp * ctxT^T, *dinv, permuted bf16 store
    {
        dim3 grid(2, 8, BATCH);
        gemm5<2><<<grid, 256, G5SMEM>>>(qph, qpl, ctxT_h, ctxT_l,
            nullptr, outs_h, outs_l,
            NPT, DDIM, NBP, NBP, NBP, HDCAT,
            (long)HH * NPT * NBP, (long)NPT * NBP,
            (long)HH * DDIM * NBP, (long)DDIM * NBP,
            (long)NPT * HDCAT, 1, HH,
            nullptr, 0, dinv, (long)HH * NPT, (long)NPT, HH);
    }

    // ---- 7) final: rep[8192][256] = outs * W_out^T + b_out
    {
        dim3 grid(2, 64, 1);
        gemm5<1><<<grid, 256, G5SMEM>>>(outs_h, outs_l, wo_h, wo_l,
            out, nullptr, nullptr,
            TT * NPT, DDIM, HDCAT, HDCAT, HDCAT, DDIM,
            0, 0, 0, 0, 0, 0, 1,
            b_out, 0, nullptr, 0, 0, 1);
    }
}

// round 7
// speedup vs baseline: 2.7653x; 1.0833x over previous
#include <cuda_runtime.h>
#include <cuda_bf16.h>
#include <cstdint>
#include <math.h>

// ---------------------------------------------------------------------------
// Problem constants (T=8, N=M=1024, H=8, D=256, NB = int(256*ln 256) = 1419)
// ---------------------------------------------------------------------------
#define TT   8
#define NPT  1024
#define HH   8
#define DDIM 256
#define NBF  1419
#define NBP  1440              // padded to multiple of 32
#define ROWS (TT * HH * NPT)   // 65536
#define BATCH (TT * HH)        // 64
#define HDCAT (HH * DDIM)      // 2048

#define DNORM   0.25f          // 256^-0.25
#define DNORM2  0.0625f
#define EPSF    1e-4f
#define RATIO   0.026547529f   // 1/sqrt(1419)

typedef __nv_bfloat16 bf16;

// ---------------------------------------------------------------------------
// Scratch (device globals; zero-init at load -> never-written pads stay 0)
// ---------------------------------------------------------------------------
__device__ float g_qp[(size_t)ROWS * NBP];
__device__ float g_kp[(size_t)ROWS * NBP];
__device__ bf16 g_qin_h[(size_t)TT * NPT * DDIM],  g_qin_l[(size_t)TT * NPT * DDIM];
__device__ bf16 g_kin_h[(size_t)TT * NPT * DDIM],  g_kin_l[(size_t)TT * NPT * DDIM];
__device__ bf16 g_vin_h[(size_t)TT * NPT * DDIM],  g_vin_l[(size_t)TT * NPT * DDIM];
__device__ bf16 g_wtq_h[(size_t)HH * DDIM * DDIM], g_wtq_l[(size_t)HH * DDIM * DDIM];
__device__ bf16 g_wtk_h[(size_t)HH * DDIM * DDIM], g_wtk_l[(size_t)HH * DDIM * DDIM];
__device__ bf16 g_wtv_h[(size_t)HH * DDIM * DDIM], g_wtv_l[(size_t)HH * DDIM * DDIM];
__device__ bf16 g_pr_h[(size_t)NBP * DDIM],        g_pr_l[(size_t)NBP * DDIM];
__device__ bf16 g_wo_h[(size_t)DDIM * HDCAT],      g_wo_l[(size_t)DDIM * HDCAT];
__device__ bf16 g_qall_h[(size_t)ROWS * DDIM],     g_qall_l[(size_t)ROWS * DDIM];
__device__ bf16 g_kall_h[(size_t)ROWS * DDIM],     g_kall_l[(size_t)ROWS * DDIM];
__device__ bf16 g_vall_h[(size_t)ROWS * DDIM],     g_vall_l[(size_t)ROWS * DDIM];
__device__ bf16 g_vt_h[(size_t)ROWS * DDIM],       g_vt_l[(size_t)ROWS * DDIM];
__device__ bf16 g_qph[(size_t)ROWS * NBP],         g_qpl[(size_t)ROWS * NBP];
__device__ bf16 g_kpT_h[(size_t)BATCH * NBP * NPT], g_kpT_l[(size_t)BATCH * NBP * NPT];
__device__ bf16 g_ctxT_h[(size_t)BATCH * DDIM * NBP], g_ctxT_l[(size_t)BATCH * DDIM * NBP];
__device__ bf16 g_outs_h[(size_t)TT * NPT * HDCAT], g_outs_l[(size_t)TT * NPT * HDCAT];
__device__ float g_diagk[(size_t)ROWS];
__device__ float g_ksum[(size_t)BATCH * NBP];
__device__ float g_kpart[(size_t)BATCH * 32 * NBP];
__device__ float g_dinv[(size_t)ROWS];
__device__ unsigned g_kmaxu[(size_t)BATCH];
__device__ unsigned g_rowmaxu[(size_t)ROWS];

// ---------------------------------------------------------------------------
// helpers
// ---------------------------------------------------------------------------
__device__ __forceinline__ uint32_t smem_u32(const void* p) {
    uint32_t a;
    asm("{ .reg .u64 t; cvta.to.shared.u64 t, %1; cvt.u32.u64 %0, t; }"
        : "=r"(a) : "l"(p));
    return a;
}

__device__ __forceinline__ void ldm4(uint32_t& r0, uint32_t& r1,
                                     uint32_t& r2, uint32_t& r3, uint32_t a) {
    asm volatile("ldmatrix.sync.aligned.m8n8.x4.shared.b16 {%0,%1,%2,%3}, [%4];"
                 : "=r"(r0), "=r"(r1), "=r"(r2), "=r"(r3) : "r"(a));
}

__device__ __forceinline__ void mma16816(float* c, uint32_t a0, uint32_t a1,
                                         uint32_t a2, uint32_t a3,
                                         uint32_t b0, uint32_t b1) {
    asm volatile(
        "mma.sync.aligned.m16n8k16.row.col.f32.bf16.bf16.f32 "
        "{%0,%1,%2,%3},{%4,%5,%6,%7},{%8,%9},{%0,%1,%2,%3};"
        : "+f"(c[0]), "+f"(c[1]), "+f"(c[2]), "+f"(c[3])
        : "r"(a0), "r"(a1), "r"(a2), "r"(a3), "r"(b0), "r"(b1));
}

__device__ __forceinline__ void cpasync16(uint32_t dst, const bf16* src, int sz) {
    asm volatile("cp.async.cg.shared.global [%0], [%1], 16, %2;"
                 :: "r"(dst), "l"(__cvta_generic_to_global(src)), "r"(sz));
}

__device__ __forceinline__ void splitw(float x, bf16& h, bf16& l) {
    h = __float2bfloat16_rn(x);
    l = __float2bfloat16_rn(x - __bfloat162float(h));
}

// monotonic float <-> unsigned encoding (total order; exact; order-independent max)
__device__ __forceinline__ unsigned encf(float f) {
    unsigned u = __float_as_uint(f);
    return (u & 0x80000000u) ? ~u : (u | 0x80000000u);
}
__device__ __forceinline__ float decf(unsigned u) {
    unsigned b = (u & 0x80000000u) ? (u ^ 0x80000000u) : ~u;
    return __uint_as_float(b);
}

// ---------------------------------------------------------------------------
// gemm6: NT bf16x3 mma.sync GEMM, 512 threads, 16 warps (4x4), 32x32/warp.
//   C[M,N] = A[M,K] * B[N,K]^T ; operands hi/lo bf16, k-contiguous.
//   EPI: 1 +bias f32 | 2 *scale[row], colMul store, bf16 pair
//        3 +bias bf16 pair | 4 plain bf16 pair
//        5 f32 + slab-max atomic (maxu[bz], cols < vlim)
//        6 f32 + row-max atomic (maxu[bz*M+row], cols < vlim)
//   K % 32 == 0, lda == ldb == K.
// ---------------------------------------------------------------------------
#define TSTRIDE 40
#define TILE_E  (128 * TSTRIDE)       // 5120 bf16
#define STAGE_E (4 * TILE_E)          // 20480 bf16
#define G6SMEM  (3 * STAGE_E * 2)     // 122880 bytes

template<int EPI>
__global__ void __launch_bounds__(512)
gemm6(const bf16* __restrict__ Ahi, const bf16* __restrict__ Alo,
      const bf16* __restrict__ Bhi, const bf16* __restrict__ Blo,
      float* __restrict__ Cf, bf16* __restrict__ Chi, bf16* __restrict__ Clo,
      int M, int N, int K, int lda, int ldb, int ldc,
      long aT, long aH, long bT, long bH, long cT, long cH, int Hdiv,
      const float* __restrict__ bias, long biasH,
      const float* __restrict__ scale, long scT, long scH, int colMul,
      unsigned* __restrict__ maxu, int vlim)
{
    extern __shared__ bf16 smb[];
    const uint32_t sb = smem_u32(smb);
    const int tid = threadIdx.x;
    const int wid = tid >> 5, lane = tid & 31;
    const int warp_m = wid >> 2, warp_n = wid & 3;
    const int g = lane >> 2, tg = lane & 3;

    const int bz = blockIdx.z;
    const int t = bz / Hdiv, h = bz % Hdiv;
    const long aoff = (long)t * aT + (long)h * aH;
    const long boff = (long)t * bT + (long)h * bH;
    const long coff = (long)t * cT + (long)h * cH;
    const float* biasp  = (EPI == 1 || EPI == 3) ? bias + (long)h * biasH : nullptr;
    const float* scalep = (EPI == 2) ? scale + (long)t * scT + (long)h * scH : nullptr;

    const int m0 = blockIdx.y * 128;
    const int n0 = blockIdx.x * 128;

    const bf16* srcs[4] = {Ahi + aoff, Alo + aoff, Bhi + boff, Blo + boff};

    const int S = K >> 5;

    auto stage = [&](int s, int bi) {
        const int k0 = s << 5;
        const int r = tid >> 2, q = tid & 3;
#pragma unroll
        for (int T = 0; T < 4; T++) {
            const int rows  = (T < 2) ? M : N;
            const int rbase = (T < 2) ? m0 : n0;
            const int ld    = (T < 2) ? lda : ldb;
            const int gr = rbase + r;
            const int sz = (gr < rows) ? 16 : 0;
            const bf16* sp = srcs[T] + (long)(sz ? gr : rbase) * ld + k0 + q * 8;
            const uint32_t dst = sb + (uint32_t)(bi * STAGE_E + T * TILE_E
                                                 + r * TSTRIDE + q * 8) * 2;
            cpasync16(dst, sp, sz);
        }
        asm volatile("cp.async.commit_group;" ::: "memory");
    };

    float acc[2][4][4];
#pragma unroll
    for (int i = 0; i < 2; i++)
#pragma unroll
        for (int j = 0; j < 4; j++)
#pragma unroll
            for (int e = 0; e < 4; e++) acc[i][j][e] = 0.f;

    stage(0, 0);
    stage(1, 1);

    for (int s = 0; s < S; s++) {
        const int bi = s % 3;
        if (s + 1 < S) asm volatile("cp.async.wait_group 1;" ::: "memory");
        else           asm volatile("cp.async.wait_group 0;" ::: "memory");
        __syncthreads();

        const uint32_t base = sb + (uint32_t)(bi * STAGE_E) * 2;
#pragma unroll
        for (int ks = 0; ks < 2; ks++) {
            const int ko = ks << 4;
            uint32_t bh[4][2], bl[4][2];
#pragma unroll
            for (int p = 0; p < 2; p++) {
                const int nrow = warp_n * 32 + p * 16 + ((lane >> 4) << 3) + (lane & 7);
                const int kcol = ko + ((lane >> 3) & 1) * 8;
                const uint32_t ab = base + (uint32_t)(2 * TILE_E + nrow * TSTRIDE + kcol) * 2;
                ldm4(bh[2 * p][0], bh[2 * p][1], bh[2 * p + 1][0], bh[2 * p + 1][1], ab);
                ldm4(bl[2 * p][0], bl[2 * p][1], bl[2 * p + 1][0], bl[2 * p + 1][1],
                     ab + (uint32_t)TILE_E * 2);
            }
#pragma unroll
            for (int ma = 0; ma < 2; ma++) {
                const int mrow = warp_m * 32 + ma * 16 + ((lane >> 3) & 1) * 8 + (lane & 7);
                const int kcol = ko + (lane >> 4) * 8;
                const uint32_t aa = base + (uint32_t)(mrow * TSTRIDE + kcol) * 2;
                uint32_t ah0, ah1, ah2, ah3, al0, al1, al2, al3;
                ldm4(ah0, ah1, ah2, ah3, aa);
                ldm4(al0, al1, al2, al3, aa + (uint32_t)TILE_E * 2);
#pragma unroll
                for (int nb = 0; nb < 4; nb++) {
                    mma16816(acc[ma][nb], ah0, ah1, ah2, ah3, bh[nb][0], bh[nb][1]);
                    mma16816(acc[ma][nb], ah0, ah1, ah2, ah3, bl[nb][0], bl[nb][1]);
                    mma16816(acc[ma][nb], al0, al1, al2, al3, bh[nb][0], bh[nb][1]);
                }
            }
        }
        if (s + 2 < S) stage(s + 2, (s + 2) % 3);
    }

    // ---- epilogue
    float slabmax = -3.4e38f;                 // EPI 5
#pragma unroll
    for (int ma = 0; ma < 2; ma++) {
#pragma unroll
        for (int hf = 0; hf < 2; hf++) {
            const int row = m0 + warp_m * 32 + ma * 16 + g + hf * 8;
            float rowmax = -3.4e38f;          // EPI 6
            const bool rok = row < M;
            const float sc = (EPI == 2 && rok) ? scalep[row] : 1.f;
#pragma unroll
            for (int nb = 0; nb < 4; nb++) {
                const int col = n0 + warp_n * 32 + nb * 8 + 2 * tg;
#pragma unroll
                for (int e = 0; e < 2; e++) {
                    if (!rok || col + e >= N) continue;
                    float v = acc[ma][nb][hf * 2 + e];
                    if (EPI == 1 || EPI == 3) v += biasp[col + e];
                    if (EPI == 2) v *= sc;
                    long idx = coff + (long)row * ldc
                             + (EPI == 2 ? (long)(col + e) * colMul : (long)(col + e));
                    if (EPI == 1 || EPI == 5 || EPI == 6) {
                        Cf[idx] = v;
                        if ((EPI == 5 || EPI == 6) && col + e < vlim) {
                            if (EPI == 5) slabmax = fmaxf(slabmax, v);
                            else          rowmax  = fmaxf(rowmax, v);
                        }
                    } else {
                        bf16 hb, lb; splitw(v, hb, lb);
                        Chi[idx] = hb; Clo[idx] = lb;
                    }
                }
            }
            if (EPI == 6) {
                rowmax = fmaxf(rowmax, __shfl_xor_sync(0xffffffffu, rowmax, 1));
                rowmax = fmaxf(rowmax, __shfl_xor_sync(0xffffffffu, rowmax, 2));
                if (tg == 0 && rok)
                    atomicMax(&maxu[(long)bz * M + row], encf(rowmax));
            }
        }
    }
    if (EPI == 5) {
#pragma unroll
        for (int o = 16; o > 0; o >>= 1)
            slabmax = fmaxf(slabmax, __shfl_xor_sync(0xffffffffu, slabmax, o));
        if (lane == 0) atomicMax(&maxu[bz], encf(slabmax));
    }
}

// ---------------------------------------------------------------------------
// conversion / transpose / reset passes
// ---------------------------------------------------------------------------
__global__ void reset_k(unsigned* __restrict__ kmaxu, unsigned* __restrict__ rowmaxu)
{
    int i = blockIdx.x * blockDim.x + threadIdx.x;
    if (i < BATCH) kmaxu[i] = 0u;
    if (i < ROWS) rowmaxu[i] = 0u;
}

__global__ void split_k(const float* __restrict__ s, bf16* __restrict__ h,
                        bf16* __restrict__ l, size_t n, float scl)
{
    size_t i = (size_t)blockIdx.x * blockDim.x + threadIdx.x;
    if (i < n) {
        float x = s[i] * scl;
        bf16 hb, lb; splitw(x, hb, lb);
        h[i] = hb; l[i] = lb;
    }
}

// fp32 [z][R][C] -> bf16 hi/lo [z][C][R]
__global__ void tsplit_k(const float* __restrict__ src, bf16* __restrict__ hi,
                         bf16* __restrict__ lo, int R, int C)
{
    __shared__ float sm[32][33];
    const int z = blockIdx.z;
    const int c0 = blockIdx.x * 32, r0 = blockIdx.y * 32;
    const float* s = src + (size_t)z * R * C;
    bf16* ho = hi + (size_t)z * R * C;
    bf16* lv = lo + (size_t)z * R * C;
    const int tx = threadIdx.x, ty = threadIdx.y;
    for (int i = ty; i < 32; i += 8)
        sm[i][tx] = s[(size_t)(r0 + i) * C + c0 + tx];
    __syncthreads();
    for (int i = ty; i < 32; i += 8) {
        float x = sm[tx][i];
        bf16 hb, lb; splitw(x, hb, lb);
        ho[(size_t)(c0 + i) * R + r0 + tx] = hb;
        lv[(size_t)(c0 + i) * R + r0 + tx] = lb;
    }
}

// bf16 [z][R][C] -> bf16 [z][C][R]
__global__ void tbf_k(const bf16* __restrict__ src, bf16* __restrict__ dst,
                      int R, int C)
{
    __shared__ bf16 sm[32][33];
    const int z = blockIdx.z;
    const int c0 = blockIdx.x * 32, r0 = blockIdx.y * 32;
    const bf16* s = src + (size_t)z * R * C;
    bf16* d = dst + (size_t)z * R * C;
    const int tx = threadIdx.x, ty = threadIdx.y;
    for (int i = ty; i < 32; i += 8)
        sm[i][tx] = s[(size_t)(r0 + i) * C + c0 + tx];
    __syncthreads();
    for (int i = ty; i < 32; i += 8)
        d[(size_t)(c0 + i) * R + r0 + tx] = sm[tx][i];
}

// ---------------------------------------------------------------------------
// feature-map / reduction kernels
// ---------------------------------------------------------------------------
// q feature map + d_inv fused (runs AFTER ksum is ready; rowmax precomputed)
__global__ void __launch_bounds__(256)
qexp2_k(const float* __restrict__ qp, const bf16* __restrict__ qh,
        const bf16* __restrict__ ql, const unsigned* __restrict__ rowmaxu,
        const float* __restrict__ ksum, bf16* __restrict__ oh,
        bf16* __restrict__ ol, float* __restrict__ dinv)
{
    const size_t r = blockIdx.x;
    const int b = (int)(r >> 10);
    const float* prow = qp + r * NBP;
    const float* ks = ksum + (size_t)b * NBP;
    const int tid = threadIdx.x;
    __shared__ float red[256];

    float x = __bfloat162float(qh[r * DDIM + tid]) + __bfloat162float(ql[r * DDIM + tid]);
    red[tid] = x * x;
    __syncthreads();
    for (int s = 128; s > 0; s >>= 1) {
        if (tid < s) red[tid] += red[tid + s];
        __syncthreads();
    }
    const float c = 0.5f * DNORM2 * red[0] + decf(rowmaxu[r]);
    __syncthreads();

    float dot = 0.f;
    for (int j = tid; j < NBP; j += 256) {
        float v = (j < NBF) ? RATIO * (expf(prow[j] - c) + EPSF) : 0.f;
        bf16 hb, lb; splitw(v, hb, lb);
        oh[r * NBP + j] = hb; ol[r * NBP + j] = lb;
        dot += v * ks[j];
    }
    red[tid] = dot;
    __syncthreads();
    for (int s = 128; s > 0; s >>= 1) {
        if (tid < s) red[tid] += red[tid + s];
        __syncthreads();
    }
    if (tid == 0) dinv[r] = 1.0f / red[0];
}

__global__ void __launch_bounds__(256)
kdiag_k(const bf16* __restrict__ kh, const bf16* __restrict__ kl,
        float* __restrict__ diag)
{
    const size_t r = blockIdx.x;
    const int tid = threadIdx.x;
    __shared__ float red[256];
    float x = __bfloat162float(kh[r * DDIM + tid]) + __bfloat162float(kl[r * DDIM + tid]);
    red[tid] = x * x;
    __syncthreads();
    for (int s = 128; s > 0; s >>= 1) {
        if (tid < s) red[tid] += red[tid + s];
        __syncthreads();
    }
    if (tid == 0) diag[r] = 0.5f * DNORM2 * red[0];
}

// transpose + exp for K -> kpT hi/lo [b][m][n] + ksum partials
__global__ void __launch_bounds__(256)
ktexp_k(const float* __restrict__ kp, const float* __restrict__ diag,
        const unsigned* __restrict__ kmaxu, bf16* __restrict__ th,
        bf16* __restrict__ tl, float* __restrict__ part)
{
    __shared__ float sm[32][33];
    const int b = blockIdx.z;
    const int m0 = blockIdx.x * 32, n0 = blockIdx.y * 32;
    const int tx = threadIdx.x, ty = threadIdx.y;
    const float km = decf(kmaxu[b]);

    for (int i = ty; i < 32; i += 8) {
        const int n = n0 + i, m = m0 + tx;
        const float dk = diag[(size_t)b * NPT + n];
        const float v = kp[((size_t)b * NPT + n) * NBP + m];
        sm[i][tx] = (m < NBF) ? RATIO * (expf(v - dk - km) + EPSF) : 0.f;
    }
    __syncthreads();

    for (int i = ty; i < 32; i += 8) {
        const int m = m0 + i;
        const float v = sm[tx][i];
        bf16 hb, lb; splitw(v, hb, lb);
        const size_t idx = ((size_t)b * NBP + m) * NPT + n0 + tx;
        th[idx] = hb; tl[idx] = lb;
        float s = v;
        for (int o = 16; o > 0; o >>= 1) s += __shfl_down_sync(0xffffffffu, s, o);
        if (tx == 0)
            part[((size_t)b * 32 + blockIdx.y) * NBP + m] = s;
    }
}

__global__ void ksum2_k(const float* __restrict__ part, float* __restrict__ ksum)
{
    const int b = blockIdx.y;
    const int m = blockIdx.x * blockDim.x + threadIdx.x;
    if (m >= NBP) return;
    float s = 0.f;
    for (int j = 0; j < 32; j++)
        s += part[((size_t)b * 32 + j) * NBP + m];
    ksum[(size_t)b * NBP + m] = s;
}

// ---------------------------------------------------------------------------
// Launch
// ---------------------------------------------------------------------------
#define GETP(var, sym) cudaGetSymbolAddress((void**)&var, sym)

extern "C" void kernel_launch(void* const* d_in, const int* in_sizes, int n_in,
                              void* d_out, int out_size)
{
    const float* q     = (const float*)d_in[0];
    const float* k     = (const float*)d_in[1];
    const float* v     = (const float*)d_in[2];
    const float* Wq    = (const float*)d_in[3];
    const float* bq    = (const float*)d_in[4];
    const float* Wk    = (const float*)d_in[5];
    const float* bk    = (const float*)d_in[6];
    const float* Wv    = (const float*)d_in[7];
    const float* bv    = (const float*)d_in[8];
    const float* W_out = (const float*)d_in[9];
    const float* b_out = (const float*)d_in[10];
    const float* proj  = (const float*)d_in[11];
    float* out = (float*)d_out;

    float *qp, *kp, *diagk, *ksum, *kpart, *dinv;
    unsigned *kmaxu, *rowmaxu;
    bf16 *qin_h, *qin_l, *kin_h, *kin_l, *vin_h, *vin_l;
    bf16 *wtq_h, *wtq_l, *wtk_h, *wtk_l, *wtv_h, *wtv_l;
    bf16 *pr_h, *pr_l, *wo_h, *wo_l;
    bf16 *qall_h, *qall_l, *kall_h, *kall_l, *vall_h, *vall_l, *vt_h, *vt_l;
    bf16 *qph, *qpl, *kpT_h, *kpT_l, *ctxT_h, *ctxT_l, *outs_h, *outs_l;

    GETP(qp, g_qp); GETP(kp, g_kp);
    GETP(qin_h, g_qin_h); GETP(qin_l, g_qin_l);
    GETP(kin_h, g_kin_h); GETP(kin_l, g_kin_l);
    GETP(vin_h, g_vin_h); GETP(vin_l, g_vin_l);
    GETP(wtq_h, g_wtq_h); GETP(wtq_l, g_wtq_l);
    GETP(wtk_h, g_wtk_h); GETP(wtk_l, g_wtk_l);
    GETP(wtv_h, g_wtv_h); GETP(wtv_l, g_wtv_l);
    GETP(pr_h, g_pr_h);   GETP(pr_l, g_pr_l);
    GETP(wo_h, g_wo_h);   GETP(wo_l, g_wo_l);
    GETP(qall_h, g_qall_h); GETP(qall_l, g_qall_l);
    GETP(kall_h, g_kall_h); GETP(kall_l, g_kall_l);
    GETP(vall_h, g_vall_h); GETP(vall_l, g_vall_l);
    GETP(vt_h, g_vt_h);     GETP(vt_l, g_vt_l);
    GETP(qph, g_qph);       GETP(qpl, g_qpl);
    GETP(kpT_h, g_kpT_h);   GETP(kpT_l, g_kpT_l);
    GETP(ctxT_h, g_ctxT_h); GETP(ctxT_l, g_ctxT_l);
    GETP(outs_h, g_outs_h); GETP(outs_l, g_outs_l);
    GETP(diagk, g_diagk); GETP(ksum, g_ksum); GETP(kpart, g_kpart);
    GETP(dinv, g_dinv); GETP(kmaxu, g_kmaxu); GETP(rowmaxu, g_rowmaxu);

    cudaFuncSetAttribute(gemm6<1>, cudaFuncAttributeMaxDynamicSharedMemorySize, G6SMEM);
    cudaFuncSetAttribute(gemm6<2>, cudaFuncAttributeMaxDynamicSharedMemorySize, G6SMEM);
    cudaFuncSetAttribute(gemm6<3>, cudaFuncAttributeMaxDynamicSharedMemorySize, G6SMEM);
    cudaFuncSetAttribute(gemm6<4>, cudaFuncAttributeMaxDynamicSharedMemorySize, G6SMEM);
    cudaFuncSetAttribute(gemm6<5>, cudaFuncAttributeMaxDynamicSharedMemorySize, G6SMEM);
    cudaFuncSetAttribute(gemm6<6>, cudaFuncAttributeMaxDynamicSharedMemorySize, G6SMEM);

    // ---- 0) reset atomic-max buffers (graph replays!) + operand splits
    reset_k<<<(ROWS + 255) / 256, 256>>>(kmaxu, rowmaxu);
    {
        const size_t nin = (size_t)TT * NPT * DDIM;
        split_k<<<(unsigned)((nin + 255) / 256), 256>>>(q, qin_h, qin_l, nin, 1.f);
        split_k<<<(unsigned)((nin + 255) / 256), 256>>>(k, kin_h, kin_l, nin, 1.f);
        split_k<<<(unsigned)((nin + 255) / 256), 256>>>(v, vin_h, vin_l, nin, 1.f);
        dim3 tg(8, 8, 8), tb(32, 8);
        tsplit_k<<<tg, tb>>>(Wq, wtq_h, wtq_l, DDIM, DDIM);
        tsplit_k<<<tg, tb>>>(Wk, wtk_h, wtk_l, DDIM, DDIM);
        tsplit_k<<<tg, tb>>>(Wv, wtv_h, wtv_l, DDIM, DDIM);
        const size_t npr = (size_t)NBF * DDIM;
        split_k<<<(unsigned)((npr + 255) / 256), 256>>>(proj, pr_h, pr_l, npr, DNORM);
        const size_t nwo = (size_t)DDIM * HDCAT;
        split_k<<<(unsigned)((nwo + 255) / 256), 256>>>(W_out, wo_h, wo_l, nwo, 1.f);
    }

    // ---- 1) per-head projections: C[t,h][1024,256] = X[t] * Wt[h]^T + b[h]
    {
        dim3 grid(2, 8, BATCH);
        gemm6<3><<<grid, 512, G6SMEM>>>(qin_h, qin_l, wtq_h, wtq_l,
            nullptr, qall_h, qall_l,
            NPT, DDIM, DDIM, DDIM, DDIM, DDIM,
            (long)NPT * DDIM, 0, 0, (long)DDIM * DDIM,
            (long)HH * NPT * DDIM, (long)NPT * DDIM, HH,
            bq, DDIM, nullptr, 0, 0, 1, nullptr, 0);
        gemm6<3><<<grid, 512, G6SMEM>>>(kin_h, kin_l, wtk_h, wtk_l,
            nullptr, kall_h, kall_l,
            NPT, DDIM, DDIM, DDIM, DDIM, DDIM,
            (long)NPT * DDIM, 0, 0, (long)DDIM * DDIM,
            (long)HH * NPT * DDIM, (long)NPT * DDIM, HH,
            bk, DDIM, nullptr, 0, 0, 1, nullptr, 0);
        gemm6<3><<<grid, 512, G6SMEM>>>(vin_h, vin_l, wtv_h, wtv_l,
            nullptr, vall_h, vall_l,
            NPT, DDIM, DDIM, DDIM, DDIM, DDIM,
            (long)NPT * DDIM, 0, 0, (long)DDIM * DDIM,
            (long)HH * NPT * DDIM, (long)NPT * DDIM, HH,
            bv, DDIM, nullptr, 0, 0, 1, nullptr, 0);
    }

    // ---- 2) dash GEMMs with fused max reductions
    {
        dim3 grid(12, 8, BATCH);
        gemm6<6><<<grid, 512, G6SMEM>>>(qall_h, qall_l, pr_h, pr_l,
            qp, nullptr, nullptr,
            NPT, NBP, DDIM, DDIM, DDIM, NBP,
            (long)NPT * DDIM, 0, 0, 0, (long)NPT * NBP, 0, 1,
            nullptr, 0, nullptr, 0, 0, 1, rowmaxu, NBF);
        gemm6<5><<<grid, 512, G6SMEM>>>(kall_h, kall_l, pr_h, pr_l,
            kp, nullptr, nullptr,
            NPT, NBP, DDIM, DDIM, DDIM, NBP,
            (long)NPT * DDIM, 0, 0, 0, (long)NPT * NBP, 0, 1,
            nullptr, 0, nullptr, 0, 0, 1, kmaxu, NBF);
    }

    // ---- 3) k-side feature map chain, then fused q-exp + d_inv
    kdiag_k<<<ROWS, 256>>>(kall_h, kall_l, diagk);
    ktexp_k<<<dim3(45, 32, BATCH), dim3(32, 8)>>>(kp, diagk, kmaxu, kpT_h, kpT_l, kpart);
    ksum2_k<<<dim3(6, BATCH), 256>>>(kpart, ksum);
    qexp2_k<<<ROWS, 256>>>(qp, qall_h, qall_l, rowmaxu, ksum, qph, qpl, dinv);

    // ---- 4) vallT
    {
        dim3 tg(8, 32, BATCH), tb(32, 8);
        tbf_k<<<tg, tb>>>(vall_h, vt_h, NPT, DDIM);
        tbf_k<<<tg, tb>>>(vall_l, vt_l, NPT, DDIM);
    }

    // ---- 5) ctxT[b][e][m] = vallT[b] * kpT[b]^T
    {
        dim3 grid(12, 2, BATCH);
        gemm6<4><<<grid, 512, G6SMEM>>>(vt_h, vt_l, kpT_h, kpT_l,
            nullptr, ctxT_h, ctxT_l,
            DDIM, NBP, NPT, NPT, NPT, NBP,
            (long)DDIM * NPT, 0, (long)NBP * NPT, 0, (long)DDIM * NBP, 0, 1,
            nullptr, 0, nullptr, 0, 0, 1, nullptr, 0);
    }

    // ---- 6) out[t,h][n][e] = qp' * ctxT^T, *dinv, permuted bf16 store
    {
        dim3 grid(2, 8, BATCH);
        gemm6<2><<<grid, 512, G6SMEM>>>(qph, qpl, ctxT_h, ctxT_l,
            nullptr, outs_h, outs_l,
            NPT, DDIM, NBP, NBP, NBP, HDCAT,
            (long)HH * NPT * NBP, (long)NPT * NBP,
            (long)HH * DDIM * NBP, (long)DDIM * NBP,
            (long)NPT * HDCAT, 1, HH,
            nullptr, 0, dinv, (long)HH * NPT, (long)NPT, HH, nullptr, 0);
    }

    // ---- 7) final: rep[8192][256] = outs * W_out^T + b_out
    {
        dim3 grid(2, 64, 1);
        gemm6<1><<<grid, 512, G6SMEM>>>(outs_h, outs_l, wo_h, wo_l,
            out, nullptr, nullptr,
            TT * NPT, DDIM, HDCAT, HDCAT, HDCAT, DDIM,
            0, 0, 0, 0, 0, 0, 1,
            b_out, 0, nullptr, 0, 0, 1, nullptr, 0);
    }
}

// round 10
// speedup vs baseline: 3.2603x; 1.1790x over previous
#include <cuda_runtime.h>
#include <cuda_bf16.h>
#include <cstdint>
#include <math.h>

// ---------------------------------------------------------------------------
// Problem constants (T=8, N=M=1024, H=8, D=256, NB = int(256*ln 256) = 1419)
// ---------------------------------------------------------------------------
#define TT   8
#define NPT  1024
#define HH   8
#define DDIM 256
#define NBF  1419
#define NBP  1440              // padded to multiple of 32
#define ROWS (TT * HH * NPT)   // 65536
#define BATCH (TT * HH)        // 64
#define HDCAT (HH * DDIM)      // 2048

#define DNORM   0.25f          // 256^-0.25
#define DNORM2  0.0625f
#define EPSF    1e-4f
#define RATIO   0.026547529f   // 1/sqrt(1419)

typedef __nv_bfloat16 bf16;

// ---------------------------------------------------------------------------
// Scratch (device globals; zero-init at load -> never-written pads stay 0)
// ---------------------------------------------------------------------------
__device__ float g_qp[(size_t)ROWS * NBP];
__device__ float g_kp[(size_t)ROWS * NBP];
__device__ bf16 g_qin_h[(size_t)TT * NPT * DDIM],  g_qin_l[(size_t)TT * NPT * DDIM];
__device__ bf16 g_kin_h[(size_t)TT * NPT * DDIM],  g_kin_l[(size_t)TT * NPT * DDIM];
__device__ bf16 g_vin_h[(size_t)TT * NPT * DDIM],  g_vin_l[(size_t)TT * NPT * DDIM];
__device__ bf16 g_wtq_h[(size_t)HH * DDIM * DDIM], g_wtq_l[(size_t)HH * DDIM * DDIM];
__device__ bf16 g_wtk_h[(size_t)HH * DDIM * DDIM], g_wtk_l[(size_t)HH * DDIM * DDIM];
__device__ bf16 g_wtv_h[(size_t)HH * DDIM * DDIM], g_wtv_l[(size_t)HH * DDIM * DDIM];
__device__ bf16 g_pr_h[(size_t)NBP * DDIM],        g_pr_l[(size_t)NBP * DDIM];
__device__ bf16 g_wo_h[(size_t)DDIM * HDCAT],      g_wo_l[(size_t)DDIM * HDCAT];
__device__ bf16 g_qall_h[(size_t)ROWS * DDIM],     g_qall_l[(size_t)ROWS * DDIM];
__device__ bf16 g_kall_h[(size_t)ROWS * DDIM],     g_kall_l[(size_t)ROWS * DDIM];
__device__ bf16 g_vall_h[(size_t)ROWS * DDIM],     g_vall_l[(size_t)ROWS * DDIM];
__device__ bf16 g_vt_h[(size_t)ROWS * DDIM],       g_vt_l[(size_t)ROWS * DDIM];
__device__ bf16 g_qph[(size_t)ROWS * NBP],         g_qpl[(size_t)ROWS * NBP];
__device__ bf16 g_kpT_h[(size_t)BATCH * NBP * NPT], g_kpT_l[(size_t)BATCH * NBP * NPT];
__device__ bf16 g_ctxT_h[(size_t)BATCH * DDIM * NBP], g_ctxT_l[(size_t)BATCH * DDIM * NBP];
__device__ bf16 g_outs_h[(size_t)TT * NPT * HDCAT], g_outs_l[(size_t)TT * NPT * HDCAT];
__device__ float g_diagk[(size_t)ROWS];
__device__ float g_ksum[(size_t)BATCH * NBP];
__device__ float g_kpart[(size_t)BATCH * 8 * NBP];
__device__ float g_dinv[(size_t)ROWS];
__device__ unsigned g_kmaxu[(size_t)BATCH];
__device__ unsigned g_rowmaxu[(size_t)ROWS];

// ---------------------------------------------------------------------------
// helpers
// ---------------------------------------------------------------------------
__device__ __forceinline__ uint32_t smem_u32(const void* p) {
    uint32_t a;
    asm("{ .reg .u64 t; cvta.to.shared.u64 t, %1; cvt.u32.u64 %0, t; }"
        : "=r"(a) : "l"(p));
    return a;
}

__device__ __forceinline__ void ldm4(uint32_t& r0, uint32_t& r1,
                                     uint32_t& r2, uint32_t& r3, uint32_t a) {
    asm volatile("ldmatrix.sync.aligned.m8n8.x4.shared.b16 {%0,%1,%2,%3}, [%4];"
                 : "=r"(r0), "=r"(r1), "=r"(r2), "=r"(r3) : "r"(a));
}

__device__ __forceinline__ void mma16816(float* c, uint32_t a0, uint32_t a1,
                                         uint32_t a2, uint32_t a3,
                                         uint32_t b0, uint32_t b1) {
    asm volatile(
        "mma.sync.aligned.m16n8k16.row.col.f32.bf16.bf16.f32 "
        "{%0,%1,%2,%3},{%4,%5,%6,%7},{%8,%9},{%0,%1,%2,%3};"
        : "+f"(c[0]), "+f"(c[1]), "+f"(c[2]), "+f"(c[3])
        : "r"(a0), "r"(a1), "r"(a2), "r"(a3), "r"(b0), "r"(b1));
}

__device__ __forceinline__ void cpasync16(uint32_t dst, const bf16* src, int sz) {
    asm volatile("cp.async.cg.shared.global [%0], [%1], 16, %2;"
                 :: "r"(dst), "l"(__cvta_generic_to_global(src)), "r"(sz));
}

__device__ __forceinline__ void splitw(float x, bf16& h, bf16& l) {
    h = __float2bfloat16_rn(x);
    l = __float2bfloat16_rn(x - __bfloat162float(h));
}

__device__ __forceinline__ uint32_t packbf(bf16 a, bf16 b) {
    return (uint32_t)__bfloat16_as_ushort(a)
         | ((uint32_t)__bfloat16_as_ushort(b) << 16);
}

// split two floats -> packed hi word, packed lo word
__device__ __forceinline__ void split2p(float x, float y,
                                        uint32_t& ph, uint32_t& pl) {
    bf16 hx, lx, hy, ly;
    splitw(x, hx, lx); splitw(y, hy, ly);
    ph = packbf(hx, hy); pl = packbf(lx, ly);
}

// sum of (hi+lo)^2 over a packed pair
__device__ __forceinline__ float sq2(uint32_t hw, uint32_t lw) {
    float x0 = __bfloat162float(__ushort_as_bfloat16((unsigned short)(hw & 0xffff)))
             + __bfloat162float(__ushort_as_bfloat16((unsigned short)(lw & 0xffff)));
    float x1 = __bfloat162float(__ushort_as_bfloat16((unsigned short)(hw >> 16)))
             + __bfloat162float(__ushort_as_bfloat16((unsigned short)(lw >> 16)));
    return x0 * x0 + x1 * x1;
}

// monotonic float <-> unsigned encoding (total order; exact; order-independent max)
__device__ __forceinline__ unsigned encf(float f) {
    unsigned u = __float_as_uint(f);
    return (u & 0x80000000u) ? ~u : (u | 0x80000000u);
}
__device__ __forceinline__ float decf(unsigned u) {
    unsigned b = (u & 0x80000000u) ? (u ^ 0x80000000u) : ~u;
    return __uint_as_float(b);
}

// ---------------------------------------------------------------------------
// gemm6: NT bf16x3 mma.sync GEMM, 512 threads, 16 warps (4x4), 32x32/warp.
//   C[M,N] = A[M,K] * B[N,K]^T ; operands hi/lo bf16, k-contiguous.
//   EPI: 1 +bias f32 | 2 *scale[row] bf16 pair | 3 +bias bf16 pair
//        4 plain bf16 pair | 5 f32 + slab-max atomic | 6 f32 + row-max atomic
//   K % 32 == 0, N even, lda == ldb == K.
// ---------------------------------------------------------------------------
#define TSTRIDE 40
#define TILE_E  (128 * TSTRIDE)       // 5120 bf16
#define STAGE_E (4 * TILE_E)          // 20480 bf16
#define G6SMEM  (3 * STAGE_E * 2)     // 122880 bytes

template<int EPI>
__global__ void __launch_bounds__(512)
gemm6(const bf16* __restrict__ Ahi, const bf16* __restrict__ Alo,
      const bf16* __restrict__ Bhi, const bf16* __restrict__ Blo,
      float* __restrict__ Cf, bf16* __restrict__ Chi, bf16* __restrict__ Clo,
      int M, int N, int K, int lda, int ldb, int ldc,
      long aT, long aH, long bT, long bH, long cT, long cH, int Hdiv,
      const float* __restrict__ bias, long biasH,
      const float* __restrict__ scale, long scT, long scH,
      unsigned* __restrict__ maxu, int vlim)
{
    extern __shared__ bf16 smb[];
    const uint32_t sb = smem_u32(smb);
    const int tid = threadIdx.x;
    const int wid = tid >> 5, lane = tid & 31;
    const int warp_m = wid >> 2, warp_n = wid & 3;
    const int g = lane >> 2, tg = lane & 3;

    const int bz = blockIdx.z;
    const int t = bz / Hdiv, h = bz % Hdiv;
    const long aoff = (long)t * aT + (long)h * aH;
    const long boff = (long)t * bT + (long)h * bH;
    const long coff = (long)t * cT + (long)h * cH;
    const float* biasp  = (EPI == 1 || EPI == 3) ? bias + (long)h * biasH : nullptr;
    const float* scalep = (EPI == 2) ? scale + (long)t * scT + (long)h * scH : nullptr;

    const int m0 = blockIdx.y * 128;
    const int n0 = blockIdx.x * 128;

    const bf16* srcs[4] = {Ahi + aoff, Alo + aoff, Bhi + boff, Blo + boff};

    const int S = K >> 5;

    auto stage = [&](int s, int bi) {
        const int k0 = s << 5;
        const int r = tid >> 2, q = tid & 3;
#pragma unroll
        for (int T = 0; T < 4; T++) {
            const int rows  = (T < 2) ? M : N;
            const int rbase = (T < 2) ? m0 : n0;
            const int ld    = (T < 2) ? lda : ldb;
            const int gr = rbase + r;
            const int sz = (gr < rows) ? 16 : 0;
            const bf16* sp = srcs[T] + (long)(sz ? gr : rbase) * ld + k0 + q * 8;
            const uint32_t dst = sb + (uint32_t)(bi * STAGE_E + T * TILE_E
                                                 + r * TSTRIDE + q * 8) * 2;
            cpasync16(dst, sp, sz);
        }
        asm volatile("cp.async.commit_group;" ::: "memory");
    };

    float acc[2][4][4];
#pragma unroll
    for (int i = 0; i < 2; i++)
#pragma unroll
        for (int j = 0; j < 4; j++)
#pragma unroll
            for (int e = 0; e < 4; e++) acc[i][j][e] = 0.f;

    stage(0, 0);
    stage(1, 1);

    for (int s = 0; s < S; s++) {
        const int bi = s % 3;
        if (s + 1 < S) asm volatile("cp.async.wait_group 1;" ::: "memory");
        else           asm volatile("cp.async.wait_group 0;" ::: "memory");
        __syncthreads();

        const uint32_t base = sb + (uint32_t)(bi * STAGE_E) * 2;
#pragma unroll
        for (int ks = 0; ks < 2; ks++) {
            const int ko = ks << 4;
            uint32_t bh[4][2], bl[4][2];
#pragma unroll
            for (int p = 0; p < 2; p++) {
                const int nrow = warp_n * 32 + p * 16 + ((lane >> 4) << 3) + (lane & 7);
                const int kcol = ko + ((lane >> 3) & 1) * 8;
                const uint32_t ab = base + (uint32_t)(2 * TILE_E + nrow * TSTRIDE + kcol) * 2;
                ldm4(bh[2 * p][0], bh[2 * p][1], bh[2 * p + 1][0], bh[2 * p + 1][1], ab);
                ldm4(bl[2 * p][0], bl[2 * p][1], bl[2 * p + 1][0], bl[2 * p + 1][1],
                     ab + (uint32_t)TILE_E * 2);
            }
#pragma unroll
            for (int ma = 0; ma < 2; ma++) {
                const int mrow = warp_m * 32 + ma * 16 + ((lane >> 3) & 1) * 8 + (lane & 7);
                const int kcol = ko + (lane >> 4) * 8;
                const uint32_t aa = base + (uint32_t)(mrow * TSTRIDE + kcol) * 2;
                uint32_t ah0, ah1, ah2, ah3, al0, al1, al2, al3;
                ldm4(ah0, ah1, ah2, ah3, aa);
                ldm4(al0, al1, al2, al3, aa + (uint32_t)TILE_E * 2);
#pragma unroll
                for (int nb = 0; nb < 4; nb++) {
                    mma16816(acc[ma][nb], ah0, ah1, ah2, ah3, bh[nb][0], bh[nb][1]);
                    mma16816(acc[ma][nb], ah0, ah1, ah2, ah3, bl[nb][0], bl[nb][1]);
                    mma16816(acc[ma][nb], al0, al1, al2, al3, bh[nb][0], bh[nb][1]);
                }
            }
        }
        if (s + 2 < S) stage(s + 2, (s + 2) % 3);
    }

    // ---- epilogue (N even; col and col+1 always in-bounds together)
    float slabmax = -3.4e38f;
#pragma unroll
    for (int ma = 0; ma < 2; ma++) {
#pragma unroll
        for (int hf = 0; hf < 2; hf++) {
            const int row = m0 + warp_m * 32 + ma * 16 + g + hf * 8;
            float rowmax = -3.4e38f;
            const bool rok = row < M;
            const float sc = (EPI == 2 && rok) ? scalep[row] : 1.f;
#pragma unroll
            for (int nb = 0; nb < 4; nb++) {
                const int col = n0 + warp_n * 32 + nb * 8 + 2 * tg;
                if (!rok || col >= N) continue;
                float v0 = acc[ma][nb][hf * 2 + 0];
                float v1 = acc[ma][nb][hf * 2 + 1];
                if (EPI == 1 || EPI == 3) { v0 += biasp[col]; v1 += biasp[col + 1]; }
                if (EPI == 2) { v0 *= sc; v1 *= sc; }
                const long idx = coff + (long)row * ldc + col;
                if (EPI == 1 || EPI == 5 || EPI == 6) {
                    *(float2*)&Cf[idx] = make_float2(v0, v1);
                    if (EPI == 5 || EPI == 6) {
                        if (col < vlim) {
                            if (EPI == 5) slabmax = fmaxf(slabmax, v0);
                            else          rowmax  = fmaxf(rowmax, v0);
                        }
                        if (col + 1 < vlim) {
                            if (EPI == 5) slabmax = fmaxf(slabmax, v1);
                            else          rowmax  = fmaxf(rowmax, v1);
                        }
                    }
                } else {
                    uint32_t ph, pl;
                    split2p(v0, v1, ph, pl);
                    *(uint32_t*)&Chi[idx] = ph;
                    *(uint32_t*)&Clo[idx] = pl;
                }
            }
            if (EPI == 6) {
                rowmax = fmaxf(rowmax, __shfl_xor_sync(0xffffffffu, rowmax, 1));
                rowmax = fmaxf(rowmax, __shfl_xor_sync(0xffffffffu, rowmax, 2));
                if (tg == 0 && rok)
                    atomicMax(&maxu[(long)bz * M + row], encf(rowmax));
            }
        }
    }
    if (EPI == 5) {
#pragma unroll
        for (int o = 16; o > 0; o >>= 1)
            slabmax = fmaxf(slabmax, __shfl_xor_sync(0xffffffffu, slabmax, o));
        if (lane == 0) atomicMax(&maxu[bz], encf(slabmax));
    }
}

// ---------------------------------------------------------------------------
// conversion / transpose / reset passes
// ---------------------------------------------------------------------------
__global__ void reset_k(unsigned* __restrict__ kmaxu, unsigned* __restrict__ rowmaxu)
{
    int i = blockIdx.x * blockDim.x + threadIdx.x;
    if (i < BATCH) kmaxu[i] = 0u;
    if (i < ROWS) rowmaxu[i] = 0u;
}

// vectorized split: 4 elems/thread (n % 4 == 0)
__global__ void split_k(const float* __restrict__ s, bf16* __restrict__ h,
                        bf16* __restrict__ l, size_t n, float scl)
{
    size_t i4 = ((size_t)blockIdx.x * blockDim.x + threadIdx.x) * 4;
    if (i4 < n) {
        float4 x = *(const float4*)(s + i4);
        uint32_t ph0, pl0, ph1, pl1;
        split2p(x.x * scl, x.y * scl, ph0, pl0);
        split2p(x.z * scl, x.w * scl, ph1, pl1);
        *(uint2*)(h + i4) = make_uint2(ph0, ph1);
        *(uint2*)(l + i4) = make_uint2(pl0, pl1);
    }
}

// W_out permuted split: wr[d][h*256+e] = W_out[d][e*8+h]
__global__ void wsplit_k(const float* __restrict__ W, bf16* __restrict__ h,
                         bf16* __restrict__ l)
{
    int i = blockIdx.x * blockDim.x + threadIdx.x;
    if (i < DDIM * HDCAT) {
        int d = i / HDCAT, fp = i % HDCAT;
        int hh = fp >> 8, e = fp & 255;
        float x = W[(size_t)d * HDCAT + e * 8 + hh];
        bf16 hb, lb; splitw(x, hb, lb);
        h[i] = hb; l[i] = lb;
    }
}

// fp32 [z][R][C] -> bf16 hi/lo [z][C][R] (weights, small)
__global__ void tsplit_k(const float* __restrict__ src, bf16* __restrict__ hi,
                         bf16* __restrict__ lo, int R, int C)
{
    __shared__ float sm[32][33];
    const int z = blockIdx.z;
    const int c0 = blockIdx.x * 32, r0 = blockIdx.y * 32;
    const float* s = src + (size_t)z * R * C;
    bf16* ho = hi + (size_t)z * R * C;
    bf16* lv = lo + (size_t)z * R * C;
    const int tx = threadIdx.x, ty = threadIdx.y;
    for (int i = ty; i < 32; i += 8)
        sm[i][tx] = s[(size_t)(r0 + i) * C + c0 + tx];
    __syncthreads();
    for (int i = ty; i < 32; i += 8) {
        float x = sm[tx][i];
        bf16 hb, lb; splitw(x, hb, lb);
        ho[(size_t)(c0 + i) * R + r0 + tx] = hb;
        lv[(size_t)(c0 + i) * R + r0 + tx] = lb;
    }
}

// bf16 [z][R][C] -> [z][C][R], 64x64 tiles, vectorized (R,C % 64 == 0)
__global__ void __launch_bounds__(256)
tbf_k(const bf16* __restrict__ src, bf16* __restrict__ dst, int R, int C)
{
    __shared__ bf16 sm[64][72];
    const int z = blockIdx.z;
    const int c0 = blockIdx.x * 64, r0 = blockIdx.y * 64;
    const bf16* s = src + (size_t)z * R * C;
    bf16* d = dst + (size_t)z * R * C;
    const int tid = threadIdx.x;
    {
        const int r = tid >> 2, cq = tid & 3;
        const uint4* sp = (const uint4*)(s + (size_t)(r0 + r) * C + c0 + cq * 16);
        *(uint4*)&sm[r][cq * 16]     = sp[0];
        *(uint4*)&sm[r][cq * 16 + 8] = sp[1];
    }
    __syncthreads();
    {
        const int c = tid >> 2, rq = tid & 3;
#pragma unroll
        for (int i = 0; i < 8; i++) {
            const int rp = rq * 8 + i;
            uint32_t w = packbf(sm[2 * rp][c], sm[2 * rp + 1][c]);
            *(uint32_t*)&d[(size_t)(c0 + c) * R + r0 + 2 * rp] = w;
        }
    }
}

// ---------------------------------------------------------------------------
// feature-map / reduction kernels
// ---------------------------------------------------------------------------
// diag_k[r] = 0.5*dn2*sum(k^2); warp per row, uint4 loads
__global__ void __launch_bounds__(256)
kdiag_k(const bf16* __restrict__ kh, const bf16* __restrict__ kl,
        float* __restrict__ diag)
{
    const int w = threadIdx.x >> 5, lane = threadIdx.x & 31;
    const size_t r = (size_t)blockIdx.x * 8 + w;
    const uint2* ph = (const uint2*)(kh + r * DDIM + lane * 8);
    const uint2* pl = (const uint2*)(kl + r * DDIM + lane * 8);
    uint2 h0 = ph[0], h1 = ph[1], l0 = pl[0], l1 = pl[1];
    float s = sq2(h0.x, l0.x) + sq2(h0.y, l0.y) + sq2(h1.x, l1.x) + sq2(h1.y, l1.y);
#pragma unroll
    for (int o = 16; o > 0; o >>= 1) s += __shfl_xor_sync(0xffffffffu, s, o);
    if (lane == 0) diag[r] = 0.5f * DNORM2 * s;
}

// q feature map + d_inv fused; float4 / packed stores
__global__ void __launch_bounds__(256)
qexp2_k(const float* __restrict__ qp, const bf16* __restrict__ qh,
        const bf16* __restrict__ ql, const unsigned* __restrict__ rowmaxu,
        const float* __restrict__ ksum, bf16* __restrict__ oh,
        bf16* __restrict__ ol, float* __restrict__ dinv)
{
    const size_t r = blockIdx.x;
    const int b = (int)(r >> 10);
    const float* prow = qp + r * NBP;
    const float* ks = ksum + (size_t)b * NBP;
    const int tid = threadIdx.x;
    __shared__ float red[256];

    float x = __bfloat162float(qh[r * DDIM + tid]) + __bfloat162float(ql[r * DDIM + tid]);
    red[tid] = x * x;
    __syncthreads();
    for (int s = 128; s > 0; s >>= 1) {
        if (tid < s) red[tid] += red[tid + s];
        __syncthreads();
    }
    const float c = 0.5f * DNORM2 * red[0] + decf(rowmaxu[r]);
    __syncthreads();

    float dot = 0.f;
    for (int j = tid * 4; j < NBP; j += 1024) {
        float4 p = *(const float4*)(prow + j);
        float v0 = (j + 0 < NBF) ? RATIO * (expf(p.x - c) + EPSF) : 0.f;
        float v1 = (j + 1 < NBF) ? RATIO * (expf(p.y - c) + EPSF) : 0.f;
        float v2 = (j + 2 < NBF) ? RATIO * (expf(p.z - c) + EPSF) : 0.f;
        float v3 = (j + 3 < NBF) ? RATIO * (expf(p.w - c) + EPSF) : 0.f;
        uint32_t ph0, pl0, ph1, pl1;
        split2p(v0, v1, ph0, pl0);
        split2p(v2, v3, ph1, pl1);
        *(uint2*)(oh + r * NBP + j) = make_uint2(ph0, ph1);
        *(uint2*)(ol + r * NBP + j) = make_uint2(pl0, pl1);
        float4 kv = *(const float4*)(ks + j);
        dot += v0 * kv.x + v1 * kv.y + v2 * kv.z + v3 * kv.w;
    }
    red[tid] = dot;
    __syncthreads();
    for (int s = 128; s > 0; s >>= 1) {
        if (tid < s) red[tid] += red[tid + s];
        __syncthreads();
    }
    if (tid == 0) dinv[r] = 1.0f / red[0];
}

// transpose + exp for K: 32 m x 128 n tiles -> kpT hi/lo [b][m][n] + ksum partials
__global__ void __launch_bounds__(256)
ktexp_k(const float* __restrict__ kp, const float* __restrict__ diag,
        const unsigned* __restrict__ kmaxu, bf16* __restrict__ th,
        bf16* __restrict__ tl, float* __restrict__ part)
{
    __shared__ float sm[128][33];
    const int b = blockIdx.z;
    const int m0 = blockIdx.x * 32, n0 = blockIdx.y * 128;
    const int tid = threadIdx.x;
    const float km = decf(kmaxu[b]);

    {
        const int n = tid >> 1, half = tid & 1;
        const float dk = diag[(size_t)b * NPT + n0 + n];
        const float* src = kp + ((size_t)b * NPT + n0 + n) * NBP + m0 + half * 16;
#pragma unroll
        for (int c4 = 0; c4 < 4; c4++) {
            float4 xx = *(const float4*)(src + c4 * 4);
            const int mb = m0 + half * 16 + c4 * 4;
            float vv[4] = {xx.x, xx.y, xx.z, xx.w};
#pragma unroll
            for (int e = 0; e < 4; e++)
                sm[n][half * 16 + c4 * 4 + e] =
                    (mb + e < NBF) ? RATIO * (expf(vv[e] - dk - km) + EPSF) : 0.f;
        }
    }
    __syncthreads();
    {
        const int m = tid >> 3, nq = tid & 7;
        const size_t obase = ((size_t)b * NBP + m0 + m) * NPT + n0;
        float s = 0.f;
#pragma unroll
        for (int i = 0; i < 8; i++) {
            const int np = nq * 8 + ((i + nq) & 7);   // bank-stagger
            float v0 = sm[2 * np][m], v1 = sm[2 * np + 1][m];
            s += v0 + v1;
            uint32_t ph, pl;
            split2p(v0, v1, ph, pl);
            *(uint32_t*)&th[obase + 2 * np] = ph;
            *(uint32_t*)&tl[obase + 2 * np] = pl;
        }
        s += __shfl_xor_sync(0xffffffffu, s, 1);
        s += __shfl_xor_sync(0xffffffffu, s, 2);
        s += __shfl_xor_sync(0xffffffffu, s, 4);
        if (nq == 0)
            part[((size_t)b * 8 + blockIdx.y) * NBP + m0 + m] = s;
    }
}

__global__ void ksum2_k(const float* __restrict__ part, float* __restrict__ ksum)
{
    const int b = blockIdx.y;
    const int m = blockIdx.x * blockDim.x + threadIdx.x;
    if (m >= NBP) return;
    float s = 0.f;
#pragma unroll
    for (int j = 0; j < 8; j++)
        s += part[((size_t)b * 8 + j) * NBP + m];
    ksum[(size_t)b * NBP + m] = s;
}

// ---------------------------------------------------------------------------
// Launch
// ---------------------------------------------------------------------------
#define GETP(var, sym) cudaGetSymbolAddress((void**)&var, sym)

extern "C" void kernel_launch(void* const* d_in, const int* in_sizes, int n_in,
                              void* d_out, int out_size)
{
    const float* q     = (const float*)d_in[0];
    const float* k     = (const float*)d_in[1];
    const float* v     = (const float*)d_in[2];
    const float* Wq    = (const float*)d_in[3];
    const float* bq    = (const float*)d_in[4];
    const float* Wk    = (const float*)d_in[5];
    const float* bk    = (const float*)d_in[6];
    const float* Wv    = (const float*)d_in[7];
    const float* bv    = (const float*)d_in[8];
    const float* W_out = (const float*)d_in[9];
    const float* b_out = (const float*)d_in[10];
    const float* proj  = (const float*)d_in[11];
    float* out = (float*)d_out;

    float *qp, *kp, *diagk, *ksum, *kpart, *dinv;
    unsigned *kmaxu, *rowmaxu;
    bf16 *qin_h, *qin_l, *kin_h, *kin_l, *vin_h, *vin_l;
    bf16 *wtq_h, *wtq_l, *wtk_h, *wtk_l, *wtv_h, *wtv_l;
    bf16 *pr_h, *pr_l, *wo_h, *wo_l;
    bf16 *qall_h, *qall_l, *kall_h, *kall_l, *vall_h, *vall_l, *vt_h, *vt_l;
    bf16 *qph, *qpl, *kpT_h, *kpT_l, *ctxT_h, *ctxT_l, *outs_h, *outs_l;

    GETP(qp, g_qp); GETP(kp, g_kp);
    GETP(qin_h, g_qin_h); GETP(qin_l, g_qin_l);
    GETP(kin_h, g_kin_h); GETP(kin_l, g_kin_l);
    GETP(vin_h, g_vin_h); GETP(vin_l, g_vin_l);
    GETP(wtq_h, g_wtq_h); GETP(wtq_l, g_wtq_l);
    GETP(wtk_h, g_wtk_h); GETP(wtk_l, g_wtk_l);
    GETP(wtv_h, g_wtv_h); GETP(wtv_l, g_wtv_l);
    GETP(pr_h, g_pr_h);   GETP(pr_l, g_pr_l);
    GETP(wo_h, g_wo_h);   GETP(wo_l, g_wo_l);
    GETP(qall_h, g_qall_h); GETP(qall_l, g_qall_l);
    GETP(kall_h, g_kall_h); GETP(kall_l, g_kall_l);
    GETP(vall_h, g_vall_h); GETP(vall_l, g_vall_l);
    GETP(vt_h, g_vt_h);     GETP(vt_l, g_vt_l);
    GETP(qph, g_qph);       GETP(qpl, g_qpl);
    GETP(kpT_h, g_kpT_h);   GETP(kpT_l, g_kpT_l);
    GETP(ctxT_h, g_ctxT_h); GETP(ctxT_l, g_ctxT_l);
    GETP(outs_h, g_outs_h); GETP(outs_l, g_outs_l);
    GETP(diagk, g_diagk); GETP(ksum, g_ksum); GETP(kpart, g_kpart);
    GETP(dinv, g_dinv); GETP(kmaxu, g_kmaxu); GETP(rowmaxu, g_rowmaxu);

    cudaFuncSetAttribute(gemm6<1>, cudaFuncAttributeMaxDynamicSharedMemorySize, G6SMEM);
    cudaFuncSetAttribute(gemm6<2>, cudaFuncAttributeMaxDynamicSharedMemorySize, G6SMEM);
    cudaFuncSetAttribute(gemm6<3>, cudaFuncAttributeMaxDynamicSharedMemorySize, G6SMEM);
    cudaFuncSetAttribute(gemm6<4>, cudaFuncAttributeMaxDynamicSharedMemorySize, G6SMEM);
    cudaFuncSetAttribute(gemm6<5>, cudaFuncAttributeMaxDynamicSharedMemorySize, G6SMEM);
    cudaFuncSetAttribute(gemm6<6>, cudaFuncAttributeMaxDynamicSharedMemorySize, G6SMEM);

    // ---- 0) reset atomic-max buffers (graph replays!) + operand splits
    reset_k<<<(ROWS + 255) / 256, 256>>>(kmaxu, rowmaxu);
    {
        const size_t nin = (size_t)TT * NPT * DDIM;
        split_k<<<(unsigned)((nin / 4 + 255) / 256), 256>>>(q, qin_h, qin_l, nin, 1.f);
        split_k<<<(unsigned)((nin / 4 + 255) / 256), 256>>>(k, kin_h, kin_l, nin, 1.f);
        split_k<<<(unsigned)((nin / 4 + 255) / 256), 256>>>(v, vin_h, vin_l, nin, 1.f);
        dim3 tg(8, 8, 8), tb(32, 8);
        tsplit_k<<<tg, tb>>>(Wq, wtq_h, wtq_l, DDIM, DDIM);
        tsplit_k<<<tg, tb>>>(Wk, wtk_h, wtk_l, DDIM, DDIM);
        tsplit_k<<<tg, tb>>>(Wv, wtv_h, wtv_l, DDIM, DDIM);
        const size_t npr = (size_t)NBF * DDIM;
        split_k<<<(unsigned)((npr / 4 + 255) / 256), 256>>>(proj, pr_h, pr_l, npr, DNORM);
        wsplit_k<<<(DDIM * HDCAT + 255) / 256, 256>>>(W_out, wo_h, wo_l);
    }

    // ---- 1) per-head projections (batched over (t,h): Hdiv = HH)
    {
        dim3 grid(2, 8, BATCH);
        gemm6<3><<<grid, 512, G6SMEM>>>(qin_h, qin_l, wtq_h, wtq_l,
            nullptr, qall_h, qall_l,
            NPT, DDIM, DDIM, DDIM, DDIM, DDIM,
            (long)NPT * DDIM, 0, 0, (long)DDIM * DDIM,
            (long)HH * NPT * DDIM, (long)NPT * DDIM, HH,
            bq, DDIM, nullptr, 0, 0, nullptr, 0);
        gemm6<3><<<grid, 512, G6SMEM>>>(kin_h, kin_l, wtk_h, wtk_l,
            nullptr, kall_h, kall_l,
            NPT, DDIM, DDIM, DDIM, DDIM, DDIM,
            (long)NPT * DDIM, 0, 0, (long)DDIM * DDIM,
            (long)HH * NPT * DDIM, (long)NPT * DDIM, HH,
            bk, DDIM, nullptr, 0, 0, nullptr, 0);
        gemm6<3><<<grid, 512, G6SMEM>>>(vin_h, vin_l, wtv_h, wtv_l,
            nullptr, vall_h, vall_l,
            NPT, DDIM, DDIM, DDIM, DDIM, DDIM,
            (long)NPT * DDIM, 0, 0, (long)DDIM * DDIM,
            (long)HH * NPT * DDIM, (long)NPT * DDIM, HH,
            bv, DDIM, nullptr, 0, 0, nullptr, 0);
    }

    // ---- 2) dash GEMMs (batched per-slab: Hdiv = 1 !) + fused max reductions
    {
        dim3 grid(12, 8, BATCH);
        gemm6<6><<<grid, 512, G6SMEM>>>(qall_h, qall_l, pr_h, pr_l,
            qp, nullptr, nullptr,
            NPT, NBP, DDIM, DDIM, DDIM, NBP,
            (long)NPT * DDIM, 0, 0, 0, (long)NPT * NBP, 0, 1,
            nullptr, 0, nullptr, 0, 0, rowmaxu, NBF);
        gemm6<5><<<grid, 512, G6SMEM>>>(kall_h, kall_l, pr_h, pr_l,
            kp, nullptr, nullptr,
            NPT, NBP, DDIM, DDIM, DDIM, NBP,
            (long)NPT * DDIM, 0, 0, 0, (long)NPT * NBP, 0, 1,
            nullptr, 0, nullptr, 0, 0, kmaxu, NBF);
    }

    // ---- 3) k-side feature map chain, then fused q-exp + d_inv
    kdiag_k<<<ROWS / 8, 256>>>(kall_h, kall_l, diagk);
    ktexp_k<<<dim3(45, 8, BATCH), 256>>>(kp, diagk, kmaxu, kpT_h, kpT_l, kpart);
    ksum2_k<<<dim3(6, BATCH), 256>>>(kpart, ksum);
    qexp2_k<<<ROWS, 256>>>(qp, qall_h, qall_l, rowmaxu, ksum, qph, qpl, dinv);

    // ---- 4) vallT
    {
        dim3 tg(DDIM / 64, NPT / 64, BATCH);
        tbf_k<<<tg, 256>>>(vall_h, vt_h, NPT, DDIM);
        tbf_k<<<tg, 256>>>(vall_l, vt_l, NPT, DDIM);
    }

    // ---- 5) ctxT[b][e][m] = vallT[b] * kpT[b]^T (per-slab: Hdiv = 1 !)
    {
        dim3 grid(12, 2, BATCH);
        gemm6<4><<<grid, 512, G6SMEM>>>(vt_h, vt_l, kpT_h, kpT_l,
            nullptr, ctxT_h, ctxT_l,
            DDIM, NBP, NPT, NPT, NPT, NBP,
            (long)DDIM * NPT, 0, (long)NBP * NPT, 0, (long)DDIM * NBP, 0, 1,
            nullptr, 0, nullptr, 0, 0, nullptr, 0);
    }

    // ---- 6) out: [t][n][h*256+e] contiguous bf16-pair store, *dinv (Hdiv = HH)
    {
        dim3 grid(2, 8, BATCH);
        gemm6<2><<<grid, 512, G6SMEM>>>(qph, qpl, ctxT_h, ctxT_l,
            nullptr, outs_h, outs_l,
            NPT, DDIM, NBP, NBP, NBP, HDCAT,
            (long)HH * NPT * NBP, (long)NPT * NBP,
            (long)HH * DDIM * NBP, (long)DDIM * NBP,
            (long)NPT * HDCAT, (long)DDIM, HH,
            nullptr, 0, dinv, (long)HH * NPT, (long)NPT, nullptr, 0);
    }

    // ---- 7) final: rep[8192][256] = outs * wr^T + b_out (wr = permuted W_out)
    {
        dim3 grid(2, 64, 1);
        gemm6<1><<<grid, 512, G6SMEM>>>(outs_h, outs_l, wo_h, wo_l,
            out, nullptr, nullptr,
            TT * NPT, DDIM, HDCAT, HDCAT, HDCAT, DDIM,
            0, 0, 0, 0, 0, 0, 1,
            b_out, 0, nullptr, 0, 0, nullptr, 0);
    }
}

// round 11
// speedup vs baseline: 3.6923x; 1.1325x over previous
#include <cuda_runtime.h>
#include <cuda_bf16.h>
#include <cstdint>
#include <math.h>

// ---------------------------------------------------------------------------
// Problem constants (T=8, N=M=1024, H=8, D=256, NB = int(256*ln 256) = 1419)
// ---------------------------------------------------------------------------
#define TT   8
#define NPT  1024
#define HH   8
#define DDIM 256
#define NBF  1419
#define NBP  1472              // padded to multiple of 64 (N-tile) and 32 (K)
#define ROWS (TT * HH * NPT)   // 65536
#define BATCH (TT * HH)        // 64
#define HDCAT (HH * DDIM)      // 2048

#define DNORM   0.25f          // 256^-0.25
#define DNORM2  0.0625f
#define EPSF    1e-4f
#define RATIO   0.026547529f   // 1/sqrt(1419)

typedef __nv_bfloat16 bf16;

// ---------------------------------------------------------------------------
// Scratch (device globals; zero-init at load -> never-written pads stay 0)
// ---------------------------------------------------------------------------
__device__ float g_qp[(size_t)ROWS * NBP];
__device__ float g_kp[(size_t)ROWS * NBP];
__device__ bf16 g_qin_h[(size_t)TT * NPT * DDIM],  g_qin_l[(size_t)TT * NPT * DDIM];
__device__ bf16 g_kin_h[(size_t)TT * NPT * DDIM],  g_kin_l[(size_t)TT * NPT * DDIM];
__device__ bf16 g_vin_h[(size_t)TT * NPT * DDIM],  g_vin_l[(size_t)TT * NPT * DDIM];
__device__ bf16 g_wtq_h[(size_t)HH * DDIM * DDIM], g_wtq_l[(size_t)HH * DDIM * DDIM];
__device__ bf16 g_wtk_h[(size_t)HH * DDIM * DDIM], g_wtk_l[(size_t)HH * DDIM * DDIM];
__device__ bf16 g_wtv_h[(size_t)HH * DDIM * DDIM], g_wtv_l[(size_t)HH * DDIM * DDIM];
__device__ bf16 g_pr_h[(size_t)NBP * DDIM],        g_pr_l[(size_t)NBP * DDIM];
__device__ bf16 g_wo_h[(size_t)DDIM * HDCAT],      g_wo_l[(size_t)DDIM * HDCAT];
__device__ bf16 g_qall_h[(size_t)ROWS * DDIM],     g_qall_l[(size_t)ROWS * DDIM];
__device__ bf16 g_kall_h[(size_t)ROWS * DDIM],     g_kall_l[(size_t)ROWS * DDIM];
__device__ bf16 g_vall_h[(size_t)ROWS * DDIM],     g_vall_l[(size_t)ROWS * DDIM];
__device__ bf16 g_vt_h[(size_t)ROWS * DDIM],       g_vt_l[(size_t)ROWS * DDIM];
__device__ bf16 g_qph[(size_t)ROWS * NBP],         g_qpl[(size_t)ROWS * NBP];
__device__ bf16 g_kpT_h[(size_t)BATCH * NBP * NPT], g_kpT_l[(size_t)BATCH * NBP * NPT];
__device__ bf16 g_ctxT_h[(size_t)BATCH * DDIM * NBP], g_ctxT_l[(size_t)BATCH * DDIM * NBP];
__device__ bf16 g_outs_h[(size_t)TT * NPT * HDCAT], g_outs_l[(size_t)TT * NPT * HDCAT];
__device__ float g_diagk[(size_t)ROWS];
__device__ float g_ksum[(size_t)BATCH * NBP];
__device__ float g_kpart[(size_t)BATCH * 8 * NBP];
__device__ float g_dinv[(size_t)ROWS];
__device__ unsigned g_kmaxu[(size_t)BATCH];
__device__ unsigned g_rowmaxu[(size_t)ROWS];

// ---------------------------------------------------------------------------
// helpers
// ---------------------------------------------------------------------------
__device__ __forceinline__ uint32_t smem_u32(const void* p) {
    uint32_t a;
    asm("{ .reg .u64 t; cvta.to.shared.u64 t, %1; cvt.u32.u64 %0, t; }"
        : "=r"(a) : "l"(p));
    return a;
}

__device__ __forceinline__ void ldm4(uint32_t& r0, uint32_t& r1,
                                     uint32_t& r2, uint32_t& r3, uint32_t a) {
    asm volatile("ldmatrix.sync.aligned.m8n8.x4.shared.b16 {%0,%1,%2,%3}, [%4];"
                 : "=r"(r0), "=r"(r1), "=r"(r2), "=r"(r3) : "r"(a));
}

__device__ __forceinline__ void mma16816(float* c, uint32_t a0, uint32_t a1,
                                         uint32_t a2, uint32_t a3,
                                         uint32_t b0, uint32_t b1) {
    asm volatile(
        "mma.sync.aligned.m16n8k16.row.col.f32.bf16.bf16.f32 "
        "{%0,%1,%2,%3},{%4,%5,%6,%7},{%8,%9},{%0,%1,%2,%3};"
        : "+f"(c[0]), "+f"(c[1]), "+f"(c[2]), "+f"(c[3])
        : "r"(a0), "r"(a1), "r"(a2), "r"(a3), "r"(b0), "r"(b1));
}

__device__ __forceinline__ void cpasync16(uint32_t dst, const bf16* src, int sz) {
    asm volatile("cp.async.cg.shared.global [%0], [%1], 16, %2;"
                 :: "r"(dst), "l"(__cvta_generic_to_global(src)), "r"(sz));
}

__device__ __forceinline__ void splitw(float x, bf16& h, bf16& l) {
    h = __float2bfloat16_rn(x);
    l = __float2bfloat16_rn(x - __bfloat162float(h));
}

__device__ __forceinline__ uint32_t packbf(bf16 a, bf16 b) {
    return (uint32_t)__bfloat16_as_ushort(a)
         | ((uint32_t)__bfloat16_as_ushort(b) << 16);
}

// split two floats -> packed hi word, packed lo word
__device__ __forceinline__ void split2p(float x, float y,
                                        uint32_t& ph, uint32_t& pl) {
    bf16 hx, lx, hy, ly;
    splitw(x, hx, lx); splitw(y, hy, ly);
    ph = packbf(hx, hy); pl = packbf(lx, ly);
}

// sum of (hi+lo)^2 over a packed pair
__device__ __forceinline__ float sq2(uint32_t hw, uint32_t lw) {
    float x0 = __bfloat162float(__ushort_as_bfloat16((unsigned short)(hw & 0xffff)))
             + __bfloat162float(__ushort_as_bfloat16((unsigned short)(lw & 0xffff)));
    float x1 = __bfloat162float(__ushort_as_bfloat16((unsigned short)(hw >> 16)))
             + __bfloat162float(__ushort_as_bfloat16((unsigned short)(lw >> 16)));
    return x0 * x0 + x1 * x1;
}

// monotonic float <-> unsigned encoding (total order; exact; order-independent max)
__device__ __forceinline__ unsigned encf(float f) {
    unsigned u = __float_as_uint(f);
    return (u & 0x80000000u) ? ~u : (u | 0x80000000u);
}
__device__ __forceinline__ float decf(unsigned u) {
    unsigned b = (u & 0x80000000u) ? (u ^ 0x80000000u) : ~u;
    return __uint_as_float(b);
}

// ---------------------------------------------------------------------------
// gemm7: NT bf16x3 mma.sync GEMM, 256 threads, 8 warps (4m x 2n), 32x32/warp,
//        CTA tile 128x64, 2-stage cp.async double buffer, 3 CTAs/SM.
//   C[M,N] = A[M,K] * B[N,K]^T ; operands hi/lo bf16, k-contiguous.
//   EPI: 1 +bias f32 | 2 *scale[row] bf16 pair | 3 +bias bf16 pair
//        4 plain bf16 pair | 5 f32 + slab-max atomic | 6 f32 + row-max atomic
//   K % 32 == 0, N even, lda == ldb == K.
// SMEM stage layout (bytes): Ah[0,10240) Al[10240,20480) Bh[20480,25600)
//                            Bl[25600,30720); 2 stages -> 61440 B.
// ---------------------------------------------------------------------------
#define TSTRIDE 40
#define AT_B 10240                   // 128*40*2
#define BT_B 5120                    // 64*40*2
#define STAGE_B 30720                // 2*AT_B + 2*BT_B
#define G7SMEM  (2 * STAGE_B)        // 61440

template<int EPI>
__global__ void __launch_bounds__(256, 3)
gemm7(const bf16* __restrict__ Ahi, const bf16* __restrict__ Alo,
      const bf16* __restrict__ Bhi, const bf16* __restrict__ Blo,
      float* __restrict__ Cf, bf16* __restrict__ Chi, bf16* __restrict__ Clo,
      int M, int N, int K, int lda, int ldb, int ldc,
      long aT, long aH, long bT, long bH, long cT, long cH, int Hdiv,
      const float* __restrict__ bias, long biasH,
      const float* __restrict__ scale, long scT, long scH,
      unsigned* __restrict__ maxu, int vlim)
{
    extern __shared__ bf16 smb[];
    const uint32_t sb = smem_u32(smb);
    const int tid = threadIdx.x;
    const int wid = tid >> 5, lane = tid & 31;
    const int warp_m = wid >> 1, warp_n = wid & 1;   // 4 x 2 warp grid
    const int g = lane >> 2, tg = lane & 3;

    const int bz = blockIdx.z;
    const int t = bz / Hdiv, h = bz % Hdiv;
    const long aoff = (long)t * aT + (long)h * aH;
    const long boff = (long)t * bT + (long)h * bH;
    const long coff = (long)t * cT + (long)h * cH;
    const float* biasp  = (EPI == 1 || EPI == 3) ? bias + (long)h * biasH : nullptr;
    const float* scalep = (EPI == 2) ? scale + (long)t * scT + (long)h * scH : nullptr;

    const int m0 = blockIdx.y * 128;
    const int n0 = blockIdx.x * 64;

    const bf16* srcAh = Ahi + aoff;
    const bf16* srcAl = Alo + aoff;
    const bf16* srcBh = Bhi + boff;
    const bf16* srcBl = Blo + boff;

    const int S = K >> 5;

    auto stage = [&](int s, int bi) {
        const int k0 = s << 5;
        const uint32_t base = sb + (uint32_t)bi * STAGE_B;
        // A: 128 rows x 4 chunks, 2 chunks per thread, hi + lo
#pragma unroll
        for (int c = 0; c < 2; c++) {
            const int id = tid + c * 256;
            const int r = id >> 2, q = id & 3;
            const int gr = m0 + r;
            const int sz = (gr < M) ? 16 : 0;
            const long so = (long)(sz ? gr : m0) * lda + k0 + q * 8;
            const uint32_t d = base + (uint32_t)(r * TSTRIDE + q * 8) * 2;
            cpasync16(d, srcAh + so, sz);
            cpasync16(d + AT_B, srcAl + so, sz);
        }
        // B: 64 rows x 4 chunks, 1 chunk per thread, hi + lo
        {
            const int r = tid >> 2, q = tid & 3;
            const int gr = n0 + r;
            const int sz = (gr < N) ? 16 : 0;
            const long so = (long)(sz ? gr : n0) * ldb + k0 + q * 8;
            const uint32_t d = base + (uint32_t)(2 * AT_B)
                             + (uint32_t)(r * TSTRIDE + q * 8) * 2;
            cpasync16(d, srcBh + so, sz);
            cpasync16(d + BT_B, srcBl + so, sz);
        }
        asm volatile("cp.async.commit_group;" ::: "memory");
    };

    float acc[2][4][4];
#pragma unroll
    for (int i = 0; i < 2; i++)
#pragma unroll
        for (int j = 0; j < 4; j++)
#pragma unroll
            for (int e = 0; e < 4; e++) acc[i][j][e] = 0.f;

    stage(0, 0);
    if (S > 1) stage(1, 1);

    for (int s = 0; s < S; s++) {
        if (s + 1 < S) asm volatile("cp.async.wait_group 1;" ::: "memory");
        else           asm volatile("cp.async.wait_group 0;" ::: "memory");
        __syncthreads();

        const uint32_t base = sb + (uint32_t)(s & 1) * STAGE_B;
#pragma unroll
        for (int ks = 0; ks < 2; ks++) {
            const int ko = ks << 4;
            uint32_t bh[4][2], bl[4][2];
#pragma unroll
            for (int p = 0; p < 2; p++) {
                const int nrow = warp_n * 32 + p * 16 + ((lane >> 4) << 3) + (lane & 7);
                const int kcol = ko + ((lane >> 3) & 1) * 8;
                const uint32_t ab = base + (uint32_t)(2 * AT_B)
                                  + (uint32_t)(nrow * TSTRIDE + kcol) * 2;
                ldm4(bh[2 * p][0], bh[2 * p][1], bh[2 * p + 1][0], bh[2 * p + 1][1], ab);
                ldm4(bl[2 * p][0], bl[2 * p][1], bl[2 * p + 1][0], bl[2 * p + 1][1],
                     ab + BT_B);
            }
#pragma unroll
            for (int ma = 0; ma < 2; ma++) {
                const int mrow = warp_m * 32 + ma * 16 + ((lane >> 3) & 1) * 8 + (lane & 7);
                const int kcol = ko + (lane >> 4) * 8;
                const uint32_t aa = base + (uint32_t)(mrow * TSTRIDE + kcol) * 2;
                uint32_t ah0, ah1, ah2, ah3, al0, al1, al2, al3;
                ldm4(ah0, ah1, ah2, ah3, aa);
                ldm4(al0, al1, al2, al3, aa + AT_B);
#pragma unroll
                for (int nb = 0; nb < 4; nb++) {
                    mma16816(acc[ma][nb], ah0, ah1, ah2, ah3, bh[nb][0], bh[nb][1]);
                    mma16816(acc[ma][nb], ah0, ah1, ah2, ah3, bl[nb][0], bl[nb][1]);
                    mma16816(acc[ma][nb], al0, al1, al2, al3, bh[nb][0], bh[nb][1]);
                }
            }
        }
        __syncthreads();
        if (s + 2 < S) stage(s + 2, s & 1);
    }

    // ---- epilogue (N even; col and col+1 always in-bounds together)
    float slabmax = -3.4e38f;
#pragma unroll
    for (int ma = 0; ma < 2; ma++) {
#pragma unroll
        for (int hf = 0; hf < 2; hf++) {
            const int row = m0 + warp_m * 32 + ma * 16 + g + hf * 8;
            float rowmax = -3.4e38f;
            const bool rok = row < M;
            const float sc = (EPI == 2 && rok) ? scalep[row] : 1.f;
#pragma unroll
            for (int nb = 0; nb < 4; nb++) {
                const int col = n0 + warp_n * 32 + nb * 8 + 2 * tg;
                if (!rok || col >= N) continue;
                float v0 = acc[ma][nb][hf * 2 + 0];
                float v1 = acc[ma][nb][hf * 2 + 1];
                if (EPI == 1 || EPI == 3) { v0 += biasp[col]; v1 += biasp[col + 1]; }
                if (EPI == 2) { v0 *= sc; v1 *= sc; }
                const long idx = coff + (long)row * ldc + col;
                if (EPI == 1 || EPI == 5 || EPI == 6) {
                    *(float2*)&Cf[idx] = make_float2(v0, v1);
                    if (EPI == 5 || EPI == 6) {
                        if (col < vlim) {
                            if (EPI == 5) slabmax = fmaxf(slabmax, v0);
                            else          rowmax  = fmaxf(rowmax, v0);
                        }
                        if (col + 1 < vlim) {
                            if (EPI == 5) slabmax = fmaxf(slabmax, v1);
                            else          rowmax  = fmaxf(rowmax, v1);
                        }
                    }
                } else {
                    uint32_t ph, pl;
                    split2p(v0, v1, ph, pl);
                    *(uint32_t*)&Chi[idx] = ph;
                    *(uint32_t*)&Clo[idx] = pl;
                }
            }
            if (EPI == 6) {
                rowmax = fmaxf(rowmax, __shfl_xor_sync(0xffffffffu, rowmax, 1));
                rowmax = fmaxf(rowmax, __shfl_xor_sync(0xffffffffu, rowmax, 2));
                if (tg == 0 && rok)
                    atomicMax(&maxu[(long)bz * M + row], encf(rowmax));
            }
        }
    }
    if (EPI == 5) {
#pragma unroll
        for (int o = 16; o > 0; o >>= 1)
            slabmax = fmaxf(slabmax, __shfl_xor_sync(0xffffffffu, slabmax, o));
        if (lane == 0) atomicMax(&maxu[bz], encf(slabmax));
    }
}

// ---------------------------------------------------------------------------
// conversion / transpose / reset passes
// ---------------------------------------------------------------------------
__global__ void reset_k(unsigned* __restrict__ kmaxu, unsigned* __restrict__ rowmaxu)
{
    int i = blockIdx.x * blockDim.x + threadIdx.x;
    if (i < BATCH) kmaxu[i] = 0u;
    if (i < ROWS) rowmaxu[i] = 0u;
}

// vectorized split: 4 elems/thread (n % 4 == 0)
__global__ void split_k(const float* __restrict__ s, bf16* __restrict__ h,
                        bf16* __restrict__ l, size_t n, float scl)
{
    size_t i4 = ((size_t)blockIdx.x * blockDim.x + threadIdx.x) * 4;
    if (i4 < n) {
        float4 x = *(const float4*)(s + i4);
        uint32_t ph0, pl0, ph1, pl1;
        split2p(x.x * scl, x.y * scl, ph0, pl0);
        split2p(x.z * scl, x.w * scl, ph1, pl1);
        *(uint2*)(h + i4) = make_uint2(ph0, ph1);
        *(uint2*)(l + i4) = make_uint2(pl0, pl1);
    }
}

// proj split with NBP row padding: dst rows [0,NBF) from src, rest stay zero
__global__ void prsplit_k(const float* __restrict__ s, bf16* __restrict__ h,
                          bf16* __restrict__ l)
{
    size_t i4 = ((size_t)blockIdx.x * blockDim.x + threadIdx.x) * 4;
    if (i4 < (size_t)NBF * DDIM) {
        float4 x = *(const float4*)(s + i4);
        uint32_t ph0, pl0, ph1, pl1;
        split2p(x.x * DNORM, x.y * DNORM, ph0, pl0);
        split2p(x.z * DNORM, x.w * DNORM, ph1, pl1);
        *(uint2*)(h + i4) = make_uint2(ph0, ph1);
        *(uint2*)(l + i4) = make_uint2(pl0, pl1);
    }
}

// W_out permuted split: wr[d][h*256+e] = W_out[d][e*8+h]
__global__ void wsplit_k(const float* __restrict__ W, bf16* __restrict__ h,
                         bf16* __restrict__ l)
{
    int i = blockIdx.x * blockDim.x + threadIdx.x;
    if (i < DDIM * HDCAT) {
        int d = i / HDCAT, fp = i % HDCAT;
        int hh = fp >> 8, e = fp & 255;
        float x = W[(size_t)d * HDCAT + e * 8 + hh];
        bf16 hb, lb; splitw(x, hb, lb);
        h[i] = hb; l[i] = lb;
    }
}

// fp32 [z][R][C] -> bf16 hi/lo [z][C][R] (weights, small)
__global__ void tsplit_k(const float* __restrict__ src, bf16* __restrict__ hi,
                         bf16* __restrict__ lo, int R, int C)
{
    __shared__ float sm[32][33];
    const int z = blockIdx.z;
    const int c0 = blockIdx.x * 32, r0 = blockIdx.y * 32;
    const float* s = src + (size_t)z * R * C;
    bf16* ho = hi + (size_t)z * R * C;
    bf16* lv = lo + (size_t)z * R * C;
    const int tx = threadIdx.x, ty = threadIdx.y;
    for (int i = ty; i < 32; i += 8)
        sm[i][tx] = s[(size_t)(r0 + i) * C + c0 + tx];
    __syncthreads();
    for (int i = ty; i < 32; i += 8) {
        float x = sm[tx][i];
        bf16 hb, lb; splitw(x, hb, lb);
        ho[(size_t)(c0 + i) * R + r0 + tx] = hb;
        lv[(size_t)(c0 + i) * R + r0 + tx] = lb;
    }
}

// bf16 [z][R][C] -> [z][C][R], 64x64 tiles, vectorized (R,C % 64 == 0)
__global__ void __launch_bounds__(256)
tbf_k(const bf16* __restrict__ src, bf16* __restrict__ dst, int R, int C)
{
    __shared__ bf16 sm[64][72];
    const int z = blockIdx.z;
    const int c0 = blockIdx.x * 64, r0 = blockIdx.y * 64;
    const bf16* s = src + (size_t)z * R * C;
    bf16* d = dst + (size_t)z * R * C;
    const int tid = threadIdx.x;
    {
        const int r = tid >> 2, cq = tid & 3;
        const uint4* sp = (const uint4*)(s + (size_t)(r0 + r) * C + c0 + cq * 16);
        *(uint4*)&sm[r][cq * 16]     = sp[0];
        *(uint4*)&sm[r][cq * 16 + 8] = sp[1];
    }
    __syncthreads();
    {
        const int c = tid >> 2, rq = tid & 3;
#pragma unroll
        for (int i = 0; i < 8; i++) {
            const int rp = rq * 8 + i;
            uint32_t w = packbf(sm[2 * rp][c], sm[2 * rp + 1][c]);
            *(uint32_t*)&d[(size_t)(c0 + c) * R + r0 + 2 * rp] = w;
        }
    }
}

// ---------------------------------------------------------------------------
// feature-map / reduction kernels
// ---------------------------------------------------------------------------
// diag_k[r] = 0.5*dn2*sum(k^2); warp per row, uint4 loads
__global__ void __launch_bounds__(256)
kdiag_k(const bf16* __restrict__ kh, const bf16* __restrict__ kl,
        float* __restrict__ diag)
{
    const int w = threadIdx.x >> 5, lane = threadIdx.x & 31;
    const size_t r = (size_t)blockIdx.x * 8 + w;
    const uint2* ph = (const uint2*)(kh + r * DDIM + lane * 8);
    const uint2* pl = (const uint2*)(kl + r * DDIM + lane * 8);
    uint2 h0 = ph[0], h1 = ph[1], l0 = pl[0], l1 = pl[1];
    float s = sq2(h0.x, l0.x) + sq2(h0.y, l0.y) + sq2(h1.x, l1.x) + sq2(h1.y, l1.y);
#pragma unroll
    for (int o = 16; o > 0; o >>= 1) s += __shfl_xor_sync(0xffffffffu, s, o);
    if (lane == 0) diag[r] = 0.5f * DNORM2 * s;
}

// q feature map + d_inv fused; float4 / packed stores
__global__ void __launch_bounds__(256)
qexp2_k(const float* __restrict__ qp, const bf16* __restrict__ qh,
        const bf16* __restrict__ ql, const unsigned* __restrict__ rowmaxu,
        const float* __restrict__ ksum, bf16* __restrict__ oh,
        bf16* __restrict__ ol, float* __restrict__ dinv)
{
    const size_t r = blockIdx.x;
    const int b = (int)(r >> 10);
    const float* prow = qp + r * NBP;
    const float* ks = ksum + (size_t)b * NBP;
    const int tid = threadIdx.x;
    __shared__ float red[256];

    float x = __bfloat162float(qh[r * DDIM + tid]) + __bfloat162float(ql[r * DDIM + tid]);
    red[tid] = x * x;
    __syncthreads();
    for (int s = 128; s > 0; s >>= 1) {
        if (tid < s) red[tid] += red[tid + s];
        __syncthreads();
    }
    const float c = 0.5f * DNORM2 * red[0] + decf(rowmaxu[r]);
    __syncthreads();

    float dot = 0.f;
    for (int j = tid * 4; j < NBP; j += 1024) {
        float4 p = *(const float4*)(prow + j);
        float v0 = (j + 0 < NBF) ? RATIO * (expf(p.x - c) + EPSF) : 0.f;
        float v1 = (j + 1 < NBF) ? RATIO * (expf(p.y - c) + EPSF) : 0.f;
        float v2 = (j + 2 < NBF) ? RATIO * (expf(p.z - c) + EPSF) : 0.f;
        float v3 = (j + 3 < NBF) ? RATIO * (expf(p.w - c) + EPSF) : 0.f;
        uint32_t ph0, pl0, ph1, pl1;
        split2p(v0, v1, ph0, pl0);
        split2p(v2, v3, ph1, pl1);
        *(uint2*)(oh + r * NBP + j) = make_uint2(ph0, ph1);
        *(uint2*)(ol + r * NBP + j) = make_uint2(pl0, pl1);
        float4 kv = *(const float4*)(ks + j);
        dot += v0 * kv.x + v1 * kv.y + v2 * kv.z + v3 * kv.w;
    }
    red[tid] = dot;
    __syncthreads();
    for (int s = 128; s > 0; s >>= 1) {
        if (tid < s) red[tid] += red[tid + s];
        __syncthreads();
    }
    if (tid == 0) dinv[r] = 1.0f / red[0];
}

// transpose + exp for K: 32 m x 128 n tiles -> kpT hi/lo [b][m][n] + ksum
// partials. Coalesced: float4 global reads, 256B-contiguous packed stores.
__global__ void __launch_bounds__(256)
ktexp_k(const float* __restrict__ kp, const float* __restrict__ diag,
        const unsigned* __restrict__ kmaxu, bf16* __restrict__ th,
        bf16* __restrict__ tl, float* __restrict__ part)
{
    __shared__ float sm[32][132];
    const int b = blockIdx.z;
    const int m0 = blockIdx.x * 32, n0 = blockIdx.y * 128;
    const int tid = threadIdx.x;
    const float km = decf(kmaxu[b]);

    // phase 1: thread = (n, half); read 16 m-values, exp, store transposed
    {
        const int n = tid >> 1, half = tid & 1;
        const float dk = diag[(size_t)b * NPT + n0 + n];
        const float* src = kp + ((size_t)b * NPT + n0 + n) * NBP + m0 + half * 16;
#pragma unroll
        for (int c4 = 0; c4 < 4; c4++) {
            float4 xx = *(const float4*)(src + c4 * 4);
            const int mb = m0 + half * 16 + c4 * 4;
            float vv[4] = {xx.x, xx.y, xx.z, xx.w};
#pragma unroll
            for (int e = 0; e < 4; e++)
                sm[half * 16 + c4 * 4 + e][n] =
                    (mb + e < NBF) ? RATIO * (expf(vv[e] - dk - km) + EPSF) : 0.f;
        }
    }
    __syncthreads();

    // phase 2: warp per 4 m-rows; lane emits 4 packed bf16 (8B) contiguous
    {
        const int w = tid >> 5, lane = tid & 31;
#pragma unroll
        for (int i = 0; i < 4; i++) {
            const int m = w * 4 + i;
            float4 v = *(const float4*)&sm[m][4 * lane];
            uint32_t ph0, pl0, ph1, pl1;
            split2p(v.x, v.y, ph0, pl0);
            split2p(v.z, v.w, ph1, pl1);
            const size_t obase = ((size_t)b * NBP + m0 + m) * NPT + n0 + 4 * lane;
            *(uint2*)&th[obase] = make_uint2(ph0, ph1);
            *(uint2*)&tl[obase] = make_uint2(pl0, pl1);
            float s = v.x + v.y + v.z + v.w;
#pragma unroll
            for (int o = 16; o > 0; o >>= 1)
                s += __shfl_xor_sync(0xffffffffu, s, o);
            if (lane == 0)
                part[((size_t)b * 8 + blockIdx.y) * NBP + m0 + m] = s;
        }
    }
}

__global__ void ksum2_k(const float* __restrict__ part, float* __restrict__ ksum)
{
    const int b = blockIdx.y;
    const int m = blockIdx.x * blockDim.x + threadIdx.x;
    if (m >= NBP) return;
    float s = 0.f;
#pragma unroll
    for (int j = 0; j < 8; j++)
        s += part[((size_t)b * 8 + j) * NBP + m];
    ksum[(size_t)b * NBP + m] = s;
}

// ---------------------------------------------------------------------------
// Launch
// ---------------------------------------------------------------------------
#define GETP(var, sym) cudaGetSymbolAddress((void**)&var, sym)

extern "C" void kernel_launch(void* const* d_in, const int* in_sizes, int n_in,
                              void* d_out, int out_size)
{
    const float* q     = (const float*)d_in[0];
    const float* k     = (const float*)d_in[1];
    const float* v     = (const float*)d_in[2];
    const float* Wq    = (const float*)d_in[3];
    const float* bq    = (const float*)d_in[4];
    const float* Wk    = (const float*)d_in[5];
    const float* bk    = (const float*)d_in[6];
    const float* Wv    = (const float*)d_in[7];
    const float* bv    = (const float*)d_in[8];
    const float* W_out = (const float*)d_in[9];
    const float* b_out = (const float*)d_in[10];
    const float* proj  = (const float*)d_in[11];
    float* out = (float*)d_out;

    float *qp, *kp, *diagk, *ksum, *kpart, *dinv;
    unsigned *kmaxu, *rowmaxu;
    bf16 *qin_h, *qin_l, *kin_h, *kin_l, *vin_h, *vin_l;
    bf16 *wtq_h, *wtq_l, *wtk_h, *wtk_l, *wtv_h, *wtv_l;
    bf16 *pr_h, *pr_l, *wo_h, *wo_l;
    bf16 *qall_h, *qall_l, *kall_h, *kall_l, *vall_h, *vall_l, *vt_h, *vt_l;
    bf16 *qph, *qpl, *kpT_h, *kpT_l, *ctxT_h, *ctxT_l, *outs_h, *outs_l;

    GETP(qp, g_qp); GETP(kp, g_kp);
    GETP(qin_h, g_qin_h); GETP(qin_l, g_qin_l);
    GETP(kin_h, g_kin_h); GETP(kin_l, g_kin_l);
    GETP(vin_h, g_vin_h); GETP(vin_l, g_vin_l);
    GETP(wtq_h, g_wtq_h); GETP(wtq_l, g_wtq_l);
    GETP(wtk_h, g_wtk_h); GETP(wtk_l, g_wtk_l);
    GETP(wtv_h, g_wtv_h); GETP(wtv_l, g_wtv_l);
    GETP(pr_h, g_pr_h);   GETP(pr_l, g_pr_l);
    GETP(wo_h, g_wo_h);   GETP(wo_l, g_wo_l);
    GETP(qall_h, g_qall_h); GETP(qall_l, g_qall_l);
    GETP(kall_h, g_kall_h); GETP(kall_l, g_kall_l);
    GETP(vall_h, g_vall_h); GETP(vall_l, g_vall_l);
    GETP(vt_h, g_vt_h);     GETP(vt_l, g_vt_l);
    GETP(qph, g_qph);       GETP(qpl, g_qpl);
    GETP(kpT_h, g_kpT_h);   GETP(kpT_l, g_kpT_l);
    GETP(ctxT_h, g_ctxT_h); GETP(ctxT_l, g_ctxT_l);
    GETP(outs_h, g_outs_h); GETP(outs_l, g_outs_l);
    GETP(diagk, g_diagk); GETP(ksum, g_ksum); GETP(kpart, g_kpart);
    GETP(dinv, g_dinv); GETP(kmaxu, g_kmaxu); GETP(rowmaxu, g_rowmaxu);

    cudaFuncSetAttribute(gemm7<1>, cudaFuncAttributeMaxDynamicSharedMemorySize, G7SMEM);
    cudaFuncSetAttribute(gemm7<2>, cudaFuncAttributeMaxDynamicSharedMemorySize, G7SMEM);
    cudaFuncSetAttribute(gemm7<3>, cudaFuncAttributeMaxDynamicSharedMemorySize, G7SMEM);
    cudaFuncSetAttribute(gemm7<4>, cudaFuncAttributeMaxDynamicSharedMemorySize, G7SMEM);
    cudaFuncSetAttribute(gemm7<5>, cudaFuncAttributeMaxDynamicSharedMemorySize, G7SMEM);
    cudaFuncSetAttribute(gemm7<6>, cudaFuncAttributeMaxDynamicSharedMemorySize, G7SMEM);

    // ---- 0) reset atomic-max buffers (graph replays!) + operand splits
    reset_k<<<(ROWS + 255) / 256, 256>>>(kmaxu, rowmaxu);
    {
        const size_t nin = (size_t)TT * NPT * DDIM;
        split_k<<<(unsigned)((nin / 4 + 255) / 256), 256>>>(q, qin_h, qin_l, nin, 1.f);
        split_k<<<(unsigned)((nin / 4 + 255) / 256), 256>>>(k, kin_h, kin_l, nin, 1.f);
        split_k<<<(unsigned)((nin / 4 + 255) / 256), 256>>>(v, vin_h, vin_l, nin, 1.f);
        dim3 tg(8, 8, 8), tb(32, 8);
        tsplit_k<<<tg, tb>>>(Wq, wtq_h, wtq_l, DDIM, DDIM);
        tsplit_k<<<tg, tb>>>(Wk, wtk_h, wtk_l, DDIM, DDIM);
        tsplit_k<<<tg, tb>>>(Wv, wtv_h, wtv_l, DDIM, DDIM);
        const size_t npr = (size_t)NBF * DDIM;
        prsplit_k<<<(unsigned)((npr / 4 + 255) / 256), 256>>>(proj, pr_h, pr_l);
        wsplit_k<<<(DDIM * HDCAT + 255) / 256, 256>>>(W_out, wo_h, wo_l);
    }

    // ---- 1) per-head projections (batched over (t,h): Hdiv = HH)
    {
        dim3 grid(4, 8, BATCH);
        gemm7<3><<<grid, 256, G7SMEM>>>(qin_h, qin_l, wtq_h, wtq_l,
            nullptr, qall_h, qall_l,
            NPT, DDIM, DDIM, DDIM, DDIM, DDIM,
            (long)NPT * DDIM, 0, 0, (long)DDIM * DDIM,
            (long)HH * NPT * DDIM, (long)NPT * DDIM, HH,
            bq, DDIM, nullptr, 0, 0, nullptr, 0);
        gemm7<3><<<grid, 256, G7SMEM>>>(kin_h, kin_l, wtk_h, wtk_l,
            nullptr, kall_h, kall_l,
            NPT, DDIM, DDIM, DDIM, DDIM, DDIM,
            (long)NPT * DDIM, 0, 0, (long)DDIM * DDIM,
            (long)HH * NPT * DDIM, (long)NPT * DDIM, HH,
            bk, DDIM, nullptr, 0, 0, nullptr, 0);
        gemm7<3><<<grid, 256, G7SMEM>>>(vin_h, vin_l, wtv_h, wtv_l,
            nullptr, vall_h, vall_l,
            NPT, DDIM, DDIM, DDIM, DDIM, DDIM,
            (long)NPT * DDIM, 0, 0, (long)DDIM * DDIM,
            (long)HH * NPT * DDIM, (long)NPT * DDIM, HH,
            bv, DDIM, nullptr, 0, 0, nullptr, 0);
    }

    // ---- 2) dash GEMMs (per-slab: Hdiv = 1) + fused max reductions
    {
        dim3 grid(NBP / 64, 8, BATCH);
        gemm7<6><<<grid, 256, G7SMEM>>>(qall_h, qall_l, pr_h, pr_l,
            qp, nullptr, nullptr,
            NPT, NBP, DDIM, DDIM, DDIM, NBP,
            (long)NPT * DDIM, 0, 0, 0, (long)NPT * NBP, 0, 1,
            nullptr, 0, nullptr, 0, 0, rowmaxu, NBF);
        gemm7<5><<<grid, 256, G7SMEM>>>(kall_h, kall_l, pr_h, pr_l,
            kp, nullptr, nullptr,
            NPT, NBP, DDIM, DDIM, DDIM, NBP,
            (long)NPT * DDIM, 0, 0, 0, (long)NPT * NBP, 0, 1,
            nullptr, 0, nullptr, 0, 0, kmaxu, NBF);
    }

    // ---- 3) k-side feature map chain, then fused q-exp + d_inv
    kdiag_k<<<ROWS / 8, 256>>>(kall_h, kall_l, diagk);
    ktexp_k<<<dim3(NBP / 32, 8, BATCH), 256>>>(kp, diagk, kmaxu, kpT_h, kpT_l, kpart);
    ksum2_k<<<dim3((NBP + 255) / 256, BATCH), 256>>>(kpart, ksum);
    qexp2_k<<<ROWS, 256>>>(qp, qall_h, qall_l, rowmaxu, ksum, qph, qpl, dinv);

    // ---- 4) vallT
    {
        dim3 tg(DDIM / 64, NPT / 64, BATCH);
        tbf_k<<<tg, 256>>>(vall_h, vt_h, NPT, DDIM);
        tbf_k<<<tg, 256>>>(vall_l, vt_l, NPT, DDIM);
    }

    // ---- 5) ctxT[b][e][m] = vallT[b] * kpT[b]^T (per-slab: Hdiv = 1)
    {
        dim3 grid(NBP / 64, 2, BATCH);
        gemm7<4><<<grid, 256, G7SMEM>>>(vt_h, vt_l, kpT_h, kpT_l,
            nullptr, ctxT_h, ctxT_l,
            DDIM, NBP, NPT, NPT, NPT, NBP,
            (long)DDIM * NPT, 0, (long)NBP * NPT, 0, (long)DDIM * NBP, 0, 1,
            nullptr, 0, nullptr, 0, 0, nullptr, 0);
    }

    // ---- 6) out: [t][n][h*256+e] contiguous bf16-pair store, *dinv (Hdiv = HH)
    {
        dim3 grid(4, 8, BATCH);
        gemm7<2><<<grid, 256, G7SMEM>>>(qph, qpl, ctxT_h, ctxT_l,
            nullptr, outs_h, outs_l,
            NPT, DDIM, NBP, NBP, NBP, HDCAT,
            (long)HH * NPT * NBP, (long)NPT * NBP,
            (long)HH * DDIM * NBP, (long)DDIM * NBP,
            (long)NPT * HDCAT, (long)DDIM, HH,
            nullptr, 0, dinv, (long)HH * NPT, (long)NPT, nullptr, 0);
    }

    // ---- 7) final: rep[8192][256] = outs * wr^T + b_out (wr = permuted W_out)
    {
        dim3 grid(4, 64, 1);
        gemm7<1><<<grid, 256, G7SMEM>>>(outs_h, outs_l, wo_h, wo_l,
            out, nullptr, nullptr,
            TT * NPT, DDIM, HDCAT, HDCAT, HDCAT, DDIM,
            0, 0, 0, 0, 0, 0, 1,
            b_out, 0, nullptr, 0, 0, nullptr, 0);
    }
}

// round 12
// speedup vs baseline: 3.8396x; 1.0399x over previous
#include <cuda_runtime.h>
#include <cuda_bf16.h>
#include <cstdint>
#include <math.h>

// ---------------------------------------------------------------------------
// Problem constants (T=8, N=M=1024, H=8, D=256, NB = int(256*ln 256) = 1419)
// ---------------------------------------------------------------------------
#define TT   8
#define NPT  1024
#define HH   8
#define DDIM 256
#define NBF  1419
#define NBP  1472              // padded to multiple of 64
#define ROWS (TT * HH * NPT)   // 65536
#define BATCH (TT * HH)        // 64
#define HDCAT (HH * DDIM)      // 2048

#define DNORM   0.25f
#define DNORM2  0.0625f
#define EPSF    1e-4f
#define RATIO   0.026547529f   // 1/sqrt(1419)
#define SSCALE  68719476736.0  // 2^36 fixed-point scale for diag accumulation

typedef __nv_bfloat16 bf16;

// ---------------------------------------------------------------------------
// Scratch (device globals; zero-init at load -> never-written pads stay 0)
// ---------------------------------------------------------------------------
__device__ float g_qp[(size_t)ROWS * NBP];
__device__ float g_kp[(size_t)ROWS * NBP];
__device__ bf16 g_qin_h[(size_t)TT * NPT * DDIM],  g_qin_l[(size_t)TT * NPT * DDIM];
__device__ bf16 g_kin_h[(size_t)TT * NPT * DDIM],  g_kin_l[(size_t)TT * NPT * DDIM];
__device__ bf16 g_vin_h[(size_t)TT * NPT * DDIM],  g_vin_l[(size_t)TT * NPT * DDIM];
__device__ bf16 g_wtq_h[(size_t)HH * DDIM * DDIM], g_wtq_l[(size_t)HH * DDIM * DDIM];
__device__ bf16 g_wtk_h[(size_t)HH * DDIM * DDIM], g_wtk_l[(size_t)HH * DDIM * DDIM];
__device__ bf16 g_wtv_h[(size_t)HH * DDIM * DDIM], g_wtv_l[(size_t)HH * DDIM * DDIM];
__device__ bf16 g_pr_h[(size_t)NBP * DDIM],        g_pr_l[(size_t)NBP * DDIM];
__device__ bf16 g_wo_h[(size_t)DDIM * HDCAT],      g_wo_l[(size_t)DDIM * HDCAT];
__device__ bf16 g_qall_h[(size_t)ROWS * DDIM],     g_qall_l[(size_t)ROWS * DDIM];
__device__ bf16 g_kall_h[(size_t)ROWS * DDIM],     g_kall_l[(size_t)ROWS * DDIM];
__device__ bf16 g_vt_h[(size_t)ROWS * DDIM],       g_vt_l[(size_t)ROWS * DDIM];
__device__ bf16 g_qph[(size_t)ROWS * NBP],         g_qpl[(size_t)ROWS * NBP];
__device__ bf16 g_kpT_h[(size_t)BATCH * NBP * NPT], g_kpT_l[(size_t)BATCH * NBP * NPT];
__device__ bf16 g_ctxT_h[(size_t)BATCH * DDIM * NBP], g_ctxT_l[(size_t)BATCH * DDIM * NBP];
__device__ bf16 g_outs_h[(size_t)TT * NPT * HDCAT], g_outs_l[(size_t)TT * NPT * HDCAT];
__device__ float g_ksum[(size_t)BATCH * NBP];
__device__ float g_kpart[(size_t)BATCH * 8 * NBP];
__device__ float g_dinv[(size_t)ROWS];
__device__ unsigned g_kmaxu[(size_t)BATCH];
__device__ unsigned g_rowmaxu[(size_t)ROWS];
__device__ unsigned long long g_dq64[(size_t)ROWS];
__device__ unsigned long long g_dk64[(size_t)ROWS];

// ---------------------------------------------------------------------------
// helpers
// ---------------------------------------------------------------------------
__device__ __forceinline__ uint32_t smem_u32(const void* p) {
    uint32_t a;
    asm("{ .reg .u64 t; cvta.to.shared.u64 t, %1; cvt.u32.u64 %0, t; }"
        : "=r"(a) : "l"(p));
    return a;
}

__device__ __forceinline__ void ldm4(uint32_t& r0, uint32_t& r1,
                                     uint32_t& r2, uint32_t& r3, uint32_t a) {
    asm volatile("ldmatrix.sync.aligned.m8n8.x4.shared.b16 {%0,%1,%2,%3}, [%4];"
                 : "=r"(r0), "=r"(r1), "=r"(r2), "=r"(r3) : "r"(a));
}

__device__ __forceinline__ void mma16816(float* c, uint32_t a0, uint32_t a1,
                                         uint32_t a2, uint32_t a3,
                                         uint32_t b0, uint32_t b1) {
    asm volatile(
        "mma.sync.aligned.m16n8k16.row.col.f32.bf16.bf16.f32 "
        "{%0,%1,%2,%3},{%4,%5,%6,%7},{%8,%9},{%0,%1,%2,%3};"
        : "+f"(c[0]), "+f"(c[1]), "+f"(c[2]), "+f"(c[3])
        : "r"(a0), "r"(a1), "r"(a2), "r"(a3), "r"(b0), "r"(b1));
}

__device__ __forceinline__ void cpasync16(uint32_t dst, const bf16* src, int sz) {
    asm volatile("cp.async.cg.shared.global [%0], [%1], 16, %2;"
                 :: "r"(dst), "l"(__cvta_generic_to_global(src)), "r"(sz));
}

__device__ __forceinline__ void splitw(float x, bf16& h, bf16& l) {
    h = __float2bfloat16_rn(x);
    l = __float2bfloat16_rn(x - __bfloat162float(h));
}

__device__ __forceinline__ uint32_t packbf(bf16 a, bf16 b) {
    return (uint32_t)__bfloat16_as_ushort(a)
         | ((uint32_t)__bfloat16_as_ushort(b) << 16);
}

__device__ __forceinline__ void split2p(float x, float y,
                                        uint32_t& ph, uint32_t& pl) {
    bf16 hx, lx, hy, ly;
    splitw(x, hx, lx); splitw(y, hy, ly);
    ph = packbf(hx, hy); pl = packbf(lx, ly);
}

// monotonic float <-> unsigned encoding (total order; exact; order-independent max)
__device__ __forceinline__ unsigned encf(float f) {
    unsigned u = __float_as_uint(f);
    return (u & 0x80000000u) ? ~u : (u | 0x80000000u);
}
__device__ __forceinline__ float decf(unsigned u) {
    unsigned b = (u & 0x80000000u) ? (u ^ 0x80000000u) : ~u;
    return __uint_as_float(b);
}

__device__ __forceinline__ float diag_from_i64(unsigned long long v) {
    return 0.5f * DNORM2 * (float)((double)(long long)v * (1.0 / SSCALE));
}

// ---------------------------------------------------------------------------
// gemm7: NT bf16x3 mma.sync GEMM, 256 threads, 8 warps (4m x 2n), 32x32/warp,
//        CTA tile 128x64, 2-stage cp.async double buffer, 3 CTAs/SM.
//   C[M,N] = A[M,K] * B[N,K]^T ; operands hi/lo bf16, k-contiguous.
//   EPI: 1 +bias[col] f32 | 2 *scale[row] bf16 pair | 3 +bias[col] bf16 pair
//        4 plain bf16 pair | 5 f32 + slab-max atomic | 6 f32 + row-max atomic
//        7 +bias[row] bf16 pair | 8 +bias[col] bf16 pair + row-sumsq i64 atomic
//   K % 32 == 0, N even, lda == ldb == K.
// ---------------------------------------------------------------------------
#define TSTRIDE 40
#define AT_B 10240
#define BT_B 5120
#define STAGE_B 30720
#define G7SMEM  (2 * STAGE_B)

template<int EPI>
__global__ void __launch_bounds__(256, 3)
gemm7(const bf16* __restrict__ Ahi, const bf16* __restrict__ Alo,
      const bf16* __restrict__ Bhi, const bf16* __restrict__ Blo,
      float* __restrict__ Cf, bf16* __restrict__ Chi, bf16* __restrict__ Clo,
      int M, int N, int K, int lda, int ldb, int ldc,
      long aT, long aH, long bT, long bH, long cT, long cH, int Hdiv,
      const float* __restrict__ bias, long biasH,
      const float* __restrict__ scale, long scT, long scH,
      unsigned* __restrict__ maxu, int vlim,
      unsigned long long* __restrict__ sacc)
{
    extern __shared__ bf16 smb[];
    const uint32_t sb = smem_u32(smb);
    const int tid = threadIdx.x;
    const int wid = tid >> 5, lane = tid & 31;
    const int warp_m = wid >> 1, warp_n = wid & 1;
    const int g = lane >> 2, tg = lane & 3;

    const int bz = blockIdx.z;
    const int t = bz / Hdiv, h = bz % Hdiv;
    const long aoff = (long)t * aT + (long)h * aH;
    const long boff = (long)t * bT + (long)h * bH;
    const long coff = (long)t * cT + (long)h * cH;
    const float* biasp  = (EPI == 1 || EPI == 3 || EPI == 7 || EPI == 8)
                        ? bias + (long)h * biasH : nullptr;
    const float* scalep = (EPI == 2) ? scale + (long)t * scT + (long)h * scH : nullptr;

    const int m0 = blockIdx.y * 128;
    const int n0 = blockIdx.x * 64;

    const bf16* srcAh = Ahi + aoff;
    const bf16* srcAl = Alo + aoff;
    const bf16* srcBh = Bhi + boff;
    const bf16* srcBl = Blo + boff;

    const int S = K >> 5;

    auto stage = [&](int s, int bi) {
        const int k0 = s << 5;
        const uint32_t base = sb + (uint32_t)bi * STAGE_B;
#pragma unroll
        for (int c = 0; c < 2; c++) {
            const int id = tid + c * 256;
            const int r = id >> 2, q = id & 3;
            const int gr = m0 + r;
            const int sz = (gr < M) ? 16 : 0;
            const long so = (long)(sz ? gr : m0) * lda + k0 + q * 8;
            const uint32_t d = base + (uint32_t)(r * TSTRIDE + q * 8) * 2;
            cpasync16(d, srcAh + so, sz);
            cpasync16(d + AT_B, srcAl + so, sz);
        }
        {
            const int r = tid >> 2, q = tid & 3;
            const int gr = n0 + r;
            const int sz = (gr < N) ? 16 : 0;
            const long so = (long)(sz ? gr : n0) * ldb + k0 + q * 8;
            const uint32_t d = base + (uint32_t)(2 * AT_B)
                             + (uint32_t)(r * TSTRIDE + q * 8) * 2;
            cpasync16(d, srcBh + so, sz);
            cpasync16(d + BT_B, srcBl + so, sz);
        }
        asm volatile("cp.async.commit_group;" ::: "memory");
    };

    float acc[2][4][4];
#pragma unroll
    for (int i = 0; i < 2; i++)
#pragma unroll
        for (int j = 0; j < 4; j++)
#pragma unroll
            for (int e = 0; e < 4; e++) acc[i][j][e] = 0.f;

    stage(0, 0);
    if (S > 1) stage(1, 1);

    for (int s = 0; s < S; s++) {
        if (s + 1 < S) asm volatile("cp.async.wait_group 1;" ::: "memory");
        else           asm volatile("cp.async.wait_group 0;" ::: "memory");
        __syncthreads();

        const uint32_t base = sb + (uint32_t)(s & 1) * STAGE_B;
#pragma unroll
        for (int ks = 0; ks < 2; ks++) {
            const int ko = ks << 4;
            uint32_t bh[4][2], bl[4][2];
#pragma unroll
            for (int p = 0; p < 2; p++) {
                const int nrow = warp_n * 32 + p * 16 + ((lane >> 4) << 3) + (lane & 7);
                const int kcol = ko + ((lane >> 3) & 1) * 8;
                const uint32_t ab = base + (uint32_t)(2 * AT_B)
                                  + (uint32_t)(nrow * TSTRIDE + kcol) * 2;
                ldm4(bh[2 * p][0], bh[2 * p][1], bh[2 * p + 1][0], bh[2 * p + 1][1], ab);
                ldm4(bl[2 * p][0], bl[2 * p][1], bl[2 * p + 1][0], bl[2 * p + 1][1],
                     ab + BT_B);
            }
#pragma unroll
            for (int ma = 0; ma < 2; ma++) {
                const int mrow = warp_m * 32 + ma * 16 + ((lane >> 3) & 1) * 8 + (lane & 7);
                const int kcol = ko + (lane >> 4) * 8;
                const uint32_t aa = base + (uint32_t)(mrow * TSTRIDE + kcol) * 2;
                uint32_t ah0, ah1, ah2, ah3, al0, al1, al2, al3;
                ldm4(ah0, ah1, ah2, ah3, aa);
                ldm4(al0, al1, al2, al3, aa + AT_B);
#pragma unroll
                for (int nb = 0; nb < 4; nb++) {
                    mma16816(acc[ma][nb], ah0, ah1, ah2, ah3, bh[nb][0], bh[nb][1]);
                    mma16816(acc[ma][nb], ah0, ah1, ah2, ah3, bl[nb][0], bl[nb][1]);
                    mma16816(acc[ma][nb], al0, al1, al2, al3, bh[nb][0], bh[nb][1]);
                }
            }
        }
        __syncthreads();
        if (s + 2 < S) stage(s + 2, s & 1);
    }

    // ---- epilogue (N even; col and col+1 in-bounds together)
    float slabmax = -3.4e38f;
#pragma unroll
    for (int ma = 0; ma < 2; ma++) {
#pragma unroll
        for (int hf = 0; hf < 2; hf++) {
            const int row = m0 + warp_m * 32 + ma * 16 + g + hf * 8;
            float rowmax = -3.4e38f;
            float ss = 0.f;
            const bool rok = row < M;
            const float sc = (EPI == 2 && rok) ? scalep[row] : 1.f;
            const float rb = (EPI == 7 && rok) ? biasp[row] : 0.f;
#pragma unroll
            for (int nb = 0; nb < 4; nb++) {
                const int col = n0 + warp_n * 32 + nb * 8 + 2 * tg;
                if (!rok || col >= N) continue;
                float v0 = acc[ma][nb][hf * 2 + 0];
                float v1 = acc[ma][nb][hf * 2 + 1];
                if (EPI == 1 || EPI == 3 || EPI == 8) { v0 += biasp[col]; v1 += biasp[col + 1]; }
                if (EPI == 7) { v0 += rb; v1 += rb; }
                if (EPI == 2) { v0 *= sc; v1 *= sc; }
                if (EPI == 8) ss += v0 * v0 + v1 * v1;
                const long idx = coff + (long)row * ldc + col;
                if (EPI == 1 || EPI == 5 || EPI == 6) {
                    *(float2*)&Cf[idx] = make_float2(v0, v1);
                    if (EPI == 5 || EPI == 6) {
                        if (col < vlim) {
                            if (EPI == 5) slabmax = fmaxf(slabmax, v0);
                            else          rowmax  = fmaxf(rowmax, v0);
                        }
                        if (col + 1 < vlim) {
                            if (EPI == 5) slabmax = fmaxf(slabmax, v1);
                            else          rowmax  = fmaxf(rowmax, v1);
                        }
                    }
                } else {
                    uint32_t ph, pl;
                    split2p(v0, v1, ph, pl);
                    *(uint32_t*)&Chi[idx] = ph;
                    *(uint32_t*)&Clo[idx] = pl;
                }
            }
            if (EPI == 6) {
                rowmax = fmaxf(rowmax, __shfl_xor_sync(0xffffffffu, rowmax, 1));
                rowmax = fmaxf(rowmax, __shfl_xor_sync(0xffffffffu, rowmax, 2));
                if (tg == 0 && rok)
                    atomicMax(&maxu[(long)bz * M + row], encf(rowmax));
            }
            if (EPI == 8) {
                ss += __shfl_xor_sync(0xffffffffu, ss, 1);
                ss += __shfl_xor_sync(0xffffffffu, ss, 2);
                if (tg == 0 && rok)
                    atomicAdd(&sacc[(long)bz * M + row],
                              (unsigned long long)(long long)((double)ss * SSCALE));
            }
        }
    }
    if (EPI == 5) {
#pragma unroll
        for (int o = 16; o > 0; o >>= 1)
            slabmax = fmaxf(slabmax, __shfl_xor_sync(0xffffffffu, slabmax, o));
        if (lane == 0) atomicMax(&maxu[bz], encf(slabmax));
    }
}

// ---------------------------------------------------------------------------
// conversion / reset passes
// ---------------------------------------------------------------------------
__global__ void reset_k(unsigned* __restrict__ kmaxu, unsigned* __restrict__ rowmaxu,
                        unsigned long long* __restrict__ dq,
                        unsigned long long* __restrict__ dk)
{
    int i = blockIdx.x * blockDim.x + threadIdx.x;
    if (i < BATCH) kmaxu[i] = 0u;
    if (i < ROWS) { rowmaxu[i] = 0u; dq[i] = 0ull; dk[i] = 0ull; }
}

__global__ void split_k(const float* __restrict__ s, bf16* __restrict__ h,
                        bf16* __restrict__ l, size_t n, float scl)
{
    size_t i4 = ((size_t)blockIdx.x * blockDim.x + threadIdx.x) * 4;
    if (i4 < n) {
        float4 x = *(const float4*)(s + i4);
        uint32_t ph0, pl0, ph1, pl1;
        split2p(x.x * scl, x.y * scl, ph0, pl0);
        split2p(x.z * scl, x.w * scl, ph1, pl1);
        *(uint2*)(h + i4) = make_uint2(ph0, ph1);
        *(uint2*)(l + i4) = make_uint2(pl0, pl1);
    }
}

__global__ void wsplit_k(const float* __restrict__ W, bf16* __restrict__ h,
                         bf16* __restrict__ l)
{
    int i = blockIdx.x * blockDim.x + threadIdx.x;
    if (i < DDIM * HDCAT) {
        int d = i / HDCAT, fp = i % HDCAT;
        int hh = fp >> 8, e = fp & 255;
        float x = W[(size_t)d * HDCAT + e * 8 + hh];
        bf16 hb, lb; splitw(x, hb, lb);
        h[i] = hb; l[i] = lb;
    }
}

// fp32 [z][R][C] -> bf16 hi/lo [z][C][R] (weights, small)
__global__ void tsplit_k(const float* __restrict__ src, bf16* __restrict__ hi,
                         bf16* __restrict__ lo, int R, int C)
{
    __shared__ float sm[32][33];
    const int z = blockIdx.z;
    const int c0 = blockIdx.x * 32, r0 = blockIdx.y * 32;
    const float* s = src + (size_t)z * R * C;
    bf16* ho = hi + (size_t)z * R * C;
    bf16* lv = lo + (size_t)z * R * C;
    const int tx = threadIdx.x, ty = threadIdx.y;
    for (int i = ty; i < 32; i += 8)
        sm[i][tx] = s[(size_t)(r0 + i) * C + c0 + tx];
    __syncthreads();
    for (int i = ty; i < 32; i += 8) {
        float x = sm[tx][i];
        bf16 hb, lb; splitw(x, hb, lb);
        ho[(size_t)(c0 + i) * R + r0 + tx] = hb;
        lv[(size_t)(c0 + i) * R + r0 + tx] = lb;
    }
}

// ---------------------------------------------------------------------------
// feature-map / reduction kernels
// ---------------------------------------------------------------------------
// q feature map + d_inv fused; diag from fused i64 accumulator
__global__ void __launch_bounds__(256)
qexp2_k(const float* __restrict__ qp, const unsigned long long* __restrict__ dq,
        const unsigned* __restrict__ rowmaxu,
        const float* __restrict__ ksum, bf16* __restrict__ oh,
        bf16* __restrict__ ol, float* __restrict__ dinv)
{
    const size_t r = blockIdx.x;
    const int b = (int)(r >> 10);
    const float* prow = qp + r * NBP;
    const float* ks = ksum + (size_t)b * NBP;
    const int tid = threadIdx.x;
    __shared__ float red[256];

    const float c = diag_from_i64(dq[r]) + decf(rowmaxu[r]);

    float dot = 0.f;
    for (int j = tid * 4; j < NBP; j += 1024) {
        float4 p = *(const float4*)(prow + j);
        float v0 = (j + 0 < NBF) ? RATIO * (__expf(p.x - c) + EPSF) : 0.f;
        float v1 = (j + 1 < NBF) ? RATIO * (__expf(p.y - c) + EPSF) : 0.f;
        float v2 = (j + 2 < NBF) ? RATIO * (__expf(p.z - c) + EPSF) : 0.f;
        float v3 = (j + 3 < NBF) ? RATIO * (__expf(p.w - c) + EPSF) : 0.f;
        uint32_t ph0, pl0, ph1, pl1;
        split2p(v0, v1, ph0, pl0);
        split2p(v2, v3, ph1, pl1);
        *(uint2*)(oh + r * NBP + j) = make_uint2(ph0, ph1);
        *(uint2*)(ol + r * NBP + j) = make_uint2(pl0, pl1);
        float4 kv = *(const float4*)(ks + j);
        dot += v0 * kv.x + v1 * kv.y + v2 * kv.z + v3 * kv.w;
    }
    red[tid] = dot;
    __syncthreads();
    for (int s = 128; s > 0; s >>= 1) {
        if (tid < s) red[tid] += red[tid + s];
        __syncthreads();
    }
    if (tid == 0) dinv[r] = 1.0f / red[0];
}

// transpose + exp for K: 32 m x 128 n tiles -> kpT hi/lo [b][m][n] + ksum partials
__global__ void __launch_bounds__(256)
ktexp_k(const float* __restrict__ kp, const unsigned long long* __restrict__ dk,
        const unsigned* __restrict__ kmaxu, bf16* __restrict__ th,
        bf16* __restrict__ tl, float* __restrict__ part)
{
    __shared__ float sm[32][132];
    const int b = blockIdx.z;
    const int m0 = blockIdx.x * 32, n0 = blockIdx.y * 128;
    const int tid = threadIdx.x;
    const float km = decf(kmaxu[b]);

    {
        const int n = tid >> 1, half = tid & 1;
        const float dkv = diag_from_i64(dk[(size_t)b * NPT + n0 + n]);
        const float* src = kp + ((size_t)b * NPT + n0 + n) * NBP + m0 + half * 16;
#pragma unroll
        for (int c4 = 0; c4 < 4; c4++) {
            float4 xx = *(const float4*)(src + c4 * 4);
            const int mb = m0 + half * 16 + c4 * 4;
            float vv[4] = {xx.x, xx.y, xx.z, xx.w};
#pragma unroll
            for (int e = 0; e < 4; e++)
                sm[half * 16 + c4 * 4 + e][n] =
                    (mb + e < NBF) ? RATIO * (__expf(vv[e] - dkv - km) + EPSF) : 0.f;
        }
    }
    __syncthreads();

    {
        const int w = tid >> 5, lane = tid & 31;
#pragma unroll
        for (int i = 0; i < 4; i++) {
            const int m = w * 4 + i;
            float4 v = *(const float4*)&sm[m][4 * lane];
            uint32_t ph0, pl0, ph1, pl1;
            split2p(v.x, v.y, ph0, pl0);
            split2p(v.z, v.w, ph1, pl1);
            const size_t obase = ((size_t)b * NBP + m0 + m) * NPT + n0 + 4 * lane;
            *(uint2*)&th[obase] = make_uint2(ph0, ph1);
            *(uint2*)&tl[obase] = make_uint2(pl0, pl1);
            float s = v.x + v.y + v.z + v.w;
#pragma unroll
            for (int o = 16; o > 0; o >>= 1)
                s += __shfl_xor_sync(0xffffffffu, s, o);
            if (lane == 0)
                part[((size_t)b * 8 + blockIdx.y) * NBP + m0 + m] = s;
        }
    }
}

__global__ void ksum2_k(const float* __restrict__ part, float* __restrict__ ksum)
{
    const int b = blockIdx.y;
    const int m = blockIdx.x * blockDim.x + threadIdx.x;
    if (m >= NBP) return;
    float s = 0.f;
#pragma unroll
    for (int j = 0; j < 8; j++)
        s += part[((size_t)b * 8 + j) * NBP + m];
    ksum[(size_t)b * NBP + m] = s;
}

// ---------------------------------------------------------------------------
// Launch
// ---------------------------------------------------------------------------
#define GETP(var, sym) cudaGetSymbolAddress((void**)&var, sym)

extern "C" void kernel_launch(void* const* d_in, const int* in_sizes, int n_in,
                              void* d_out, int out_size)
{
    const float* q     = (const float*)d_in[0];
    const float* k     = (const float*)d_in[1];
    const float* v     = (const float*)d_in[2];
    const float* Wq    = (const float*)d_in[3];
    const float* bq    = (const float*)d_in[4];
    const float* Wk    = (const float*)d_in[5];
    const float* bk    = (const float*)d_in[6];
    const float* Wv    = (const float*)d_in[7];
    const float* bv    = (const float*)d_in[8];
    const float* W_out = (const float*)d_in[9];
    const float* b_out = (const float*)d_in[10];
    const float* proj  = (const float*)d_in[11];
    float* out = (float*)d_out;

    float *qp, *kp, *ksum, *kpart, *dinv;
    unsigned *kmaxu, *rowmaxu;
    unsigned long long *dq64, *dk64;
    bf16 *qin_h, *qin_l, *kin_h, *kin_l, *vin_h, *vin_l;
    bf16 *wtq_h, *wtq_l, *wtk_h, *wtk_l, *wtv_h, *wtv_l;
    bf16 *pr_h, *pr_l, *wo_h, *wo_l;
    bf16 *qall_h, *qall_l, *kall_h, *kall_l, *vt_h, *vt_l;
    bf16 *qph, *qpl, *kpT_h, *kpT_l, *ctxT_h, *ctxT_l, *outs_h, *outs_l;

    GETP(qp, g_qp); GETP(kp, g_kp);
    GETP(qin_h, g_qin_h); GETP(qin_l, g_qin_l);
    GETP(kin_h, g_kin_h); GETP(kin_l, g_kin_l);
    GETP(vin_h, g_vin_h); GETP(vin_l, g_vin_l);
    GETP(wtq_h, g_wtq_h); GETP(wtq_l, g_wtq_l);
    GETP(wtk_h, g_wtk_h); GETP(wtk_l, g_wtk_l);
    GETP(wtv_h, g_wtv_h); GETP(wtv_l, g_wtv_l);
    GETP(pr_h, g_pr_h);   GETP(pr_l, g_pr_l);
    GETP(wo_h, g_wo_h);   GETP(wo_l, g_wo_l);
    GETP(qall_h, g_qall_h); GETP(qall_l, g_qall_l);
    GETP(kall_h, g_kall_h); GETP(kall_l, g_kall_l);
    GETP(vt_h, g_vt_h);     GETP(vt_l, g_vt_l);
    GETP(qph, g_qph);       GETP(qpl, g_qpl);
    GETP(kpT_h, g_kpT_h);   GETP(kpT_l, g_kpT_l);
    GETP(ctxT_h, g_ctxT_h); GETP(ctxT_l, g_ctxT_l);
    GETP(outs_h, g_outs_h); GETP(outs_l, g_outs_l);
    GETP(ksum, g_ksum); GETP(kpart, g_kpart);
    GETP(dinv, g_dinv); GETP(kmaxu, g_kmaxu); GETP(rowmaxu, g_rowmaxu);
    GETP(dq64, g_dq64); GETP(dk64, g_dk64);

    cudaFuncSetAttribute(gemm7<1>, cudaFuncAttributeMaxDynamicSharedMemorySize, G7SMEM);
    cudaFuncSetAttribute(gemm7<2>, cudaFuncAttributeMaxDynamicSharedMemorySize, G7SMEM);
    cudaFuncSetAttribute(gemm7<4>, cudaFuncAttributeMaxDynamicSharedMemorySize, G7SMEM);
    cudaFuncSetAttribute(gemm7<5>, cudaFuncAttributeMaxDynamicSharedMemorySize, G7SMEM);
    cudaFuncSetAttribute(gemm7<6>, cudaFuncAttributeMaxDynamicSharedMemorySize, G7SMEM);
    cudaFuncSetAttribute(gemm7<7>, cudaFuncAttributeMaxDynamicSharedMemorySize, G7SMEM);
    cudaFuncSetAttribute(gemm7<8>, cudaFuncAttributeMaxDynamicSharedMemorySize, G7SMEM);

    // ---- 0) reset accumulators (graph replays!) + operand splits
    reset_k<<<(ROWS + 255) / 256, 256>>>(kmaxu, rowmaxu, dq64, dk64);
    {
        const size_t nin = (size_t)TT * NPT * DDIM;
        split_k<<<(unsigned)((nin / 4 + 255) / 256), 256>>>(q, qin_h, qin_l, nin, 1.f);
        split_k<<<(unsigned)((nin / 4 + 255) / 256), 256>>>(k, kin_h, kin_l, nin, 1.f);
        split_k<<<(unsigned)((nin / 4 + 255) / 256), 256>>>(v, vin_h, vin_l, nin, 1.f);
        dim3 tg(8, 8, 8), tb(32, 8);
        tsplit_k<<<tg, tb>>>(Wq, wtq_h, wtq_l, DDIM, DDIM);
        tsplit_k<<<tg, tb>>>(Wk, wtk_h, wtk_l, DDIM, DDIM);
        tsplit_k<<<tg, tb>>>(Wv, wtv_h, wtv_l, DDIM, DDIM);
        const size_t npr = (size_t)NBF * DDIM;
        split_k<<<(unsigned)((npr / 4 + 255) / 256), 256>>>(proj, pr_h, pr_l, npr, DNORM);
        wsplit_k<<<(DDIM * HDCAT + 255) / 256, 256>>>(W_out, wo_h, wo_l);
    }

    // ---- 1) q/k projections with fused row-sumsq (EPI 8, Hdiv = HH)
    {
        dim3 grid(4, 8, BATCH);
        gemm7<8><<<grid, 256, G7SMEM>>>(qin_h, qin_l, wtq_h, wtq_l,
            nullptr, qall_h, qall_l,
            NPT, DDIM, DDIM, DDIM, DDIM, DDIM,
            (long)NPT * DDIM, 0, 0, (long)DDIM * DDIM,
            (long)HH * NPT * DDIM, (long)NPT * DDIM, HH,
            bq, DDIM, nullptr, 0, 0, nullptr, 0, dq64);
        gemm7<8><<<grid, 256, G7SMEM>>>(kin_h, kin_l, wtk_h, wtk_l,
            nullptr, kall_h, kall_l,
            NPT, DDIM, DDIM, DDIM, DDIM, DDIM,
            (long)NPT * DDIM, 0, 0, (long)DDIM * DDIM,
            (long)HH * NPT * DDIM, (long)NPT * DDIM, HH,
            bk, DDIM, nullptr, 0, 0, nullptr, 0, dk64);
    }
    // v projection directly transposed: vt[b][e][n] (EPI 7: row bias)
    {
        dim3 grid(NPT / 64, 2, BATCH);
        gemm7<7><<<grid, 256, G7SMEM>>>(wtv_h, wtv_l, vin_h, vin_l,
            nullptr, vt_h, vt_l,
            DDIM, NPT, DDIM, DDIM, DDIM, NPT,
            0, (long)DDIM * DDIM, (long)NPT * DDIM, 0,
            (long)HH * DDIM * NPT, (long)DDIM * NPT, HH,
            bv, DDIM, nullptr, 0, 0, nullptr, 0, nullptr);
    }

    // ---- 2) dash GEMMs (per-slab: Hdiv = 1) + fused max reductions
    {
        dim3 grid(NBP / 64, 8, BATCH);
        gemm7<6><<<grid, 256, G7SMEM>>>(qall_h, qall_l, pr_h, pr_l,
            qp, nullptr, nullptr,
            NPT, NBP, DDIM, DDIM, DDIM, NBP,
            (long)NPT * DDIM, 0, 0, 0, (long)NPT * NBP, 0, 1,
            nullptr, 0, nullptr, 0, 0, rowmaxu, NBF, nullptr);
        gemm7<5><<<grid, 256, G7SMEM>>>(kall_h, kall_l, pr_h, pr_l,
            kp, nullptr, nullptr,
            NPT, NBP, DDIM, DDIM, DDIM, NBP,
            (long)NPT * DDIM, 0, 0, 0, (long)NPT * NBP, 0, 1,
            nullptr, 0, nullptr, 0, 0, kmaxu, NBF, nullptr);
    }

    // ---- 3) k-side feature map chain, then fused q-exp + d_inv
    ktexp_k<<<dim3(NBP / 32, 8, BATCH), 256>>>(kp, dk64, kmaxu, kpT_h, kpT_l, kpart);
    ksum2_k<<<dim3((NBP + 255) / 256, BATCH), 256>>>(kpart, ksum);
    qexp2_k<<<ROWS, 256>>>(qp, dq64, rowmaxu, ksum, qph, qpl, dinv);

    // ---- 4) ctxT[b][e][m] = vt[b] * kpT[b]^T (per-slab: Hdiv = 1)
    {
        dim3 grid(NBP / 64, 2, BATCH);
        gemm7<4><<<grid, 256, G7SMEM>>>(vt_h, vt_l, kpT_h, kpT_l,
            nullptr, ctxT_h, ctxT_l,
            DDIM, NBP, NPT, NPT, NPT, NBP,
            (long)DDIM * NPT, 0, (long)NBP * NPT, 0, (long)DDIM * NBP, 0, 1,
            nullptr, 0, nullptr, 0, 0, nullptr, 0, nullptr);
    }

    // ---- 5) out: [t][n][h*256+e] contiguous bf16-pair store, *dinv (Hdiv = HH)
    {
        dim3 grid(4, 8, BATCH);
        gemm7<2><<<grid, 256, G7SMEM>>>(qph, qpl, ctxT_h, ctxT_l,
            nullptr, outs_h, outs_l,
            NPT, DDIM, NBP, NBP, NBP, HDCAT,
            (long)HH * NPT * NBP, (long)NPT * NBP,
            (long)HH * DDIM * NBP, (long)DDIM * NBP,
            (long)NPT * HDCAT, (long)DDIM, HH,
            nullptr, 0, dinv, (long)HH * NPT, (long)NPT, nullptr, 0, nullptr);
    }

    // ---- 6) final: rep[8192][256] = outs * wr^T + b_out (wr = permuted W_out)
    {
        dim3 grid(4, 64, 1);
        gemm7<1><<<grid, 256, G7SMEM>>>(outs_h, outs_l, wo_h, wo_l,
            out, nullptr, nullptr,
            TT * NPT, DDIM, HDCAT, HDCAT, HDCAT, DDIM,
            0, 0, 0, 0, 0, 0, 1,
            b_out, 0, nullptr, 0, 0, nullptr, 0, nullptr);
    }
}

// round 15
// speedup vs baseline: 3.8859x; 1.0121x over previous
#include <cuda_runtime.h>
#include <cuda_bf16.h>
#include <cstdint>
#include <math.h>

// ---------------------------------------------------------------------------
// Problem constants (T=8, N=M=1024, H=8, D=256, NB = int(256*ln 256) = 1419)
// ---------------------------------------------------------------------------
#define TT   8
#define NPT  1024
#define HH   8
#define DDIM 256
#define NBF  1419
#define NBP  1472              // padded to multiple of 64
#define ROWS (TT * HH * NPT)   // 65536
#define BATCH (TT * HH)        // 64
#define HDCAT (HH * DDIM)      // 2048

#define DNORM   0.25f
#define DNORM2  0.0625f
#define EPSF    1e-4f
#define RATIO   0.026547529f   // 1/sqrt(1419)
#define SSCALE  68719476736.0  // 2^36 fixed-point scale for diag accumulation

typedef __nv_bfloat16 bf16;

// ---------------------------------------------------------------------------
// Scratch (device globals; zero-init at load -> never-written pads stay 0)
// ---------------------------------------------------------------------------
__device__ float g_qp[(size_t)ROWS * NBP];
__device__ float g_kp[(size_t)ROWS * NBP];
__device__ bf16 g_qin_h[(size_t)TT * NPT * DDIM],  g_qin_l[(size_t)TT * NPT * DDIM];
__device__ bf16 g_kin_h[(size_t)TT * NPT * DDIM],  g_kin_l[(size_t)TT * NPT * DDIM];
__device__ bf16 g_vin_h[(size_t)TT * NPT * DDIM],  g_vin_l[(size_t)TT * NPT * DDIM];
__device__ bf16 g_wtq_h[(size_t)HH * DDIM * DDIM], g_wtq_l[(size_t)HH * DDIM * DDIM];
__device__ bf16 g_wtk_h[(size_t)HH * DDIM * DDIM], g_wtk_l[(size_t)HH * DDIM * DDIM];
__device__ bf16 g_wtv_h[(size_t)HH * DDIM * DDIM], g_wtv_l[(size_t)HH * DDIM * DDIM];
__device__ bf16 g_pr_h[(size_t)NBP * DDIM],        g_pr_l[(size_t)NBP * DDIM];
__device__ bf16 g_wo_h[(size_t)DDIM * HDCAT],      g_wo_l[(size_t)DDIM * HDCAT];
__device__ bf16 g_qall_h[(size_t)ROWS * DDIM],     g_qall_l[(size_t)ROWS * DDIM];
__device__ bf16 g_kall_h[(size_t)ROWS * DDIM],     g_kall_l[(size_t)ROWS * DDIM];
__device__ bf16 g_vt_h[(size_t)ROWS * DDIM],       g_vt_l[(size_t)ROWS * DDIM];
__device__ bf16 g_qph[(size_t)ROWS * NBP],         g_qpl[(size_t)ROWS * NBP];
__device__ bf16 g_kpT_h[(size_t)BATCH * NBP * NPT], g_kpT_l[(size_t)BATCH * NBP * NPT];
__device__ bf16 g_ctxT_h[(size_t)BATCH * DDIM * NBP], g_ctxT_l[(size_t)BATCH * DDIM * NBP];
__device__ bf16 g_outs_h[(size_t)TT * NPT * HDCAT], g_outs_l[(size_t)TT * NPT * HDCAT];
__device__ float g_ksum[(size_t)BATCH * NBP];
__device__ float g_kpart[(size_t)BATCH * 8 * NBP];
__device__ float g_dinv[(size_t)ROWS];
__device__ unsigned g_kmaxu[(size_t)BATCH];
__device__ unsigned g_rowmaxu[(size_t)ROWS];
__device__ unsigned long long g_dq64[(size_t)ROWS];
__device__ unsigned long long g_dk64[(size_t)ROWS];

// second operand/output set for merged launches
struct Dual {
    const bf16 *a2h, *a2l, *b2h, *b2l;
    float* cf2;
    bf16 *c2h, *c2l;
    const float* bias2;
    unsigned* maxu2;
    unsigned long long* sacc2;
};

// ---------------------------------------------------------------------------
// helpers
// ---------------------------------------------------------------------------
__device__ __forceinline__ uint32_t smem_u32(const void* p) {
    uint32_t a;
    asm("{ .reg .u64 t; cvta.to.shared.u64 t, %1; cvt.u32.u64 %0, t; }"
        : "=r"(a) : "l"(p));
    return a;
}

__device__ __forceinline__ void ldm4(uint32_t& r0, uint32_t& r1,
                                     uint32_t& r2, uint32_t& r3, uint32_t a) {
    asm volatile("ldmatrix.sync.aligned.m8n8.x4.shared.b16 {%0,%1,%2,%3}, [%4];"
                 : "=r"(r0), "=r"(r1), "=r"(r2), "=r"(r3) : "r"(a));
}

__device__ __forceinline__ void mma16816(float* c, uint32_t a0, uint32_t a1,
                                         uint32_t a2, uint32_t a3,
                                         uint32_t b0, uint32_t b1) {
    asm volatile(
        "mma.sync.aligned.m16n8k16.row.col.f32.bf16.bf16.f32 "
        "{%0,%1,%2,%3},{%4,%5,%6,%7},{%8,%9},{%0,%1,%2,%3};"
        : "+f"(c[0]), "+f"(c[1]), "+f"(c[2]), "+f"(c[3])
        : "r"(a0), "r"(a1), "r"(a2), "r"(a3), "r"(b0), "r"(b1));
}

__device__ __forceinline__ void cpasync16(uint32_t dst, const bf16* src, int sz) {
    asm volatile("cp.async.cg.shared.global [%0], [%1], 16, %2;"
                 :: "r"(dst), "l"(__cvta_generic_to_global(src)), "r"(sz));
}

__device__ __forceinline__ void splitw(float x, bf16& h, bf16& l) {
    h = __float2bfloat16_rn(x);
    l = __float2bfloat16_rn(x - __bfloat162float(h));
}

__device__ __forceinline__ uint32_t packbf(bf16 a, bf16 b) {
    return (uint32_t)__bfloat16_as_ushort(a)
         | ((uint32_t)__bfloat16_as_ushort(b) << 16);
}

__device__ __forceinline__ void split2p(float x, float y,
                                        uint32_t& ph, uint32_t& pl) {
    bf16 hx, lx, hy, ly;
    splitw(x, hx, lx); splitw(y, hy, ly);
    ph = packbf(hx, hy); pl = packbf(lx, ly);
}

__device__ __forceinline__ unsigned encf(float f) {
    unsigned u = __float_as_uint(f);
    return (u & 0x80000000u) ? ~u : (u | 0x80000000u);
}
__device__ __forceinline__ float decf(unsigned u) {
    unsigned b = (u & 0x80000000u) ? (u ^ 0x80000000u) : ~u;
    return __uint_as_float(b);
}

__device__ __forceinline__ float diag_from_i64(unsigned long long v) {
    return 0.5f * DNORM2 * (float)((double)(long long)v * (1.0 / SSCALE));
}

// ---------------------------------------------------------------------------
// gemm7: NT bf16x3 mma.sync GEMM, 256 threads, 8 warps (4m x 2n), 32x32/warp,
//        CTA tile 128x64, 2-stage cp.async double buffer, 3 CTAs/SM.
//   C[M,N] = A[M,K] * B[N,K]^T ; operands hi/lo bf16, k-contiguous.
//   EPI: 1 +bias[col] f32 | 2 *scale[row] bf16 pair | 4 plain bf16 pair
//        7 +bias[row] bf16 pair
//        9 merged dash: z<zSplit -> f32 + row-max | z>=zSplit -> dual A/C set,
//          f32 + slab-max  (B operand shared)
//       10 merged proj: +bias[col] bf16 pair + row-sumsq i64; dual set for
//          z>=zSplit
//   K % 32 == 0, N even, lda == ldb == K.
// ---------------------------------------------------------------------------
#define TSTRIDE 40
#define AT_B 10240
#define BT_B 5120
#define STAGE_B 30720
#define G7SMEM  (2 * STAGE_B)

template<int EPI>
__global__ void __launch_bounds__(256, 3)
gemm7(const bf16* __restrict__ Ahi, const bf16* __restrict__ Alo,
      const bf16* __restrict__ Bhi, const bf16* __restrict__ Blo,
      float* __restrict__ Cf, bf16* __restrict__ Chi, bf16* __restrict__ Clo,
      int M, int N, int K, int lda, int ldb, int ldc,
      long aT, long aH, long bT, long bH, long cT, long cH, int Hdiv,
      const float* __restrict__ bias, long biasH,
      const float* __restrict__ scale, long scT, long scH,
      unsigned* __restrict__ maxu, int vlim,
      unsigned long long* __restrict__ sacc,
      Dual dp, int zSplit)
{
    extern __shared__ bf16 smb[];
    const uint32_t sb = smem_u32(smb);
    const int tid = threadIdx.x;
    const int wid = tid >> 5, lane = tid & 31;
    const int warp_m = wid >> 1, warp_n = wid & 1;
    const int g = lane >> 2, tg = lane & 3;

    const bool second = (EPI == 9 || EPI == 10) && ((int)blockIdx.z >= zSplit);
    const int bz = second ? (int)blockIdx.z - zSplit : (int)blockIdx.z;
    const int t = bz / Hdiv, h = bz % Hdiv;
    const long aoff = (long)t * aT + (long)h * aH;
    const long boff = (long)t * bT + (long)h * bH;
    const long coff = (long)t * cT + (long)h * cH;

    const bf16* srcAh = (second ? dp.a2h : Ahi) + aoff;
    const bf16* srcAl = (second ? dp.a2l : Alo) + aoff;
    const bf16* srcBh = ((EPI == 10 && second) ? dp.b2h : Bhi) + boff;
    const bf16* srcBl = ((EPI == 10 && second) ? dp.b2l : Blo) + boff;
    float* Cfp = (EPI == 9 && second) ? dp.cf2 : Cf;
    bf16* Chip = (EPI == 10 && second) ? dp.c2h : Chi;
    bf16* Clop = (EPI == 10 && second) ? dp.c2l : Clo;
    const float* biasb = (EPI == 10 && second) ? dp.bias2 : bias;
    unsigned long long* saccp = (EPI == 10 && second) ? dp.sacc2 : sacc;

    const float* biasp  = (EPI == 1 || EPI == 7 || EPI == 10)
                        ? biasb + (long)h * biasH : nullptr;
    const float* scalep = (EPI == 2) ? scale + (long)t * scT + (long)h * scH : nullptr;

    const int m0 = blockIdx.y * 128;
    const int n0 = blockIdx.x * 64;

    const int S = K >> 5;

    auto stage = [&](int s, int bi) {
        const int k0 = s << 5;
        const uint32_t base = sb + (uint32_t)bi * STAGE_B;
#pragma unroll
        for (int c = 0; c < 2; c++) {
            const int id = tid + c * 256;
            const int r = id >> 2, q = id & 3;
            const int gr = m0 + r;
            const int sz = (gr < M) ? 16 : 0;
            const long so = (long)(sz ? gr : m0) * lda + k0 + q * 8;
            const uint32_t d = base + (uint32_t)(r * TSTRIDE + q * 8) * 2;
            cpasync16(d, srcAh + so, sz);
            cpasync16(d + AT_B, srcAl + so, sz);
        }
        {
            const int r = tid >> 2, q = tid & 3;
            const int gr = n0 + r;
            const int sz = (gr < N) ? 16 : 0;
            const long so = (long)(sz ? gr : n0) * ldb + k0 + q * 8;
            const uint32_t d = base + (uint32_t)(2 * AT_B)
                             + (uint32_t)(r * TSTRIDE + q * 8) * 2;
            cpasync16(d, srcBh + so, sz);
            cpasync16(d + BT_B, srcBl + so, sz);
        }
        asm volatile("cp.async.commit_group;" ::: "memory");
    };

    float acc[2][4][4];
#pragma unroll
    for (int i = 0; i < 2; i++)
#pragma unroll
        for (int j = 0; j < 4; j++)
#pragma unroll
            for (int e = 0; e < 4; e++) acc[i][j][e] = 0.f;

    stage(0, 0);
    if (S > 1) stage(1, 1);

    for (int s = 0; s < S; s++) {
        if (s + 1 < S) asm volatile("cp.async.wait_group 1;" ::: "memory");
        else           asm volatile("cp.async.wait_group 0;" ::: "memory");
        __syncthreads();

        const uint32_t base = sb + (uint32_t)(s & 1) * STAGE_B;
#pragma unroll
        for (int ks = 0; ks < 2; ks++) {
            const int ko = ks << 4;
            uint32_t bh[4][2], bl[4][2];
#pragma unroll
            for (int p = 0; p < 2; p++) {
                const int nrow = warp_n * 32 + p * 16 + ((lane >> 4) << 3) + (lane & 7);
                const int kcol = ko + ((lane >> 3) & 1) * 8;
                const uint32_t ab = base + (uint32_t)(2 * AT_B)
                                  + (uint32_t)(nrow * TSTRIDE + kcol) * 2;
                ldm4(bh[2 * p][0], bh[2 * p][1], bh[2 * p + 1][0], bh[2 * p + 1][1], ab);
                ldm4(bl[2 * p][0], bl[2 * p][1], bl[2 * p + 1][0], bl[2 * p + 1][1],
                     ab + BT_B);
            }
#pragma unroll
            for (int ma = 0; ma < 2; ma++) {
                const int mrow = warp_m * 32 + ma * 16 + ((lane >> 3) & 1) * 8 + (lane & 7);
                const int kcol = ko + (lane >> 4) * 8;
                const uint32_t aa = base + (uint32_t)(mrow * TSTRIDE + kcol) * 2;
                uint32_t ah0, ah1, ah2, ah3, al0, al1, al2, al3;
                ldm4(ah0, ah1, ah2, ah3, aa);
                ldm4(al0, al1, al2, al3, aa + AT_B);
#pragma unroll
                for (int nb = 0; nb < 4; nb++) {
                    mma16816(acc[ma][nb], ah0, ah1, ah2, ah3, bh[nb][0], bh[nb][1]);
                    mma16816(acc[ma][nb], ah0, ah1, ah2, ah3, bl[nb][0], bl[nb][1]);
                    mma16816(acc[ma][nb], al0, al1, al2, al3, bh[nb][0], bh[nb][1]);
                }
            }
        }
        __syncthreads();
        if (s + 2 < S) stage(s + 2, s & 1);
    }

    // ---- epilogue (N even; col and col+1 in-bounds together)
    float slabmax = -3.4e38f;
#pragma unroll
    for (int ma = 0; ma < 2; ma++) {
#pragma unroll
        for (int hf = 0; hf < 2; hf++) {
            const int row = m0 + warp_m * 32 + ma * 16 + g + hf * 8;
            float rowmax = -3.4e38f;
            float ss = 0.f;
            const bool rok = row < M;
            const float sc = (EPI == 2 && rok) ? scalep[row] : 1.f;
            const float rb = (EPI == 7 && rok) ? biasp[row] : 0.f;
#pragma unroll
            for (int nb = 0; nb < 4; nb++) {
                const int col = n0 + warp_n * 32 + nb * 8 + 2 * tg;
                if (!rok || col >= N) continue;
                float v0 = acc[ma][nb][hf * 2 + 0];
                float v1 = acc[ma][nb][hf * 2 + 1];
                if (EPI == 1 || EPI == 10) { v0 += biasp[col]; v1 += biasp[col + 1]; }
                if (EPI == 7) { v0 += rb; v1 += rb; }
                if (EPI == 2) { v0 *= sc; v1 *= sc; }
                if (EPI == 10) ss += v0 * v0 + v1 * v1;
                const long idx = coff + (long)row * ldc + col;
                if (EPI == 1 || EPI == 9) {
                    *(float2*)&Cfp[idx] = make_float2(v0, v1);
                    if (EPI == 9) {
                        if (col < vlim) {
                            if (second) slabmax = fmaxf(slabmax, v0);
                            else        rowmax  = fmaxf(rowmax, v0);
                        }
                        if (col + 1 < vlim) {
                            if (second) slabmax = fmaxf(slabmax, v1);
                            else        rowmax  = fmaxf(rowmax, v1);
                        }
                    }
                } else {
                    uint32_t ph, pl;
                    split2p(v0, v1, ph, pl);
                    *(uint32_t*)&Chip[idx] = ph;
                    *(uint32_t*)&Clop[idx] = pl;
                }
            }
            if (EPI == 9 && !second) {
                rowmax = fmaxf(rowmax, __shfl_xor_sync(0xffffffffu, rowmax, 1));
                rowmax = fmaxf(rowmax, __shfl_xor_sync(0xffffffffu, rowmax, 2));
                if (tg == 0 && rok)
                    atomicMax(&maxu[(long)bz * M + row], encf(rowmax));
            }
            if (EPI == 10) {
                ss += __shfl_xor_sync(0xffffffffu, ss, 1);
                ss += __shfl_xor_sync(0xffffffffu, ss, 2);
                if (tg == 0 && rok)
                    atomicAdd(&saccp[(long)bz * M + row],
                              (unsigned long long)(long long)((double)ss * SSCALE));
            }
        }
    }
    if (EPI == 9 && second) {
#pragma unroll
        for (int o = 16; o > 0; o >>= 1)
            slabmax = fmaxf(slabmax, __shfl_xor_sync(0xffffffffu, slabmax, o));
        if (lane == 0) atomicMax(&dp.maxu2[bz], encf(slabmax));
    }
}

// ---------------------------------------------------------------------------
// conversion / reset passes
// ---------------------------------------------------------------------------
__global__ void reset_k(unsigned* __restrict__ kmaxu, unsigned* __restrict__ rowmaxu,
                        unsigned long long* __restrict__ dq,
                        unsigned long long* __restrict__ dk)
{
    int i = blockIdx.x * blockDim.x + threadIdx.x;
    if (i < BATCH) kmaxu[i] = 0u;
    if (i < ROWS) { rowmaxu[i] = 0u; dq[i] = 0ull; dk[i] = 0ull; }
}

// vectorized split: 8 elems/thread (n % 8 == 0)
__global__ void split_k(const float* __restrict__ s, bf16* __restrict__ h,
                        bf16* __restrict__ l, size_t n, float scl)
{
    size_t i8 = ((size_t)blockIdx.x * blockDim.x + threadIdx.x) * 8;
    if (i8 < n) {
        float4 x0 = *(const float4*)(s + i8);
        float4 x1 = *(const float4*)(s + i8 + 4);
        uint32_t ph0, pl0, ph1, pl1, ph2, pl2, ph3, pl3;
        split2p(x0.x * scl, x0.y * scl, ph0, pl0);
        split2p(x0.z * scl, x0.w * scl, ph1, pl1);
        split2p(x1.x * scl, x1.y * scl, ph2, pl2);
        split2p(x1.z * scl, x1.w * scl, ph3, pl3);
        *(uint4*)(h + i8) = make_uint4(ph0, ph1, ph2, ph3);
        *(uint4*)(l + i8) = make_uint4(pl0, pl1, pl2, pl3);
    }
}

__global__ void wsplit_k(const float* __restrict__ W, bf16* __restrict__ h,
                         bf16* __restrict__ l)
{
    int i = blockIdx.x * blockDim.x + threadIdx.x;
    if (i < DDIM * HDCAT) {
        int d = i / HDCAT, fp = i % HDCAT;
        int hh = fp >> 8, e = fp & 255;
        float x = W[(size_t)d * HDCAT + e * 8 + hh];
        bf16 hb, lb; splitw(x, hb, lb);
        h[i] = hb; l[i] = lb;
    }
}

// fp32 [z][R][C] -> bf16 hi/lo [z][C][R] (weights, small)
__global__ void tsplit_k(const float* __restrict__ src, bf16* __restrict__ hi,
                         bf16* __restrict__ lo, int R, int C)
{
    __shared__ float sm[32][33];
    const int z = blockIdx.z;
    const int c0 = blockIdx.x * 32, r0 = blockIdx.y * 32;
    const float* s = src + (size_t)z * R * C;
    bf16* ho = hi + (size_t)z * R * C;
    bf16* lv = lo + (size_t)z * R * C;
    const int tx = threadIdx.x, ty = threadIdx.y;
    for (int i = ty; i < 32; i += 8)
        sm[i][tx] = s[(size_t)(r0 + i) * C + c0 + tx];
    __syncthreads();
    for (int i = ty; i < 32; i += 8) {
        float x = sm[tx][i];
        bf16 hb, lb; splitw(x, hb, lb);
        ho[(size_t)(c0 + i) * R + r0 + tx] = hb;
        lv[(size_t)(c0 + i) * R + r0 + tx] = lb;
    }
}

// ---------------------------------------------------------------------------
// feature-map / reduction kernels
// ---------------------------------------------------------------------------
__global__ void __launch_bounds__(256)
qexp2_k(const float* __restrict__ qp, const unsigned long long* __restrict__ dq,
        const unsigned* __restrict__ rowmaxu,
        const float* __restrict__ ksum, bf16* __restrict__ oh,
        bf16* __restrict__ ol, float* __restrict__ dinv)
{
    const size_t r = blockIdx.x;
    const int b = (int)(r >> 10);
    const float* prow = qp + r * NBP;
    const float* ks = ksum + (size_t)b * NBP;
    const int tid = threadIdx.x;
    __shared__ float red[256];

    const float c = diag_from_i64(dq[r]) + decf(rowmaxu[r]);

    float dot = 0.f;
    for (int j = tid * 4; j < NBP; j += 1024) {
        float4 p = *(const float4*)(prow + j);
        float v0 = (j + 0 < NBF) ? RATIO * (__expf(p.x - c) + EPSF) : 0.f;
        float v1 = (j + 1 < NBF) ? RATIO * (__expf(p.y - c) + EPSF) : 0.f;
        float v2 = (j + 2 < NBF) ? RATIO * (__expf(p.z - c) + EPSF) : 0.f;
        float v3 = (j + 3 < NBF) ? RATIO * (__expf(p.w - c) + EPSF) : 0.f;
        uint32_t ph0, pl0, ph1, pl1;
        split2p(v0, v1, ph0, pl0);
        split2p(v2, v3, ph1, pl1);
        *(uint2*)(oh + r * NBP + j) = make_uint2(ph0, ph1);
        *(uint2*)(ol + r * NBP + j) = make_uint2(pl0, pl1);
        float4 kv = *(const float4*)(ks + j);
        dot += v0 * kv.x + v1 * kv.y + v2 * kv.z + v3 * kv.w;
    }
    red[tid] = dot;
    __syncthreads();
    for (int s = 128; s > 0; s >>= 1) {
        if (tid < s) red[tid] += red[tid + s];
        __syncthreads();
    }
    if (tid == 0) dinv[r] = 1.0f / red[0];
}

__global__ void __launch_bounds__(256)
ktexp_k(const float* __restrict__ kp, const unsigned long long* __restrict__ dk,
        const unsigned* __restrict__ kmaxu, bf16* __restrict__ th,
        bf16* __restrict__ tl, float* __restrict__ part)
{
    __shared__ float sm[32][132];
    const int b = blockIdx.z;
    const int m0 = blockIdx.x * 32, n0 = blockIdx.y * 128;
    const int tid = threadIdx.x;
    const float km = decf(kmaxu[b]);

    {
        const int n = tid >> 1, half = tid & 1;
        const float dkv = diag_from_i64(dk[(size_t)b * NPT + n0 + n]);
        const float* src = kp + ((size_t)b * NPT + n0 + n) * NBP + m0 + half * 16;
#pragma unroll
        for (int c4 = 0; c4 < 4; c4++) {
            float4 xx = *(const float4*)(src + c4 * 4);
            const int mb = m0 + half * 16 + c4 * 4;
            float vv[4] = {xx.x, xx.y, xx.z, xx.w};
#pragma unroll
            for (int e = 0; e < 4; e++)
                sm[half * 16 + c4 * 4 + e][n] =
                    (mb + e < NBF) ? RATIO * (__expf(vv[e] - dkv - km) + EPSF) : 0.f;
        }
    }
    __syncthreads();

    {
        const int w = tid >> 5, lane = tid & 31;
#pragma unroll
        for (int i = 0; i < 4; i++) {
            const int m = w * 4 + i;
            float4 v = *(const float4*)&sm[m][4 * lane];
            uint32_t ph0, pl0, ph1, pl1;
            split2p(v.x, v.y, ph0, pl0);
            split2p(v.z, v.w, ph1, pl1);
            const size_t obase = ((size_t)b * NBP + m0 + m) * NPT + n0 + 4 * lane;
            *(uint2*)&th[obase] = make_uint2(ph0, ph1);
            *(uint2*)&tl[obase] = make_uint2(pl0, pl1);
            float s = v.x + v.y + v.z + v.w;
#pragma unroll
            for (int o = 16; o > 0; o >>= 1)
                s += __shfl_xor_sync(0xffffffffu, s, o);
            if (lane == 0)
                part[((size_t)b * 8 + blockIdx.y) * NBP + m0 + m] = s;
        }
    }
}

__global__ void ksum2_k(const float* __restrict__ part, float* __restrict__ ksum)
{
    const int b = blockIdx.y;
    const int m = blockIdx.x * blockDim.x + threadIdx.x;
    if (m >= NBP) return;
    float s = 0.f;
#pragma unroll
    for (int j = 0; j < 8; j++)
        s += part[((size_t)b * 8 + j) * NBP + m];
    ksum[(size_t)b * NBP + m] = s;
}

// ---------------------------------------------------------------------------
// Launch
// ---------------------------------------------------------------------------
#define GETP(var, sym) cudaGetSymbolAddress((void**)&var, sym)

extern "C" void kernel_launch(void* const* d_in, const int* in_sizes, int n_in,
                              void* d_out, int out_size)
{
    const float* q     = (const float*)d_in[0];
    const float* k     = (const float*)d_in[1];
    const float* v     = (const float*)d_in[2];
    const float* Wq    = (const float*)d_in[3];
    const float* bq    = (const float*)d_in[4];
    const float* Wk    = (const float*)d_in[5];
    const float* bk    = (const float*)d_in[6];
    const float* Wv    = (const float*)d_in[7];
    const float* bv    = (const float*)d_in[8];
    const float* W_out = (const float*)d_in[9];
    const float* b_out = (const float*)d_in[10];
    const float* proj  = (const float*)d_in[11];
    float* out = (float*)d_out;

    float *qp, *kp, *ksum, *kpart, *dinv;
    unsigned *kmaxu, *rowmaxu;
    unsigned long long *dq64, *dk64;
    bf16 *qin_h, *qin_l, *kin_h, *kin_l, *vin_h, *vin_l;
    bf16 *wtq_h, *wtq_l, *wtk_h, *wtk_l, *wtv_h, *wtv_l;
    bf16 *pr_h, *pr_l, *wo_h, *wo_l;
    bf16 *qall_h, *qall_l, *kall_h, *kall_l, *vt_h, *vt_l;
    bf16 *qph, *qpl, *kpT_h, *kpT_l, *ctxT_h, *ctxT_l, *outs_h, *outs_l;

    GETP(qp, g_qp); GETP(kp, g_kp);
    GETP(qin_h, g_qin_h); GETP(qin_l, g_qin_l);
    GETP(kin_h, g_kin_h); GETP(kin_l, g_kin_l);
    GETP(vin_h, g_vin_h); GETP(vin_l, g_vin_l);
    GETP(wtq_h, g_wtq_h); GETP(wtq_l, g_wtq_l);
    GETP(wtk_h, g_wtk_h); GETP(wtk_l, g_wtk_l);
    GETP(wtv_h, g_wtv_h); GETP(wtv_l, g_wtv_l);
    GETP(pr_h, g_pr_h);   GETP(pr_l, g_pr_l);
    GETP(wo_h, g_wo_h);   GETP(wo_l, g_wo_l);
    GETP(qall_h, g_qall_h); GETP(qall_l, g_qall_l);
    GETP(kall_h, g_kall_h); GETP(kall_l, g_kall_l);
    GETP(vt_h, g_vt_h);     GETP(vt_l, g_vt_l);
    GETP(qph, g_qph);       GETP(qpl, g_qpl);
    GETP(kpT_h, g_kpT_h);   GETP(kpT_l, g_kpT_l);
    GETP(ctxT_h, g_ctxT_h); GETP(ctxT_l, g_ctxT_l);
    GETP(outs_h, g_outs_h); GETP(outs_l, g_outs_l);
    GETP(ksum, g_ksum); GETP(kpart, g_kpart);
    GETP(dinv, g_dinv); GETP(kmaxu, g_kmaxu); GETP(rowmaxu, g_rowmaxu);
    GETP(dq64, g_dq64); GETP(dk64, g_dk64);

    cudaFuncSetAttribute(gemm7<1>,  cudaFuncAttributeMaxDynamicSharedMemorySize, G7SMEM);
    cudaFuncSetAttribute(gemm7<2>,  cudaFuncAttributeMaxDynamicSharedMemorySize, G7SMEM);
    cudaFuncSetAttribute(gemm7<4>,  cudaFuncAttributeMaxDynamicSharedMemorySize, G7SMEM);
    cudaFuncSetAttribute(gemm7<7>,  cudaFuncAttributeMaxDynamicSharedMemorySize, G7SMEM);
    cudaFuncSetAttribute(gemm7<9>,  cudaFuncAttributeMaxDynamicSharedMemorySize, G7SMEM);
    cudaFuncSetAttribute(gemm7<10>, cudaFuncAttributeMaxDynamicSharedMemorySize, G7SMEM);

    Dual d0 = {};

    // ---- 0) reset accumulators (graph replays!) + operand splits
    reset_k<<<(ROWS + 255) / 256, 256>>>(kmaxu, rowmaxu, dq64, dk64);
    {
        const size_t nin = (size_t)TT * NPT * DDIM;
        split_k<<<(unsigned)((nin / 8 + 255) / 256), 256>>>(q, qin_h, qin_l, nin, 1.f);
        split_k<<<(unsigned)((nin / 8 + 255) / 256), 256>>>(k, kin_h, kin_l, nin, 1.f);
        split_k<<<(unsigned)((nin / 8 + 255) / 256), 256>>>(v, vin_h, vin_l, nin, 1.f);
        dim3 tg(8, 8, 8), tb(32, 8);
        tsplit_k<<<tg, tb>>>(Wq, wtq_h, wtq_l, DDIM, DDIM);
        tsplit_k<<<tg, tb>>>(Wk, wtk_h, wtk_l, DDIM, DDIM);
        tsplit_k<<<tg, tb>>>(Wv, wtv_h, wtv_l, DDIM, DDIM);
        const size_t npr = (size_t)NBF * DDIM;
        split_k<<<(unsigned)((npr / 8 + 255) / 256), 256>>>(proj, pr_h, pr_l, npr, DNORM);
        wsplit_k<<<(DDIM * HDCAT + 255) / 256, 256>>>(W_out, wo_h, wo_l);
    }

    // ---- 1) merged q+k projections (EPI 10; z<64 -> q, z>=64 -> k)
    {
        Dual dk_ = d0;
        dk_.a2h = kin_h; dk_.a2l = kin_l;
        dk_.b2h = wtk_h; dk_.b2l = wtk_l;
        dk_.c2h = kall_h; dk_.c2l = kall_l;
        dk_.bias2 = bk; dk_.sacc2 = dk64;
        dim3 grid(4, 8, 2 * BATCH);
        gemm7<10><<<grid, 256, G7SMEM>>>(qin_h, qin_l, wtq_h, wtq_l,
            nullptr, qall_h, qall_l,
            NPT, DDIM, DDIM, DDIM, DDIM, DDIM,
            (long)NPT * DDIM, 0, 0, (long)DDIM * DDIM,
            (long)HH * NPT * DDIM, (long)NPT * DDIM, HH,
            bq, DDIM, nullptr, 0, 0, nullptr, 0, dq64, dk_, BATCH);
    }
    // v projection directly transposed: vt[b][e][n] (EPI 7: row bias)
    {
        dim3 grid(NPT / 64, 2, BATCH);
        gemm7<7><<<grid, 256, G7SMEM>>>(wtv_h, wtv_l, vin_h, vin_l,
            nullptr, vt_h, vt_l,
            DDIM, NPT, DDIM, DDIM, DDIM, NPT,
            0, (long)DDIM * DDIM, (long)NPT * DDIM, 0,
            (long)HH * DDIM * NPT, (long)DDIM * NPT, HH,
            bv, DDIM, nullptr, 0, 0, nullptr, 0, nullptr, d0, 1 << 30);
    }

    // ---- 2) merged dash (EPI 9; z<64 -> q rows+rowmax, z>=64 -> k+slabmax)
    {
        Dual dd = d0;
        dd.a2h = kall_h; dd.a2l = kall_l;
        dd.cf2 = kp; dd.maxu2 = kmaxu;
        dim3 grid(NBP / 64, 8, 2 * BATCH);
        gemm7<9><<<grid, 256, G7SMEM>>>(qall_h, qall_l, pr_h, pr_l,
            qp, nullptr, nullptr,
            NPT, NBP, DDIM, DDIM, DDIM, NBP,
            (long)NPT * DDIM, 0, 0, 0, (long)NPT * NBP, 0, 1,
            nullptr, 0, nullptr, 0, 0, rowmaxu, NBF, nullptr, dd, BATCH);
    }

    // ---- 3) k-side feature map chain, then fused q-exp + d_inv
    ktexp_k<<<dim3(NBP / 32, 8, BATCH), 256>>>(kp, dk64, kmaxu, kpT_h, kpT_l, kpart);
    ksum2_k<<<dim3((NBP + 255) / 256, BATCH), 256>>>(kpart, ksum);
    qexp2_k<<<ROWS, 256>>>(qp, dq64, rowmaxu, ksum, qph, qpl, dinv);

    // ---- 4) ctxT[b][e][m] = vt[b] * kpT[b]^T (per-slab: Hdiv = 1)
    {
        dim3 grid(NBP / 64, 2, BATCH);
        gemm7<4><<<grid, 256, G7SMEM>>>(vt_h, vt_l, kpT_h, kpT_l,
            nullptr, ctxT_h, ctxT_l,
            DDIM, NBP, NPT, NPT, NPT, NBP,
            (long)DDIM * NPT, 0, (long)NBP * NPT, 0, (long)DDIM * NBP, 0, 1,
            nullptr, 0, nullptr, 0, 0, nullptr, 0, nullptr, d0, 1 << 30);
    }

    // ---- 5) out: [t][n][h*256+e] contiguous bf16-pair store, *dinv (Hdiv = HH)
    {
        dim3 grid(4, 8, BATCH);
        gemm7<2><<<grid, 256, G7SMEM>>>(qph, qpl, ctxT_h, ctxT_l,
            nullptr, outs_h, outs_l,
            NPT, DDIM, NBP, NBP, NBP, HDCAT,
            (long)HH * NPT * NBP, (long)NPT * NBP,
            (long)HH * DDIM * NBP, (long)DDIM * NBP,
            (long)NPT * HDCAT, (long)DDIM, HH,
            nullptr, 0, dinv, (long)HH * NPT, (long)NPT, nullptr, 0, nullptr,
            d0, 1 << 30);
    }

    // ---- 6) final: rep[8192][256] = outs * wr^T + b_out (wr = permuted W_out)
    {
        dim3 grid(4, 64, 1);
        gemm7<1><<<grid, 256, G7SMEM>>>(outs_h, outs_l, wo_h, wo_l,
            out, nullptr, nullptr,
            TT * NPT, DDIM, HDCAT, HDCAT, HDCAT, DDIM,
            0, 0, 0, 0, 0, 0, 1,
            b_out, 0, nullptr, 0, 0, nullptr, 0, nullptr, d0, 1 << 30);
    }
}

// round 16
// speedup vs baseline: 3.9193x; 1.0086x over previous
#include <cuda_runtime.h>
#include <cuda_bf16.h>
#include <cstdint>
#include <math.h>

// ---------------------------------------------------------------------------
// Problem constants (T=8, N=M=1024, H=8, D=256, NB = int(256*ln 256) = 1419)
// ---------------------------------------------------------------------------
#define TT   8
#define NPT  1024
#define HH   8
#define DDIM 256
#define NBF  1419
#define NBP  1472              // padded to multiple of 64
#define ROWS (TT * HH * NPT)   // 65536
#define BATCH (TT * HH)        // 64
#define HDCAT (HH * DDIM)      // 2048

#define DNORM   0.25f
#define DNORM2  0.0625f
#define EPSF    1e-4f
#define RATIO   0.026547529f   // 1/sqrt(1419)
#define SSCALE  68719476736.0  // 2^36 fixed-point scale for diag accumulation

typedef __nv_bfloat16 bf16;

// ---------------------------------------------------------------------------
// Scratch (device globals; zero-init at load -> never-written pads stay 0)
// ---------------------------------------------------------------------------
__device__ float g_qp[(size_t)ROWS * NBP];
__device__ float g_kp[(size_t)ROWS * NBP];
__device__ bf16 g_qin_h[(size_t)TT * NPT * DDIM],  g_qin_l[(size_t)TT * NPT * DDIM];
__device__ bf16 g_kin_h[(size_t)TT * NPT * DDIM],  g_kin_l[(size_t)TT * NPT * DDIM];
__device__ bf16 g_vin_h[(size_t)TT * NPT * DDIM],  g_vin_l[(size_t)TT * NPT * DDIM];
__device__ bf16 g_wtq_h[(size_t)HH * DDIM * DDIM], g_wtq_l[(size_t)HH * DDIM * DDIM];
__device__ bf16 g_wtk_h[(size_t)HH * DDIM * DDIM], g_wtk_l[(size_t)HH * DDIM * DDIM];
__device__ bf16 g_wtv_h[(size_t)HH * DDIM * DDIM], g_wtv_l[(size_t)HH * DDIM * DDIM];
__device__ bf16 g_pr_h[(size_t)NBP * DDIM],        g_pr_l[(size_t)NBP * DDIM];
__device__ bf16 g_wo_h[(size_t)DDIM * HDCAT],      g_wo_l[(size_t)DDIM * HDCAT];
__device__ bf16 g_qall_h[(size_t)ROWS * DDIM],     g_qall_l[(size_t)ROWS * DDIM];
__device__ bf16 g_kall_h[(size_t)ROWS * DDIM],     g_kall_l[(size_t)ROWS * DDIM];
__device__ bf16 g_vt_h[(size_t)ROWS * DDIM],       g_vt_l[(size_t)ROWS * DDIM];
__device__ bf16 g_qph[(size_t)ROWS * NBP],         g_qpl[(size_t)ROWS * NBP];
__device__ bf16 g_kpT_h[(size_t)BATCH * NBP * NPT], g_kpT_l[(size_t)BATCH * NBP * NPT];
__device__ bf16 g_ctxT_h[(size_t)BATCH * DDIM * NBP], g_ctxT_l[(size_t)BATCH * DDIM * NBP];
__device__ bf16 g_outs_h[(size_t)TT * NPT * HDCAT], g_outs_l[(size_t)TT * NPT * HDCAT];
__device__ float g_ksum[(size_t)BATCH * NBP];
__device__ float g_kpart[(size_t)BATCH * 8 * NBP];
__device__ float g_dinv[(size_t)ROWS];
__device__ unsigned g_kmaxu[(size_t)BATCH];
__device__ unsigned g_rowmaxu[(size_t)ROWS];
__device__ unsigned long long g_dq64[(size_t)ROWS];
__device__ unsigned long long g_dk64[(size_t)ROWS];

// second operand/output set for merged launches
struct Dual {
    const bf16 *a2h, *a2l, *b2h, *b2l;
    float* cf2;
    bf16 *c2h, *c2l;
    const float* bias2;
    unsigned* maxu2;
    unsigned long long* sacc2;
};

// ---------------------------------------------------------------------------
// helpers
// ---------------------------------------------------------------------------
__device__ __forceinline__ uint32_t smem_u32(const void* p) {
    uint32_t a;
    asm("{ .reg .u64 t; cvta.to.shared.u64 t, %1; cvt.u32.u64 %0, t; }"
        : "=r"(a) : "l"(p));
    return a;
}

__device__ __forceinline__ void ldm4(uint32_t& r0, uint32_t& r1,
                                     uint32_t& r2, uint32_t& r3, uint32_t a) {
    asm volatile("ldmatrix.sync.aligned.m8n8.x4.shared.b16 {%0,%1,%2,%3}, [%4];"
                 : "=r"(r0), "=r"(r1), "=r"(r2), "=r"(r3) : "r"(a));
}

__device__ __forceinline__ void mma16816(float* c, uint32_t a0, uint32_t a1,
                                         uint32_t a2, uint32_t a3,
                                         uint32_t b0, uint32_t b1) {
    asm volatile(
        "mma.sync.aligned.m16n8k16.row.col.f32.bf16.bf16.f32 "
        "{%0,%1,%2,%3},{%4,%5,%6,%7},{%8,%9},{%0,%1,%2,%3};"
        : "+f"(c[0]), "+f"(c[1]), "+f"(c[2]), "+f"(c[3])
        : "r"(a0), "r"(a1), "r"(a2), "r"(a3), "r"(b0), "r"(b1));
}

__device__ __forceinline__ void cpasync16(uint32_t dst, const bf16* src, int sz) {
    asm volatile("cp.async.cg.shared.global [%0], [%1], 16, %2;"
                 :: "r"(dst), "l"(__cvta_generic_to_global(src)), "r"(sz));
}

__device__ __forceinline__ void splitw(float x, bf16& h, bf16& l) {
    h = __float2bfloat16_rn(x);
    l = __float2bfloat16_rn(x - __bfloat162float(h));
}

__device__ __forceinline__ uint32_t packbf(bf16 a, bf16 b) {
    return (uint32_t)__bfloat16_as_ushort(a)
         | ((uint32_t)__bfloat16_as_ushort(b) << 16);
}

__device__ __forceinline__ void split2p(float x, float y,
                                        uint32_t& ph, uint32_t& pl) {
    bf16 hx, lx, hy, ly;
    splitw(x, hx, lx); splitw(y, hy, ly);
    ph = packbf(hx, hy); pl = packbf(lx, ly);
}

__device__ __forceinline__ unsigned encf(float f) {
    unsigned u = __float_as_uint(f);
    return (u & 0x80000000u) ? ~u : (u | 0x80000000u);
}
__device__ __forceinline__ float decf(unsigned u) {
    unsigned b = (u & 0x80000000u) ? (u ^ 0x80000000u) : ~u;
    return __uint_as_float(b);
}

__device__ __forceinline__ float diag_from_i64(unsigned long long v) {
    return 0.5f * DNORM2 * (float)((double)(long long)v * (1.0 / SSCALE));
}

// ---------------------------------------------------------------------------
// gemm7: NT bf16x3 mma.sync GEMM, 256 threads, 8 warps (4m x 2n), 32x32/warp,
//        CTA tile 128x64, 2-stage cp.async double buffer, 3 CTAs/SM.
//   C[M,N] = A[M,K] * B[N,K]^T ; operands hi/lo bf16, k-contiguous.
//   EPI: 1 +bias[col] f32 | 2 *scale[row] bf16 pair | 4 plain bf16 pair
//        7 +bias[row] bf16 pair
//        9 merged dash: z<zSplit -> f32 + row-max | z>=zSplit -> dual A/C set,
//          f32 + slab-max  (B operand shared)
//       10 merged proj: +bias[col] bf16 pair + row-sumsq i64; dual set for
//          z>=zSplit
//   K % 32 == 0, N even, lda == ldb == K.
// ---------------------------------------------------------------------------
#define TSTRIDE 40
#define AT_B 10240
#define BT_B 5120
#define STAGE_B 30720
#define G7SMEM  (2 * STAGE_B)

template<int EPI>
__global__ void __launch_bounds__(256, 3)
gemm7(const bf16* __restrict__ Ahi, const bf16* __restrict__ Alo,
      const bf16* __restrict__ Bhi, const bf16* __restrict__ Blo,
      float* __restrict__ Cf, bf16* __restrict__ Chi, bf16* __restrict__ Clo,
      int M, int N, int K, int lda, int ldb, int ldc,
      long aT, long aH, long bT, long bH, long cT, long cH, int Hdiv,
      const float* __restrict__ bias, long biasH,
      const float* __restrict__ scale, long scT, long scH,
      unsigned* __restrict__ maxu, int vlim,
      unsigned long long* __restrict__ sacc,
      Dual dp, int zSplit)
{
    extern __shared__ bf16 smb[];
    const uint32_t sb = smem_u32(smb);
    const int tid = threadIdx.x;
    const int wid = tid >> 5, lane = tid & 31;
    const int warp_m = wid >> 1, warp_n = wid & 1;
    const int g = lane >> 2, tg = lane & 3;

    const bool second = (EPI == 9 || EPI == 10) && ((int)blockIdx.z >= zSplit);
    const int bz = second ? (int)blockIdx.z - zSplit : (int)blockIdx.z;
    const int t = bz / Hdiv, h = bz % Hdiv;
    const long aoff = (long)t * aT + (long)h * aH;
    const long boff = (long)t * bT + (long)h * bH;
    const long coff = (long)t * cT + (long)h * cH;

    const bf16* srcAh = (second ? dp.a2h : Ahi) + aoff;
    const bf16* srcAl = (second ? dp.a2l : Alo) + aoff;
    const bf16* srcBh = ((EPI == 10 && second) ? dp.b2h : Bhi) + boff;
    const bf16* srcBl = ((EPI == 10 && second) ? dp.b2l : Blo) + boff;
    float* Cfp = (EPI == 9 && second) ? dp.cf2 : Cf;
    bf16* Chip = (EPI == 10 && second) ? dp.c2h : Chi;
    bf16* Clop = (EPI == 10 && second) ? dp.c2l : Clo;
    const float* biasb = (EPI == 10 && second) ? dp.bias2 : bias;
    unsigned long long* saccp = (EPI == 10 && second) ? dp.sacc2 : sacc;

    const float* biasp  = (EPI == 1 || EPI == 7 || EPI == 10)
                        ? biasb + (long)h * biasH : nullptr;
    const float* scalep = (EPI == 2) ? scale + (long)t * scT + (long)h * scH : nullptr;

    const int m0 = blockIdx.y * 128;
    const int n0 = blockIdx.x * 64;

    const int S = K >> 5;

    auto stage = [&](int s, int bi) {
        const int k0 = s << 5;
        const uint32_t base = sb + (uint32_t)bi * STAGE_B;
#pragma unroll
        for (int c = 0; c < 2; c++) {
            const int id = tid + c * 256;
            const int r = id >> 2, q = id & 3;
            const int gr = m0 + r;
            const int sz = (gr < M) ? 16 : 0;
            const long so = (long)(sz ? gr : m0) * lda + k0 + q * 8;
            const uint32_t d = base + (uint32_t)(r * TSTRIDE + q * 8) * 2;
            cpasync16(d, srcAh + so, sz);
            cpasync16(d + AT_B, srcAl + so, sz);
        }
        {
            const int r = tid >> 2, q = tid & 3;
            const int gr = n0 + r;
            const int sz = (gr < N) ? 16 : 0;
            const long so = (long)(sz ? gr : n0) * ldb + k0 + q * 8;
            const uint32_t d = base + (uint32_t)(2 * AT_B)
                             + (uint32_t)(r * TSTRIDE + q * 8) * 2;
            cpasync16(d, srcBh + so, sz);
            cpasync16(d + BT_B, srcBl + so, sz);
        }
        asm volatile("cp.async.commit_group;" ::: "memory");
    };

    float acc[2][4][4];
#pragma unroll
    for (int i = 0; i < 2; i++)
#pragma unroll
        for (int j = 0; j < 4; j++)
#pragma unroll
            for (int e = 0; e < 4; e++) acc[i][j][e] = 0.f;

    stage(0, 0);
    if (S > 1) stage(1, 1);

    for (int s = 0; s < S; s++) {
        if (s + 1 < S) asm volatile("cp.async.wait_group 1;" ::: "memory");
        else           asm volatile("cp.async.wait_group 0;" ::: "memory");
        __syncthreads();

        const uint32_t base = sb + (uint32_t)(s & 1) * STAGE_B;
#pragma unroll
        for (int ks = 0; ks < 2; ks++) {
            const int ko = ks << 4;
            uint32_t bh[4][2], bl[4][2];
#pragma unroll
            for (int p = 0; p < 2; p++) {
                const int nrow = warp_n * 32 + p * 16 + ((lane >> 4) << 3) + (lane & 7);
                const int kcol = ko + ((lane >> 3) & 1) * 8;
                const uint32_t ab = base + (uint32_t)(2 * AT_B)
                                  + (uint32_t)(nrow * TSTRIDE + kcol) * 2;
                ldm4(bh[2 * p][0], bh[2 * p][1], bh[2 * p + 1][0], bh[2 * p + 1][1], ab);
                ldm4(bl[2 * p][0], bl[2 * p][1], bl[2 * p + 1][0], bl[2 * p + 1][1],
                     ab + BT_B);
            }
#pragma unroll
            for (int ma = 0; ma < 2; ma++) {
                const int mrow = warp_m * 32 + ma * 16 + ((lane >> 3) & 1) * 8 + (lane & 7);
                const int kcol = ko + (lane >> 4) * 8;
                const uint32_t aa = base + (uint32_t)(mrow * TSTRIDE + kcol) * 2;
                uint32_t ah0, ah1, ah2, ah3, al0, al1, al2, al3;
                ldm4(ah0, ah1, ah2, ah3, aa);
                ldm4(al0, al1, al2, al3, aa + AT_B);
#pragma unroll
                for (int nb = 0; nb < 4; nb++) {
                    mma16816(acc[ma][nb], ah0, ah1, ah2, ah3, bh[nb][0], bh[nb][1]);
                    mma16816(acc[ma][nb], ah0, ah1, ah2, ah3, bl[nb][0], bl[nb][1]);
                    mma16816(acc[ma][nb], al0, al1, al2, al3, bh[nb][0], bh[nb][1]);
                }
            }
        }
        __syncthreads();
        if (s + 2 < S) stage(s + 2, s & 1);
    }

    // ---- epilogue (N even; col and col+1 in-bounds together)
    float slabmax = -3.4e38f;
#pragma unroll
    for (int ma = 0; ma < 2; ma++) {
#pragma unroll
        for (int hf = 0; hf < 2; hf++) {
            const int row = m0 + warp_m * 32 + ma * 16 + g + hf * 8;
            float rowmax = -3.4e38f;
            float ss = 0.f;
            const bool rok = row < M;
            const float sc = (EPI == 2 && rok) ? scalep[row] : 1.f;
            const float rb = (EPI == 7 && rok) ? biasp[row] : 0.f;
#pragma unroll
            for (int nb = 0; nb < 4; nb++) {
                const int col = n0 + warp_n * 32 + nb * 8 + 2 * tg;
                if (!rok || col >= N) continue;
                float v0 = acc[ma][nb][hf * 2 + 0];
                float v1 = acc[ma][nb][hf * 2 + 1];
                if (EPI == 1 || EPI == 10) { v0 += biasp[col]; v1 += biasp[col + 1]; }
                if (EPI == 7) { v0 += rb; v1 += rb; }
                if (EPI == 2) { v0 *= sc; v1 *= sc; }
                if (EPI == 10) ss += v0 * v0 + v1 * v1;
                const long idx = coff + (long)row * ldc + col;
                if (EPI == 1 || EPI == 9) {
                    *(float2*)&Cfp[idx] = make_float2(v0, v1);
                    if (EPI == 9) {
                        if (col < vlim) {
                            if (second) slabmax = fmaxf(slabmax, v0);
                            else        rowmax  = fmaxf(rowmax, v0);
                        }
                        if (col + 1 < vlim) {
                            if (second) slabmax = fmaxf(slabmax, v1);
                            else        rowmax  = fmaxf(rowmax, v1);
                        }
                    }
                } else {
                    uint32_t ph, pl;
                    split2p(v0, v1, ph, pl);
                    *(uint32_t*)&Chip[idx] = ph;
                    *(uint32_t*)&Clop[idx] = pl;
                }
            }
            if (EPI == 9 && !second) {
                rowmax = fmaxf(rowmax, __shfl_xor_sync(0xffffffffu, rowmax, 1));
                rowmax = fmaxf(rowmax, __shfl_xor_sync(0xffffffffu, rowmax, 2));
                if (tg == 0 && rok)
                    atomicMax(&maxu[(long)bz * M + row], encf(rowmax));
            }
            if (EPI == 10) {
                ss += __shfl_xor_sync(0xffffffffu, ss, 1);
                ss += __shfl_xor_sync(0xffffffffu, ss, 2);
                if (tg == 0 && rok)
                    atomicAdd(&saccp[(long)bz * M + row],
                              (unsigned long long)(long long)((double)ss * SSCALE));
            }
        }
    }
    if (EPI == 9 && second) {
#pragma unroll
        for (int o = 16; o > 0; o >>= 1)
            slabmax = fmaxf(slabmax, __shfl_xor_sync(0xffffffffu, slabmax, o));
        if (lane == 0) atomicMax(&dp.maxu2[bz], encf(slabmax));
    }
}

// ---------------------------------------------------------------------------
// conversion / reset passes
// ---------------------------------------------------------------------------
__global__ void reset_k(unsigned* __restrict__ kmaxu, unsigned* __restrict__ rowmaxu,
                        unsigned long long* __restrict__ dq,
                        unsigned long long* __restrict__ dk)
{
    int i = blockIdx.x * blockDim.x + threadIdx.x;
    if (i < BATCH) kmaxu[i] = 0u;
    if (i < ROWS) { rowmaxu[i] = 0u; dq[i] = 0ull; dk[i] = 0ull; }
}

// merged q/k/v input split: 8 elems/thread, blockIdx.y selects tensor
__global__ void splitin_k(const float* __restrict__ q, const float* __restrict__ k,
                          const float* __restrict__ v,
                          bf16* __restrict__ qh, bf16* __restrict__ ql,
                          bf16* __restrict__ kh, bf16* __restrict__ kl,
                          bf16* __restrict__ vh, bf16* __restrict__ vl,
                          size_t n)
{
    const int which = blockIdx.y;
    const float* s = (which == 0) ? q : (which == 1) ? k : v;
    bf16* h = (which == 0) ? qh : (which == 1) ? kh : vh;
    bf16* l = (which == 0) ? ql : (which == 1) ? kl : vl;
    size_t i8 = ((size_t)blockIdx.x * blockDim.x + threadIdx.x) * 8;
    if (i8 < n) {
        float4 x0 = *(const float4*)(s + i8);
        float4 x1 = *(const float4*)(s + i8 + 4);
        uint32_t ph0, pl0, ph1, pl1, ph2, pl2, ph3, pl3;
        split2p(x0.x, x0.y, ph0, pl0);
        split2p(x0.z, x0.w, ph1, pl1);
        split2p(x1.x, x1.y, ph2, pl2);
        split2p(x1.z, x1.w, ph3, pl3);
        *(uint4*)(h + i8) = make_uint4(ph0, ph1, ph2, ph3);
        *(uint4*)(l + i8) = make_uint4(pl0, pl1, pl2, pl3);
    }
}

// generic split (proj): 8 elems/thread (n % 8 == 0)
__global__ void split_k(const float* __restrict__ s, bf16* __restrict__ h,
                        bf16* __restrict__ l, size_t n, float scl)
{
    size_t i8 = ((size_t)blockIdx.x * blockDim.x + threadIdx.x) * 8;
    if (i8 < n) {
        float4 x0 = *(const float4*)(s + i8);
        float4 x1 = *(const float4*)(s + i8 + 4);
        uint32_t ph0, pl0, ph1, pl1, ph2, pl2, ph3, pl3;
        split2p(x0.x * scl, x0.y * scl, ph0, pl0);
        split2p(x0.z * scl, x0.w * scl, ph1, pl1);
        split2p(x1.x * scl, x1.y * scl, ph2, pl2);
        split2p(x1.z * scl, x1.w * scl, ph3, pl3);
        *(uint4*)(h + i8) = make_uint4(ph0, ph1, ph2, ph3);
        *(uint4*)(l + i8) = make_uint4(pl0, pl1, pl2, pl3);
    }
}

__global__ void wsplit_k(const float* __restrict__ W, bf16* __restrict__ h,
                         bf16* __restrict__ l)
{
    int i = blockIdx.x * blockDim.x + threadIdx.x;
    if (i < DDIM * HDCAT) {
        int d = i / HDCAT, fp = i % HDCAT;
        int hh = fp >> 8, e = fp & 255;
        float x = W[(size_t)d * HDCAT + e * 8 + hh];
        bf16 hb, lb; splitw(x, hb, lb);
        h[i] = hb; l[i] = lb;
    }
}

// merged weight transpose-split: z in [0, 3*HH); z/HH selects Wq/Wk/Wv
__global__ void tsplit3_k(const float* __restrict__ Wq, const float* __restrict__ Wk,
                          const float* __restrict__ Wv,
                          bf16* __restrict__ qh, bf16* __restrict__ ql,
                          bf16* __restrict__ kh, bf16* __restrict__ kl,
                          bf16* __restrict__ vh, bf16* __restrict__ vl)
{
    __shared__ float sm[32][33];
    const int zz = blockIdx.z;
    const int which = zz / HH, z = zz % HH;
    const float* W = (which == 0) ? Wq : (which == 1) ? Wk : Wv;
    bf16* hi = (which == 0) ? qh : (which == 1) ? kh : vh;
    bf16* lo = (which == 0) ? ql : (which == 1) ? kl : vl;
    const int R = DDIM, C = DDIM;
    const int c0 = blockIdx.x * 32, r0 = blockIdx.y * 32;
    const float* s = W + (size_t)z * R * C;
    bf16* ho = hi + (size_t)z * R * C;
    bf16* lv = lo + (size_t)z * R * C;
    const int tx = threadIdx.x, ty = threadIdx.y;
    for (int i = ty; i < 32; i += 8)
        sm[i][tx] = s[(size_t)(r0 + i) * C + c0 + tx];
    __syncthreads();
    for (int i = ty; i < 32; i += 8) {
        float x = sm[tx][i];
        bf16 hb, lb; splitw(x, hb, lb);
        ho[(size_t)(c0 + i) * R + r0 + tx] = hb;
        lv[(size_t)(c0 + i) * R + r0 + tx] = lb;
    }
}

// ---------------------------------------------------------------------------
// feature-map / reduction kernels
// ---------------------------------------------------------------------------
__global__ void __launch_bounds__(256)
qexp2_k(const float* __restrict__ qp, const unsigned long long* __restrict__ dq,
        const unsigned* __restrict__ rowmaxu,
        const float* __restrict__ ksum, bf16* __restrict__ oh,
        bf16* __restrict__ ol, float* __restrict__ dinv)
{
    const size_t r = blockIdx.x;
    const int b = (int)(r >> 10);
    const float* prow = qp + r * NBP;
    const float* ks = ksum + (size_t)b * NBP;
    const int tid = threadIdx.x;
    const int wid = tid >> 5, lane = tid & 31;
    __shared__ float wred[8];

    const float c = diag_from_i64(dq[r]) + decf(rowmaxu[r]);

    float dot = 0.f;
    for (int j = tid * 4; j < NBP; j += 1024) {
        float4 p = *(const float4*)(prow + j);
        float v0 = (j + 0 < NBF) ? RATIO * (__expf(p.x - c) + EPSF) : 0.f;
        float v1 = (j + 1 < NBF) ? RATIO * (__expf(p.y - c) + EPSF) : 0.f;
        float v2 = (j + 2 < NBF) ? RATIO * (__expf(p.z - c) + EPSF) : 0.f;
        float v3 = (j + 3 < NBF) ? RATIO * (__expf(p.w - c) + EPSF) : 0.f;
        uint32_t ph0, pl0, ph1, pl1;
        split2p(v0, v1, ph0, pl0);
        split2p(v2, v3, ph1, pl1);
        *(uint2*)(oh + r * NBP + j) = make_uint2(ph0, ph1);
        *(uint2*)(ol + r * NBP + j) = make_uint2(pl0, pl1);
        float4 kv = *(const float4*)(ks + j);
        dot += v0 * kv.x + v1 * kv.y + v2 * kv.z + v3 * kv.w;
    }
#pragma unroll
    for (int o = 16; o > 0; o >>= 1)
        dot += __shfl_xor_sync(0xffffffffu, dot, o);
    if (lane == 0) wred[wid] = dot;
    __syncthreads();
    if (tid == 0) {
        float s = wred[0];
#pragma unroll
        for (int i = 1; i < 8; i++) s += wred[i];
        dinv[r] = 1.0f / s;
    }
}

__global__ void __launch_bounds__(256)
ktexp_k(const float* __restrict__ kp, const unsigned long long* __restrict__ dk,
        const unsigned* __restrict__ kmaxu, bf16* __restrict__ th,
        bf16* __restrict__ tl, float* __restrict__ part)
{
    __shared__ float sm[32][132];
    const int b = blockIdx.z;
    const int m0 = blockIdx.x * 32, n0 = blockIdx.y * 128;
    const int tid = threadIdx.x;
    const float km = decf(kmaxu[b]);

    {
        const int n = tid >> 1, half = tid & 1;
        const float dkv = diag_from_i64(dk[(size_t)b * NPT + n0 + n]);
        const float* src = kp + ((size_t)b * NPT + n0 + n) * NBP + m0 + half * 16;
#pragma unroll
        for (int c4 = 0; c4 < 4; c4++) {
            float4 xx = *(const float4*)(src + c4 * 4);
            const int mb = m0 + half * 16 + c4 * 4;
            float vv[4] = {xx.x, xx.y, xx.z, xx.w};
#pragma unroll
            for (int e = 0; e < 4; e++)
                sm[half * 16 + c4 * 4 + e][n] =
                    (mb + e < NBF) ? RATIO * (__expf(vv[e] - dkv - km) + EPSF) : 0.f;
        }
    }
    __syncthreads();

    {
        const int w = tid >> 5, lane = tid & 31;
#pragma unroll
        for (int i = 0; i < 4; i++) {
            const int m = w * 4 + i;
            float4 v = *(const float4*)&sm[m][4 * lane];
            uint32_t ph0, pl0, ph1, pl1;
            split2p(v.x, v.y, ph0, pl0);
            split2p(v.z, v.w, ph1, pl1);
            const size_t obase = ((size_t)b * NBP + m0 + m) * NPT + n0 + 4 * lane;
            *(uint2*)&th[obase] = make_uint2(ph0, ph1);
            *(uint2*)&tl[obase] = make_uint2(pl0, pl1);
            float s = v.x + v.y + v.z + v.w;
#pragma unroll
            for (int o = 16; o > 0; o >>= 1)
                s += __shfl_xor_sync(0xffffffffu, s, o);
            if (lane == 0)
                part[((size_t)b * 8 + blockIdx.y) * NBP + m0 + m] = s;
        }
    }
}

__global__ void ksum2_k(const float* __restrict__ part, float* __restrict__ ksum)
{
    const int b = blockIdx.y;
    const int m = blockIdx.x * blockDim.x + threadIdx.x;
    if (m >= NBP) return;
    float s = 0.f;
#pragma unroll
    for (int j = 0; j < 8; j++)
        s += part[((size_t)b * 8 + j) * NBP + m];
    ksum[(size_t)b * NBP + m] = s;
}

// ---------------------------------------------------------------------------
// Launch
// ---------------------------------------------------------------------------
#define GETP(var, sym) cudaGetSymbolAddress((void**)&var, sym)

extern "C" void kernel_launch(void* const* d_in, const int* in_sizes, int n_in,
                              void* d_out, int out_size)
{
    const float* q     = (const float*)d_in[0];
    const float* k     = (const float*)d_in[1];
    const float* v     = (const float*)d_in[2];
    const float* Wq    = (const float*)d_in[3];
    const float* bq    = (const float*)d_in[4];
    const float* Wk    = (const float*)d_in[5];
    const float* bk    = (const float*)d_in[6];
    const float* Wv    = (const float*)d_in[7];
    const float* bv    = (const float*)d_in[8];
    const float* W_out = (const float*)d_in[9];
    const float* b_out = (const float*)d_in[10];
    const float* proj  = (const float*)d_in[11];
    float* out = (float*)d_out;

    float *qp, *kp, *ksum, *kpart, *dinv;
    unsigned *kmaxu, *rowmaxu;
    unsigned long long *dq64, *dk64;
    bf16 *qin_h, *qin_l, *kin_h, *kin_l, *vin_h, *vin_l;
    bf16 *wtq_h, *wtq_l, *wtk_h, *wtk_l, *wtv_h, *wtv_l;
    bf16 *pr_h, *pr_l, *wo_h, *wo_l;
    bf16 *qall_h, *qall_l, *kall_h, *kall_l, *vt_h, *vt_l;
    bf16 *qph, *qpl, *kpT_h, *kpT_l, *ctxT_h, *ctxT_l, *outs_h, *outs_l;

    GETP(qp, g_qp); GETP(kp, g_kp);
    GETP(qin_h, g_qin_h); GETP(qin_l, g_qin_l);
    GETP(kin_h, g_kin_h); GETP(kin_l, g_kin_l);
    GETP(vin_h, g_vin_h); GETP(vin_l, g_vin_l);
    GETP(wtq_h, g_wtq_h); GETP(wtq_l, g_wtq_l);
    GETP(wtk_h, g_wtk_h); GETP(wtk_l, g_wtk_l);
    GETP(wtv_h, g_wtv_h); GETP(wtv_l, g_wtv_l);
    GETP(pr_h, g_pr_h);   GETP(pr_l, g_pr_l);
    GETP(wo_h, g_wo_h);   GETP(wo_l, g_wo_l);
    GETP(qall_h, g_qall_h); GETP(qall_l, g_qall_l);
    GETP(kall_h, g_kall_h); GETP(kall_l, g_kall_l);
    GETP(vt_h, g_vt_h);     GETP(vt_l, g_vt_l);
    GETP(qph, g_qph);       GETP(qpl, g_qpl);
    GETP(kpT_h, g_kpT_h);   GETP(kpT_l, g_kpT_l);
    GETP(ctxT_h, g_ctxT_h); GETP(ctxT_l, g_ctxT_l);
    GETP(outs_h, g_outs_h); GETP(outs_l, g_outs_l);
    GETP(ksum, g_ksum); GETP(kpart, g_kpart);
    GETP(dinv, g_dinv); GETP(kmaxu, g_kmaxu); GETP(rowmaxu, g_rowmaxu);
    GETP(dq64, g_dq64); GETP(dk64, g_dk64);

    cudaFuncSetAttribute(gemm7<1>,  cudaFuncAttributeMaxDynamicSharedMemorySize, G7SMEM);
    cudaFuncSetAttribute(gemm7<2>,  cudaFuncAttributeMaxDynamicSharedMemorySize, G7SMEM);
    cudaFuncSetAttribute(gemm7<4>,  cudaFuncAttributeMaxDynamicSharedMemorySize, G7SMEM);
    cudaFuncSetAttribute(gemm7<7>,  cudaFuncAttributeMaxDynamicSharedMemorySize, G7SMEM);
    cudaFuncSetAttribute(gemm7<9>,  cudaFuncAttributeMaxDynamicSharedMemorySize, G7SMEM);
    cudaFuncSetAttribute(gemm7<10>, cudaFuncAttributeMaxDynamicSharedMemorySize, G7SMEM);

    Dual d0 = {};

    // ---- 0) reset accumulators (graph replays!) + operand splits
    reset_k<<<(ROWS + 255) / 256, 256>>>(kmaxu, rowmaxu, dq64, dk64);
    {
        const size_t nin = (size_t)TT * NPT * DDIM;
        dim3 sg((unsigned)((nin / 8 + 255) / 256), 3);
        splitin_k<<<sg, 256>>>(q, k, v, qin_h, qin_l, kin_h, kin_l,
                               vin_h, vin_l, nin);
        dim3 tg(8, 8, 3 * HH), tb(32, 8);
        tsplit3_k<<<tg, tb>>>(Wq, Wk, Wv, wtq_h, wtq_l, wtk_h, wtk_l,
                              wtv_h, wtv_l);
        const size_t npr = (size_t)NBF * DDIM;
        split_k<<<(unsigned)((npr / 8 + 255) / 256), 256>>>(proj, pr_h, pr_l, npr, DNORM);
        wsplit_k<<<(DDIM * HDCAT + 255) / 256, 256>>>(W_out, wo_h, wo_l);
    }

    // ---- 1) merged q+k projections (EPI 10; z<64 -> q, z>=64 -> k)
    {
        Dual dk_ = d0;
        dk_.a2h = kin_h; dk_.a2l = kin_l;
        dk_.b2h = wtk_h; dk_.b2l = wtk_l;
        dk_.c2h = kall_h; dk_.c2l = kall_l;
        dk_.bias2 = bk; dk_.sacc2 = dk64;
        dim3 grid(4, 8, 2 * BATCH);
        gemm7<10><<<grid, 256, G7SMEM>>>(qin_h, qin_l, wtq_h, wtq_l,
            nullptr, qall_h, qall_l,
            NPT, DDIM, DDIM, DDIM, DDIM, DDIM,
            (long)NPT * DDIM, 0, 0, (long)DDIM * DDIM,
            (long)HH * NPT * DDIM, (long)NPT * DDIM, HH,
            bq, DDIM, nullptr, 0, 0, nullptr, 0, dq64, dk_, BATCH);
    }
    // v projection directly transposed: vt[b][e][n] (EPI 7: row bias)
    {
        dim3 grid(NPT / 64, 2, BATCH);
        gemm7<7><<<grid, 256, G7SMEM>>>(wtv_h, wtv_l, vin_h, vin_l,
            nullptr, vt_h, vt_l,
            DDIM, NPT, DDIM, DDIM, DDIM, NPT,
            0, (long)DDIM * DDIM, (long)NPT * DDIM, 0,
            (long)HH * DDIM * NPT, (long)DDIM * NPT, HH,
            bv, DDIM, nullptr, 0, 0, nullptr, 0, nullptr, d0, 1 << 30);
    }

    // ---- 2) merged dash (EPI 9; z<64 -> q rows+rowmax, z>=64 -> k+slabmax)
    {
        Dual dd = d0;
        dd.a2h = kall_h; dd.a2l = kall_l;
        dd.cf2 = kp; dd.maxu2 = kmaxu;
        dim3 grid(NBP / 64, 8, 2 * BATCH);
        gemm7<9><<<grid, 256, G7SMEM>>>(qall_h, qall_l, pr_h, pr_l,
            qp, nullptr, nullptr,
            NPT, NBP, DDIM, DDIM, DDIM, NBP,
            (long)NPT * DDIM, 0, 0, 0, (long)NPT * NBP, 0, 1,
            nullptr, 0, nullptr, 0, 0, rowmaxu, NBF, nullptr, dd, BATCH);
    }

    // ---- 3) k-side feature map chain, then fused q-exp + d_inv
    ktexp_k<<<dim3(NBP / 32, 8, BATCH), 256>>>(kp, dk64, kmaxu, kpT_h, kpT_l, kpart);
    ksum2_k<<<dim3((NBP + 255) / 256, BATCH), 256>>>(kpart, ksum);
    qexp2_k<<<ROWS, 256>>>(qp, dq64, rowmaxu, ksum, qph, qpl, dinv);

    // ---- 4) ctxT[b][e][m] = vt[b] * kpT[b]^T (per-slab: Hdiv = 1)
    {
        dim3 grid(NBP / 64, 2, BATCH);
        gemm7<4><<<grid, 256, G7SMEM>>>(vt_h, vt_l, kpT_h, kpT_l,
            nullptr, ctxT_h, ctxT_l,
            DDIM, NBP, NPT, NPT, NPT, NBP,
            (long)DDIM * NPT, 0, (long)NBP * NPT, 0, (long)DDIM * NBP, 0, 1,
            nullptr, 0, nullptr, 0, 0, nullptr, 0, nullptr, d0, 1 << 30);
    }

    // ---- 5) out: [t][n][h*256+e] contiguous bf16-pair store, *dinv (Hdiv = HH)
    {
        dim3 grid(4, 8, BATCH);
        gemm7<2><<<grid, 256, G7SMEM>>>(qph, qpl, ctxT_h, ctxT_l,
            nullptr, outs_h, outs_l,
            NPT, DDIM, NBP, NBP, NBP, HDCAT,
            (long)HH * NPT * NBP, (long)NPT * NBP,
            (long)HH * DDIM * NBP, (long)DDIM * NBP,
            (long)NPT * HDCAT, (long)DDIM, HH,
            nullptr, 0, dinv, (long)HH * NPT, (long)NPT, nullptr, 0, nullptr,
            d0, 1 << 30);
    }

    // ---- 6) final: rep[8192][256] = outs * wr^T + b_out (wr = permuted W_out)
    {
        dim3 grid(4, 64, 1);
        gemm7<1><<<grid, 256, G7SMEM>>>(outs_h, outs_l, wo_h, wo_l,
            out, nullptr, nullptr,
            TT * NPT, DDIM, HDCAT, HDCAT, HDCAT, DDIM,
            0, 0, 0, 0, 0, 0, 1,
            b_out, 0, nullptr, 0, 0, nullptr, 0, nullptr, d0, 1 << 30);
    }
}